// round 1
// baseline (speedup 1.0000x reference)
#include <cuda_runtime.h>
#include <cstddef>

// Problem constants
#define E_DIM 1024
#define S_LEN 1024
#define B_SZ 4
#define NH 16
#define HD 64
#define FF_DIM 4096
#define M_ROWS (B_SZ * S_LEN)   // 4096

// ---------------- scratch (static device globals; no allocation) ----------------
__device__ float g_q[M_ROWS * E_DIM];
__device__ float g_k[M_ROWS * E_DIM];
__device__ float g_v[M_ROWS * E_DIM];
__device__ float g_gate[M_ROWS * E_DIM];
__device__ float g_ctx[M_ROWS * E_DIM];
__device__ float g_tmp[M_ROWS * E_DIM];   // attn_out, later ff_out
__device__ float g_x1[M_ROWS * E_DIM];
__device__ float g_h1[M_ROWS * FF_DIM];
__device__ float g_hg[M_ROWS * FF_DIM];
__device__ float g_pb[S_LEN * S_LEN];

// ---------------- SGEMM: C[M,N] = A[M,K] @ B[K,N] + bias[N] ----------------
// BM=BN=128, BK=8, 256 threads, 8x8 per thread.
__global__ __launch_bounds__(256)
void sgemm_bias(const float* __restrict__ A, const float* __restrict__ B,
                const float* __restrict__ bias, float* __restrict__ C,
                int M, int N, int K) {
    __shared__ float As[8][128];
    __shared__ float Bs[8][128];

    const int tid = threadIdx.x;
    const int tr = tid >> 4;        // 0..15
    const int tc = tid & 15;        // 0..15
    const int brow = blockIdx.y * 128;
    const int bcol = blockIdx.x * 128;

    const int aRow = tid >> 1;            // 0..127
    const int aCol = (tid & 1) << 2;      // 0 or 4
    const int bRow = tid >> 5;            // 0..7
    const int bCol = (tid & 31) << 2;     // 0..124

    float acc[8][8];
#pragma unroll
    for (int i = 0; i < 8; i++)
#pragma unroll
        for (int j = 0; j < 8; j++) acc[i][j] = 0.f;

    for (int kk = 0; kk < K; kk += 8) {
        float4 av = *(const float4*)&A[(size_t)(brow + aRow) * K + kk + aCol];
        As[aCol + 0][aRow] = av.x;
        As[aCol + 1][aRow] = av.y;
        As[aCol + 2][aRow] = av.z;
        As[aCol + 3][aRow] = av.w;
        *(float4*)&Bs[bRow][bCol] =
            *(const float4*)&B[(size_t)(kk + bRow) * N + bcol + bCol];
        __syncthreads();

#pragma unroll
        for (int k = 0; k < 8; k++) {
            float ar[8], br[8];
            *(float4*)(ar)     = *(const float4*)&As[k][tr * 8];
            *(float4*)(ar + 4) = *(const float4*)&As[k][tr * 8 + 4];
            *(float4*)(br)     = *(const float4*)&Bs[k][tc * 8];
            *(float4*)(br + 4) = *(const float4*)&Bs[k][tc * 8 + 4];
#pragma unroll
            for (int i = 0; i < 8; i++)
#pragma unroll
                for (int j = 0; j < 8; j++)
                    acc[i][j] = fmaf(ar[i], br[j], acc[i][j]);
        }
        __syncthreads();
    }

#pragma unroll
    for (int i = 0; i < 8; i++) {
        const size_t r = (size_t)(brow + tr * 8 + i);
#pragma unroll
        for (int j4 = 0; j4 < 8; j4 += 4) {
            const int c = bcol + tc * 8 + j4;
            float4 o;
            o.x = acc[i][j4 + 0] + bias[c + 0];
            o.y = acc[i][j4 + 1] + bias[c + 1];
            o.z = acc[i][j4 + 2] + bias[c + 2];
            o.w = acc[i][j4 + 3] + bias[c + 3];
            *(float4*)&C[r * N + c] = o;
        }
    }
}

// ---------------- pos bias: pb[i,j] = mean over 8 ----------------
__global__ __launch_bounds__(256)
void posbias_kernel(const float* __restrict__ pe, float* __restrict__ pb) {
    const size_t i = (size_t)blockIdx.x * 256 + threadIdx.x;   // 0..1M-1
    const float4 a = *(const float4*)&pe[i * 8];
    const float4 b = *(const float4*)&pe[i * 8 + 4];
    pb[i] = (a.x + a.y + a.z + a.w + b.x + b.y + b.z + b.w) * 0.125f;
}

// ---------------- fused attention (online softmax) ----------------
// grid (16 q-tiles, 64 b*h), 256 threads. Thread owns rows ty*4+i (i<4),
// cols tx + 16*j (j<4). Smem rows padded to 65 floats (conflict-free scalar).
__global__ __launch_bounds__(256)
void attention_kernel(const float* __restrict__ Q, const float* __restrict__ K,
                      const float* __restrict__ V, const float* __restrict__ PB,
                      float* __restrict__ CTX) {
    extern __shared__ float sm[];
    float* qs = sm;                 // [64][65]
    float* ks = sm + 64 * 65;       // [64][65]
    float* vs = sm + 2 * 64 * 65;   // [64][65]
    float* ps = sm + 3 * 64 * 65;   // [64][65]

    const int tid = threadIdx.x;
    const int ty = tid >> 4, tx = tid & 15;
    const int b = blockIdx.y >> 4, h = blockIdx.y & 15;
    const int q0 = blockIdx.x * 64;

    // load Q tile (64 rows x 64 d)
#pragma unroll
    for (int it = 0; it < 4; it++) {
        const int i = tid + it * 256;
        const int r = i >> 4, c4 = (i & 15) << 2;
        const float4 val =
            *(const float4*)&Q[((((size_t)b << 10) + q0 + r) * 16 + h) * 64 + c4];
        float* dst = &qs[r * 65 + c4];
        dst[0] = val.x; dst[1] = val.y; dst[2] = val.z; dst[3] = val.w;
    }

    float mrow[4], lrow[4], acc[4][4];
#pragma unroll
    for (int i = 0; i < 4; i++) {
        mrow[i] = -1e30f; lrow[i] = 0.f;
#pragma unroll
        for (int j = 0; j < 4; j++) acc[i][j] = 0.f;
    }

    for (int kt = 0; kt < 16; kt++) {
        const int k0 = kt * 64;
        __syncthreads();   // protect ks/vs against previous pv readers
#pragma unroll
        for (int it = 0; it < 4; it++) {
            const int i = tid + it * 256;
            const int r = i >> 4, c4 = (i & 15) << 2;
            const size_t g = ((((size_t)b << 10) + k0 + r) * 16 + h) * 64 + c4;
            const float4 kv = *(const float4*)&K[g];
            const float4 vv = *(const float4*)&V[g];
            float* kd = &ks[r * 65 + c4];
            kd[0] = kv.x; kd[1] = kv.y; kd[2] = kv.z; kd[3] = kv.w;
            float* vd = &vs[r * 65 + c4];
            vd[0] = vv.x; vd[1] = vv.y; vd[2] = vv.z; vd[3] = vv.w;
        }
        __syncthreads();

        // scores s[i][j] = q[row_i] . k[col_j]
        float s[4][4];
#pragma unroll
        for (int i = 0; i < 4; i++)
#pragma unroll
            for (int j = 0; j < 4; j++) s[i][j] = 0.f;

#pragma unroll 4
        for (int d = 0; d < 64; d++) {
            float aq[4], ak[4];
#pragma unroll
            for (int i = 0; i < 4; i++) aq[i] = qs[(ty * 4 + i) * 65 + d];
#pragma unroll
            for (int j = 0; j < 4; j++) ak[j] = ks[(tx + 16 * j) * 65 + d];
#pragma unroll
            for (int i = 0; i < 4; i++)
#pragma unroll
                for (int j = 0; j < 4; j++)
                    s[i][j] = fmaf(aq[i], ak[j], s[i][j]);
        }

        // scale + bias + online softmax update
#pragma unroll
        for (int i = 0; i < 4; i++) {
            const size_t r = (size_t)(q0 + ty * 4 + i);
            float mi = -1e30f;
#pragma unroll
            for (int j = 0; j < 4; j++) {
                s[i][j] = s[i][j] * 0.125f + PB[r * 1024 + k0 + tx + 16 * j];
                mi = fmaxf(mi, s[i][j]);
            }
#pragma unroll
            for (int o = 8; o; o >>= 1)
                mi = fmaxf(mi, __shfl_xor_sync(0xffffffffu, mi, o));
            const float mnew = fmaxf(mrow[i], mi);
            const float corr = __expf(mrow[i] - mnew);
            mrow[i] = mnew;
            float rsum = 0.f;
#pragma unroll
            for (int j = 0; j < 4; j++) {
                const float p = __expf(s[i][j] - mnew);
                ps[(ty * 4 + i) * 65 + tx + 16 * j] = p;
                rsum += p;
            }
#pragma unroll
            for (int o = 8; o; o >>= 1)
                rsum += __shfl_xor_sync(0xffffffffu, rsum, o);
            lrow[i] = lrow[i] * corr + rsum;
#pragma unroll
            for (int j = 0; j < 4; j++) acc[i][j] *= corr;
        }
        __syncthreads();

        // acc += p @ v
#pragma unroll 4
        for (int jj = 0; jj < 64; jj++) {
            float pv[4], vvv[4];
#pragma unroll
            for (int i = 0; i < 4; i++) pv[i] = ps[(ty * 4 + i) * 65 + jj];
#pragma unroll
            for (int j = 0; j < 4; j++) vvv[j] = vs[jj * 65 + tx + 16 * j];
#pragma unroll
            for (int i = 0; i < 4; i++)
#pragma unroll
                for (int j = 0; j < 4; j++)
                    acc[i][j] = fmaf(pv[i], vvv[j], acc[i][j]);
        }
    }

#pragma unroll
    for (int i = 0; i < 4; i++) {
        const float inv = 1.f / lrow[i];
        const size_t base = ((((size_t)b << 10) + q0 + ty * 4 + i) * 16 + h) * 64;
#pragma unroll
        for (int j = 0; j < 4; j++)
            CTX[base + tx + 16 * j] = acc[i][j] * inv;
    }
}

// ---------------- LN1: x1 = LN(x + sigmoid(gate)*attn) ----------------
__global__ __launch_bounds__(256)
void ln1_kernel(const float* __restrict__ x, const float* __restrict__ attn,
                const float* __restrict__ gate, const float* __restrict__ gw,
                const float* __restrict__ gb, float* __restrict__ x1) {
    const size_t base = (size_t)blockIdx.x * E_DIM;
    const int t = threadIdx.x;
    float vals[4];
    float s = 0.f, s2 = 0.f;
#pragma unroll
    for (int i = 0; i < 4; i++) {
        const int c = t + i * 256;
        const float gp = gate[base + c];
        const float sg = 1.f / (1.f + __expf(-gp));
        const float val = x[base + c] + attn[base + c] * sg;
        vals[i] = val; s += val; s2 += val * val;
    }
    __shared__ float rs[8], rs2[8];
#pragma unroll
    for (int o = 16; o; o >>= 1) {
        s  += __shfl_xor_sync(0xffffffffu, s,  o);
        s2 += __shfl_xor_sync(0xffffffffu, s2, o);
    }
    if ((t & 31) == 0) { rs[t >> 5] = s; rs2[t >> 5] = s2; }
    __syncthreads();
    float S = 0.f, S2 = 0.f;
#pragma unroll
    for (int i = 0; i < 8; i++) { S += rs[i]; S2 += rs2[i]; }
    const float mean = S * (1.f / E_DIM);
    const float var = S2 * (1.f / E_DIM) - mean * mean;
    const float inv = rsqrtf(var + 1e-6f);
#pragma unroll
    for (int i = 0; i < 4; i++) {
        const int c = t + i * 256;
        x1[base + c] = (vals[i] - mean) * inv * gw[c] + gb[c];
    }
}

// ---------------- LN2: out = LN(x1 + ff) ----------------
__global__ __launch_bounds__(256)
void ln2_kernel(const float* __restrict__ x1, const float* __restrict__ ff,
                const float* __restrict__ gw, const float* __restrict__ gb,
                float* __restrict__ out) {
    const size_t base = (size_t)blockIdx.x * E_DIM;
    const int t = threadIdx.x;
    float vals[4];
    float s = 0.f, s2 = 0.f;
#pragma unroll
    for (int i = 0; i < 4; i++) {
        const int c = t + i * 256;
        const float val = x1[base + c] + ff[base + c];
        vals[i] = val; s += val; s2 += val * val;
    }
    __shared__ float rs[8], rs2[8];
#pragma unroll
    for (int o = 16; o; o >>= 1) {
        s  += __shfl_xor_sync(0xffffffffu, s,  o);
        s2 += __shfl_xor_sync(0xffffffffu, s2, o);
    }
    if ((t & 31) == 0) { rs[t >> 5] = s; rs2[t >> 5] = s2; }
    __syncthreads();
    float S = 0.f, S2 = 0.f;
#pragma unroll
    for (int i = 0; i < 8; i++) { S += rs[i]; S2 += rs2[i]; }
    const float mean = S * (1.f / E_DIM);
    const float var = S2 * (1.f / E_DIM) - mean * mean;
    const float inv = rsqrtf(var + 1e-6f);
#pragma unroll
    for (int i = 0; i < 4; i++) {
        const int c = t + i * 256;
        out[base + c] = (vals[i] - mean) * inv * gw[c] + gb[c];
    }
}

// ---------------- SwiGLU: h1 *= sigmoid(hg) ----------------
__global__ __launch_bounds__(256)
void swiglu_kernel(float* __restrict__ h1, const float* __restrict__ hg) {
    const size_t i = (size_t)blockIdx.x * 256 + threadIdx.x;   // float4 index
    float4 a = ((float4*)h1)[i];
    const float4 g = ((const float4*)hg)[i];
    a.x *= 1.f / (1.f + __expf(-g.x));
    a.y *= 1.f / (1.f + __expf(-g.y));
    a.z *= 1.f / (1.f + __expf(-g.z));
    a.w *= 1.f / (1.f + __expf(-g.w));
    ((float4*)h1)[i] = a;
}

// ---------------- launch ----------------
extern "C" void kernel_launch(void* const* d_in, const int* in_sizes, int n_in,
                              void* d_out, int out_size) {
    const float* x   = (const float*)d_in[0];
    const float* pe  = (const float*)d_in[1];
    const float* Wq  = (const float*)d_in[2];
    const float* bq  = (const float*)d_in[3];
    const float* Wk  = (const float*)d_in[4];
    const float* bk  = (const float*)d_in[5];
    const float* Wv  = (const float*)d_in[6];
    const float* bv  = (const float*)d_in[7];
    const float* Wo  = (const float*)d_in[8];
    const float* bo  = (const float*)d_in[9];
    const float* Wg  = (const float*)d_in[10];
    const float* bg  = (const float*)d_in[11];
    const float* Wf1 = (const float*)d_in[12];
    const float* bf1 = (const float*)d_in[13];
    const float* Wfg = (const float*)d_in[14];
    const float* bfg = (const float*)d_in[15];
    const float* Wf2 = (const float*)d_in[16];
    const float* bf2 = (const float*)d_in[17];
    const float* l1g = (const float*)d_in[18];
    const float* l1b = (const float*)d_in[19];
    const float* l2g = (const float*)d_in[20];
    const float* l2b = (const float*)d_in[21];
    float* out = (float*)d_out;

    float *q, *k, *v, *gate, *ctx, *tmp, *x1, *h1, *hg, *pb;
    cudaGetSymbolAddress((void**)&q, g_q);
    cudaGetSymbolAddress((void**)&k, g_k);
    cudaGetSymbolAddress((void**)&v, g_v);
    cudaGetSymbolAddress((void**)&gate, g_gate);
    cudaGetSymbolAddress((void**)&ctx, g_ctx);
    cudaGetSymbolAddress((void**)&tmp, g_tmp);
    cudaGetSymbolAddress((void**)&x1, g_x1);
    cudaGetSymbolAddress((void**)&h1, g_h1);
    cudaGetSymbolAddress((void**)&hg, g_hg);
    cudaGetSymbolAddress((void**)&pb, g_pb);

    const int ATT_SMEM = 4 * 64 * 65 * 4;   // 66560 bytes
    cudaFuncSetAttribute(attention_kernel,
                         cudaFuncAttributeMaxDynamicSharedMemorySize, ATT_SMEM);

    // pos bias (S*S = 1M elems)
    posbias_kernel<<<4096, 256>>>(pe, pb);

    const dim3 gN1024(E_DIM / 128, M_ROWS / 128);   // (8, 32)
    const dim3 gN4096(FF_DIM / 128, M_ROWS / 128);  // (32, 32)

    // QKV + gate projections
    sgemm_bias<<<gN1024, 256>>>(x, Wq, bq, q, M_ROWS, E_DIM, E_DIM);
    sgemm_bias<<<gN1024, 256>>>(x, Wk, bk, k, M_ROWS, E_DIM, E_DIM);
    sgemm_bias<<<gN1024, 256>>>(x, Wv, bv, v, M_ROWS, E_DIM, E_DIM);
    sgemm_bias<<<gN1024, 256>>>(x, Wg, bg, gate, M_ROWS, E_DIM, E_DIM);

    // fused attention -> ctx
    attention_kernel<<<dim3(S_LEN / 64, B_SZ * NH), 256, ATT_SMEM>>>(q, k, v, pb, ctx);

    // output projection
    sgemm_bias<<<gN1024, 256>>>(ctx, Wo, bo, tmp, M_ROWS, E_DIM, E_DIM);

    // gate * attn + residual + LN1
    ln1_kernel<<<M_ROWS, 256>>>(x, tmp, gate, l1g, l1b, x1);

    // FFN
    sgemm_bias<<<gN4096, 256>>>(x1, Wf1, bf1, h1, M_ROWS, FF_DIM, E_DIM);
    sgemm_bias<<<gN4096, 256>>>(x1, Wfg, bfg, hg, M_ROWS, FF_DIM, E_DIM);
    swiglu_kernel<<<(M_ROWS * FF_DIM) / (4 * 256), 256>>>(h1, hg);
    sgemm_bias<<<gN1024, 256>>>(h1, Wf2, bf2, tmp, M_ROWS, E_DIM, FF_DIM);

    // residual + LN2 -> out
    ln2_kernel<<<M_ROWS, 256>>>(x1, tmp, l2g, l2b, out);
}

// round 3
// speedup vs baseline: 2.1752x; 2.1752x over previous
#include <cuda_runtime.h>
#include <cuda_bf16.h>
#include <cstdint>
#include <cstddef>

// Problem constants
#define E_DIM 1024
#define S_LEN 1024
#define B_SZ 4
#define NH 16
#define HD 64
#define FF_DIM 4096
#define M_ROWS (B_SZ * S_LEN)   // 4096

// ---------------- scratch (static device globals; no allocation) ----------------
__device__ float g_qkvg[M_ROWS * 4096];          // [q|k|v|gate] fp32
__device__ float g_ff[(size_t)M_ROWS * 8192];    // [h1|hg] fp32
__device__ float g_tmp[M_ROWS * E_DIM];          // attn_out, later ff_out
__device__ float g_x1[M_ROWS * E_DIM];
__device__ float g_pb[S_LEN * S_LEN];

// bf16 hi/lo activation pairs
__device__ __nv_bfloat16 g_xh[M_ROWS * E_DIM];
__device__ __nv_bfloat16 g_xl[M_ROWS * E_DIM];
__device__ __nv_bfloat16 g_ctxh[M_ROWS * E_DIM];
__device__ __nv_bfloat16 g_ctxl[M_ROWS * E_DIM];
__device__ __nv_bfloat16 g_x1h[M_ROWS * E_DIM];
__device__ __nv_bfloat16 g_x1l[M_ROWS * E_DIM];
__device__ __nv_bfloat16 g_h1h[(size_t)M_ROWS * FF_DIM];
__device__ __nv_bfloat16 g_h1l[(size_t)M_ROWS * FF_DIM];

// transposed bf16 weight pairs (K-major: [N,K])
__device__ __nv_bfloat16 g_wqkvg_h[4096 * 1024];
__device__ __nv_bfloat16 g_wqkvg_l[4096 * 1024];
__device__ __nv_bfloat16 g_wo_h[1024 * 1024];
__device__ __nv_bfloat16 g_wo_l[1024 * 1024];
__device__ __nv_bfloat16 g_wff_h[8192 * 1024];
__device__ __nv_bfloat16 g_wff_l[8192 * 1024];
__device__ __nv_bfloat16 g_wf2_h[1024 * 4096];
__device__ __nv_bfloat16 g_wf2_l[1024 * 4096];

__device__ float g_bias_qkvg[4096];
__device__ float g_bias_ff[8192];

// =================== PTX helpers (baseline sm_80+ features only) ===================
__device__ __forceinline__ uint32_t smem_u32(const void* p) {
    uint32_t a;
    asm("{ .reg .u64 t; cvta.to.shared.u64 t, %1; cvt.u32.u64 %0, t; }" : "=r"(a) : "l"(p));
    return a;
}
__device__ __forceinline__ void cp16(uint32_t dst, const void* src) {
    asm volatile("cp.async.cg.shared.global [%0], [%1], 16;" :: "r"(dst), "l"(src));
}
#define CP_COMMIT() asm volatile("cp.async.commit_group;" ::: "memory")
#define CP_WAIT1()  asm volatile("cp.async.wait_group 1;" ::: "memory")

__device__ __forceinline__ void ldm_x4(uint32_t& r0, uint32_t& r1, uint32_t& r2,
                                       uint32_t& r3, uint32_t addr) {
    asm volatile("ldmatrix.sync.aligned.m8n8.x4.shared.b16 {%0,%1,%2,%3}, [%4];"
                 : "=r"(r0), "=r"(r1), "=r"(r2), "=r"(r3) : "r"(addr));
}
__device__ __forceinline__ void mma16816(float* c, const uint32_t* a,
                                         uint32_t b0, uint32_t b1) {
    asm volatile(
        "mma.sync.aligned.m16n8k16.row.col.f32.bf16.bf16.f32 "
        "{%0,%1,%2,%3}, {%4,%5,%6,%7}, {%8,%9}, {%0,%1,%2,%3};"
        : "+f"(c[0]), "+f"(c[1]), "+f"(c[2]), "+f"(c[3])
        : "r"(a[0]), "r"(a[1]), "r"(a[2]), "r"(a[3]), "r"(b0), "r"(b1));
}

// =================== HMMA GEMM: C[M,N] = (Ah+Al) @ (Wh+Wl)^T + bias ===================
// A: [M,K] bf16 pairs (K-major). W: [N,K] bf16 pairs (K-major). C: fp32 [M,N].
// CTA tile 128x128, BK=32, 8 warps (warp tile 64x32), double-buffered cp.async.
// smem stage layout (rows padded to 80B): Ah@0, Al@10240, Bh@20480, Bl@30720.
#define STAGE_BYTES 40960
#define GEMM_SMEM (2 * STAGE_BYTES)

__global__ __launch_bounds__(256)
void hmma_gemm(const __nv_bfloat16* __restrict__ Ah, const __nv_bfloat16* __restrict__ Al,
               const __nv_bfloat16* __restrict__ Wh, const __nv_bfloat16* __restrict__ Wl,
               const float* __restrict__ bias, float* __restrict__ C,
               int M, int N, int K) {
    extern __shared__ char smem[];
    const uint32_t sb = smem_u32(smem);
    const int tid = threadIdx.x;
    const int wid = tid >> 5, lane = tid & 31;
    const int brow = blockIdx.y * 128, bcol = blockIdx.x * 128;
    const int wm = (wid >> 2) * 64, wn = (wid & 3) * 32;
    const int nst = K >> 5;

    // per-thread load slots: chunks tid, tid+256; chunk c -> row=c>>2, col16=c&3
    const int r0c = tid >> 2, r1c = (tid + 256) >> 2;
    const int c0c = tid & 3,  c1c = (tid + 256) & 3;
    const uint32_t so0 = (uint32_t)(r0c * 80 + c0c * 16);
    const uint32_t so1 = (uint32_t)(r1c * 80 + c1c * 16);

#define LOAD_STAGE(s, buf) do {                                               \
        const uint32_t stb_ = sb + (buf) * STAGE_BYTES;                       \
        const size_t ga0 = (size_t)(brow + r0c) * K + (s) * 32 + c0c * 8;     \
        const size_t ga1 = (size_t)(brow + r1c) * K + (s) * 32 + c1c * 8;     \
        const size_t gb0 = (size_t)(bcol + r0c) * K + (s) * 32 + c0c * 8;     \
        const size_t gb1 = (size_t)(bcol + r1c) * K + (s) * 32 + c1c * 8;     \
        cp16(stb_ + so0,         Ah + ga0);                                   \
        cp16(stb_ + so1,         Ah + ga1);                                   \
        cp16(stb_ + 10240 + so0, Al + ga0);                                   \
        cp16(stb_ + 10240 + so1, Al + ga1);                                   \
        cp16(stb_ + 20480 + so0, Wh + gb0);                                   \
        cp16(stb_ + 20480 + so1, Wh + gb1);                                   \
        cp16(stb_ + 30720 + so0, Wl + gb0);                                   \
        cp16(stb_ + 30720 + so1, Wl + gb1);                                   \
    } while (0)

    float acc[4][4][4];
#pragma unroll
    for (int i = 0; i < 4; i++)
#pragma unroll
        for (int j = 0; j < 4; j++)
#pragma unroll
            for (int r = 0; r < 4; r++) acc[i][j][r] = 0.f;

    LOAD_STAGE(0, 0); CP_COMMIT();
    LOAD_STAGE(1, 1); CP_COMMIT();

    // ldmatrix lane addressing (constant per thread)
    const uint32_t a_lrow = (uint32_t)(lane & 15);            // row within m16 tile
    const uint32_t a_koff = (uint32_t)((lane & 16) >> 1);     // +8 k for upper half
    const uint32_t b_lrow = (uint32_t)((lane & 7) + ((lane & 16) >> 1)); // row within n16
    const uint32_t b_koff = (uint32_t)(lane & 8);             // +8 k

    for (int s = 0; s < nst; s++) {
        CP_WAIT1();
        __syncthreads();
        const uint32_t stb = sb + (uint32_t)(s & 1) * STAGE_BYTES;

#pragma unroll
        for (int kk = 0; kk < 32; kk += 16) {
            uint32_t ah[4][4], al[4][4], bh[2][4], bl[2][4];
            const uint32_t akcol = (uint32_t)kk + a_koff;
#pragma unroll
            for (int mi = 0; mi < 4; mi++) {
                const uint32_t addr = stb + (uint32_t)(wm + mi * 16 + a_lrow) * 80 + akcol * 2;
                ldm_x4(ah[mi][0], ah[mi][1], ah[mi][2], ah[mi][3], addr);
                ldm_x4(al[mi][0], al[mi][1], al[mi][2], al[mi][3], addr + 10240);
            }
            const uint32_t bkcol = (uint32_t)kk + b_koff;
#pragma unroll
            for (int ni = 0; ni < 2; ni++) {
                const uint32_t addr =
                    stb + 20480 + (uint32_t)(wn + ni * 16 + b_lrow) * 80 + bkcol * 2;
                ldm_x4(bh[ni][0], bh[ni][1], bh[ni][2], bh[ni][3], addr);
                ldm_x4(bl[ni][0], bl[ni][1], bl[ni][2], bl[ni][3], addr + 10240);
            }
#pragma unroll
            for (int mi = 0; mi < 4; mi++)
#pragma unroll
                for (int nj = 0; nj < 4; nj++) {
                    const int g = nj >> 1, p = (nj & 1) * 2;
                    mma16816(acc[mi][nj], ah[mi], bh[g][p], bh[g][p + 1]);
                    mma16816(acc[mi][nj], ah[mi], bl[g][p], bl[g][p + 1]);
                    mma16816(acc[mi][nj], al[mi], bh[g][p], bh[g][p + 1]);
                }
        }
        __syncthreads();
        if (s + 2 < nst) LOAD_STAGE(s + 2, s & 1);
        CP_COMMIT();   // commit every iter (possibly empty) to keep group count uniform
    }

    // epilogue: add bias, write fp32
    const int qr = lane >> 2, qc = (lane & 3) * 2;
#pragma unroll
    for (int mi = 0; mi < 4; mi++) {
        const size_t gr  = (size_t)(brow + wm + mi * 16 + qr);
#pragma unroll
        for (int nj = 0; nj < 4; nj++) {
            const int gc = bcol + wn + nj * 8 + qc;
            const float2 b2 = *(const float2*)(bias + gc);
            float2 o0, o1;
            o0.x = acc[mi][nj][0] + b2.x;
            o0.y = acc[mi][nj][1] + b2.y;
            o1.x = acc[mi][nj][2] + b2.x;
            o1.y = acc[mi][nj][3] + b2.y;
            *(float2*)(C + gr * N + gc)       = o0;
            *(float2*)(C + (gr + 8) * N + gc) = o1;
        }
    }
#undef LOAD_STAGE
}

// =================== weight transpose + bf16 split: T[n][k] = W[k][n] ===================
__global__ __launch_bounds__(256)
void transpose_conv(const float* __restrict__ W, __nv_bfloat16* __restrict__ Th,
                    __nv_bfloat16* __restrict__ Tl, int K, int N) {
    __shared__ float t[32][33];
    const int k0 = blockIdx.y * 32, n0 = blockIdx.x * 32;
    const int tx = threadIdx.x & 31, ty = threadIdx.x >> 5;
#pragma unroll
    for (int l = 0; l < 4; l++)
        t[ty + 8 * l][tx] = W[(size_t)(k0 + ty + 8 * l) * N + n0 + tx];
    __syncthreads();
#pragma unroll
    for (int l = 0; l < 4; l++) {
        const float v = t[tx][ty + 8 * l];
        const __nv_bfloat16 h = __float2bfloat16(v);
        const size_t o = (size_t)(n0 + ty + 8 * l) * K + k0 + tx;
        Th[o] = h;
        Tl[o] = __float2bfloat16(v - __bfloat162float(h));
    }
}

// =================== fp32 -> bf16 pair ===================
__device__ __forceinline__ void pack4(float4 v, __nv_bfloat16* hp, __nv_bfloat16* lp) {
    __nv_bfloat162 h0 = __floats2bfloat162_rn(v.x, v.y);
    __nv_bfloat162 h1 = __floats2bfloat162_rn(v.z, v.w);
    __nv_bfloat162 l0 = __floats2bfloat162_rn(v.x - __bfloat162float(h0.x),
                                              v.y - __bfloat162float(h0.y));
    __nv_bfloat162 l1 = __floats2bfloat162_rn(v.z - __bfloat162float(h1.x),
                                              v.w - __bfloat162float(h1.y));
    uint2 hw, lw;
    hw.x = *(uint32_t*)&h0; hw.y = *(uint32_t*)&h1;
    lw.x = *(uint32_t*)&l0; lw.y = *(uint32_t*)&l1;
    *(uint2*)hp = hw;
    *(uint2*)lp = lw;
}

__global__ __launch_bounds__(256)
void conv_pair(const float* __restrict__ X, __nv_bfloat16* __restrict__ Xh,
               __nv_bfloat16* __restrict__ Xl) {
    const size_t i = ((size_t)blockIdx.x * 256 + threadIdx.x) * 4;
    pack4(*(const float4*)(X + i), Xh + i, Xl + i);
}

// =================== bias packing ===================
__global__ void pack_bias(const float* bq, const float* bk, const float* bv,
                          const float* bg, const float* bf1, const float* bfg,
                          float* outq, float* outf) {
    const int i = blockIdx.x * 256 + threadIdx.x;   // 0..12287
    if (i < 1024) outq[i] = bq[i];
    else if (i < 2048) outq[i] = bk[i - 1024];
    else if (i < 3072) outq[i] = bv[i - 2048];
    else if (i < 4096) outq[i] = bg[i - 3072];
    else if (i < 8192) outf[i - 4096] = bf1[i - 4096];
    else outf[i - 4096] = bfg[i - 8192];
}

// ---------------- pos bias: pb[i,j] = mean over 8 ----------------
__global__ __launch_bounds__(256)
void posbias_kernel(const float* __restrict__ pe, float* __restrict__ pb) {
    const size_t i = (size_t)blockIdx.x * 256 + threadIdx.x;
    const float4 a = *(const float4*)&pe[i * 8];
    const float4 b = *(const float4*)&pe[i * 8 + 4];
    pb[i] = (a.x + a.y + a.z + a.w + b.x + b.y + b.z + b.w) * 0.125f;
}

// ---------------- fused attention (online softmax, fp32) ----------------
__global__ __launch_bounds__(256)
void attention_kernel(const float* __restrict__ QKVG, const float* __restrict__ PB,
                      __nv_bfloat16* __restrict__ CTXH, __nv_bfloat16* __restrict__ CTXL) {
    extern __shared__ float sm[];
    float* qs = sm;
    float* ks = sm + 64 * 65;
    float* vs = sm + 2 * 64 * 65;
    float* ps = sm + 3 * 64 * 65;

    const int tid = threadIdx.x;
    const int ty = tid >> 4, tx = tid & 15;
    const int b = blockIdx.y >> 4, h = blockIdx.y & 15;
    const int q0 = blockIdx.x * 64;

#pragma unroll
    for (int it = 0; it < 4; it++) {
        const int i = tid + it * 256;
        const int r = i >> 4, c4 = (i & 15) << 2;
        const float4 val =
            *(const float4*)&QKVG[(((size_t)b << 10) + q0 + r) * 4096 + h * 64 + c4];
        float* dst = &qs[r * 65 + c4];
        dst[0] = val.x; dst[1] = val.y; dst[2] = val.z; dst[3] = val.w;
    }

    float mrow[4], lrow[4], acc[4][4];
#pragma unroll
    for (int i = 0; i < 4; i++) {
        mrow[i] = -1e30f; lrow[i] = 0.f;
#pragma unroll
        for (int j = 0; j < 4; j++) acc[i][j] = 0.f;
    }

    for (int kt = 0; kt < 16; kt++) {
        const int k0 = kt * 64;
        __syncthreads();
#pragma unroll
        for (int it = 0; it < 4; it++) {
            const int i = tid + it * 256;
            const int r = i >> 4, c4 = (i & 15) << 2;
            const size_t gbase = (((size_t)b << 10) + k0 + r) * 4096 + h * 64 + c4;
            const float4 kv = *(const float4*)&QKVG[gbase + 1024];
            const float4 vv = *(const float4*)&QKVG[gbase + 2048];
            float* kd = &ks[r * 65 + c4];
            kd[0] = kv.x; kd[1] = kv.y; kd[2] = kv.z; kd[3] = kv.w;
            float* vd = &vs[r * 65 + c4];
            vd[0] = vv.x; vd[1] = vv.y; vd[2] = vv.z; vd[3] = vv.w;
        }
        __syncthreads();

        float s[4][4];
#pragma unroll
        for (int i = 0; i < 4; i++)
#pragma unroll
            for (int j = 0; j < 4; j++) s[i][j] = 0.f;

#pragma unroll 4
        for (int d = 0; d < 64; d++) {
            float aq[4], ak[4];
#pragma unroll
            for (int i = 0; i < 4; i++) aq[i] = qs[(ty * 4 + i) * 65 + d];
#pragma unroll
            for (int j = 0; j < 4; j++) ak[j] = ks[(tx + 16 * j) * 65 + d];
#pragma unroll
            for (int i = 0; i < 4; i++)
#pragma unroll
                for (int j = 0; j < 4; j++)
                    s[i][j] = fmaf(aq[i], ak[j], s[i][j]);
        }

#pragma unroll
        for (int i = 0; i < 4; i++) {
            const size_t r = (size_t)(q0 + ty * 4 + i);
            float mi = -1e30f;
#pragma unroll
            for (int j = 0; j < 4; j++) {
                s[i][j] = s[i][j] * 0.125f + PB[r * 1024 + k0 + tx + 16 * j];
                mi = fmaxf(mi, s[i][j]);
            }
#pragma unroll
            for (int o = 8; o; o >>= 1)
                mi = fmaxf(mi, __shfl_xor_sync(0xffffffffu, mi, o));
            const float mnew = fmaxf(mrow[i], mi);
            const float corr = __expf(mrow[i] - mnew);
            mrow[i] = mnew;
            float rsum = 0.f;
#pragma unroll
            for (int j = 0; j < 4; j++) {
                const float p = __expf(s[i][j] - mnew);
                ps[(ty * 4 + i) * 65 + tx + 16 * j] = p;
                rsum += p;
            }
#pragma unroll
            for (int o = 8; o; o >>= 1)
                rsum += __shfl_xor_sync(0xffffffffu, rsum, o);
            lrow[i] = lrow[i] * corr + rsum;
#pragma unroll
            for (int j = 0; j < 4; j++) acc[i][j] *= corr;
        }
        __syncthreads();

#pragma unroll 4
        for (int jj = 0; jj < 64; jj++) {
            float pv[4], vvv[4];
#pragma unroll
            for (int i = 0; i < 4; i++) pv[i] = ps[(ty * 4 + i) * 65 + jj];
#pragma unroll
            for (int j = 0; j < 4; j++) vvv[j] = vs[jj * 65 + tx + 16 * j];
#pragma unroll
            for (int i = 0; i < 4; i++)
#pragma unroll
                for (int j = 0; j < 4; j++)
                    acc[i][j] = fmaf(pv[i], vvv[j], acc[i][j]);
        }
    }

#pragma unroll
    for (int i = 0; i < 4; i++) {
        const float inv = 1.f / lrow[i];
        const size_t base = (((size_t)b << 10) + q0 + ty * 4 + i) * 1024 + h * 64;
#pragma unroll
        for (int j = 0; j < 4; j++) {
            const float v = acc[i][j] * inv;
            const __nv_bfloat16 hi = __float2bfloat16(v);
            CTXH[base + tx + 16 * j] = hi;
            CTXL[base + tx + 16 * j] = __float2bfloat16(v - __bfloat162float(hi));
        }
    }
}

// ---------------- LN1: x1 = LN(x + sigmoid(gate)*attn); also emit bf16 pair ----------------
__global__ __launch_bounds__(256)
void ln1_kernel(const float* __restrict__ x, const float* __restrict__ attn,
                const float* __restrict__ qkvg, const float* __restrict__ gw,
                const float* __restrict__ gb, float* __restrict__ x1,
                __nv_bfloat16* __restrict__ x1h, __nv_bfloat16* __restrict__ x1l) {
    const size_t base = (size_t)blockIdx.x * E_DIM;
    const size_t gbase = (size_t)blockIdx.x * 4096 + 3072;
    const int t = threadIdx.x;
    float vals[4];
    float s = 0.f, s2 = 0.f;
#pragma unroll
    for (int i = 0; i < 4; i++) {
        const int c = t + i * 256;
        const float gp = qkvg[gbase + c];
        const float sg = 1.f / (1.f + __expf(-gp));
        const float val = x[base + c] + attn[base + c] * sg;
        vals[i] = val; s += val; s2 += val * val;
    }
    __shared__ float rs[8], rs2[8];
#pragma unroll
    for (int o = 16; o; o >>= 1) {
        s  += __shfl_xor_sync(0xffffffffu, s,  o);
        s2 += __shfl_xor_sync(0xffffffffu, s2, o);
    }
    if ((t & 31) == 0) { rs[t >> 5] = s; rs2[t >> 5] = s2; }
    __syncthreads();
    float S = 0.f, S2 = 0.f;
#pragma unroll
    for (int i = 0; i < 8; i++) { S += rs[i]; S2 += rs2[i]; }
    const float mean = S * (1.f / E_DIM);
    const float var = S2 * (1.f / E_DIM) - mean * mean;
    const float inv = rsqrtf(var + 1e-6f);
#pragma unroll
    for (int i = 0; i < 4; i++) {
        const int c = t + i * 256;
        const float v = (vals[i] - mean) * inv * gw[c] + gb[c];
        x1[base + c] = v;
        const __nv_bfloat16 hi = __float2bfloat16(v);
        x1h[base + c] = hi;
        x1l[base + c] = __float2bfloat16(v - __bfloat162float(hi));
    }
}

// ---------------- LN2 ----------------
__global__ __launch_bounds__(256)
void ln2_kernel(const float* __restrict__ x1, const float* __restrict__ ff,
                const float* __restrict__ gw, const float* __restrict__ gb,
                float* __restrict__ out) {
    const size_t base = (size_t)blockIdx.x * E_DIM;
    const int t = threadIdx.x;
    float vals[4];
    float s = 0.f, s2 = 0.f;
#pragma unroll
    for (int i = 0; i < 4; i++) {
        const int c = t + i * 256;
        const float val = x1[base + c] + ff[base + c];
        vals[i] = val; s += val; s2 += val * val;
    }
    __shared__ float rs[8], rs2[8];
#pragma unroll
    for (int o = 16; o; o >>= 1) {
        s  += __shfl_xor_sync(0xffffffffu, s,  o);
        s2 += __shfl_xor_sync(0xffffffffu, s2, o);
    }
    if ((t & 31) == 0) { rs[t >> 5] = s; rs2[t >> 5] = s2; }
    __syncthreads();
    float S = 0.f, S2 = 0.f;
#pragma unroll
    for (int i = 0; i < 8; i++) { S += rs[i]; S2 += rs2[i]; }
    const float mean = S * (1.f / E_DIM);
    const float var = S2 * (1.f / E_DIM) - mean * mean;
    const float inv = rsqrtf(var + 1e-6f);
#pragma unroll
    for (int i = 0; i < 4; i++) {
        const int c = t + i * 256;
        out[base + c] = (vals[i] - mean) * inv * gw[c] + gb[c];
    }
}

// ---------------- SwiGLU: h1 = ff[:, :4096] * sigmoid(ff[:, 4096:]) -> bf16 pair ----------------
__global__ __launch_bounds__(256)
void swiglu_conv(const float* __restrict__ ff, __nv_bfloat16* __restrict__ h1h,
                 __nv_bfloat16* __restrict__ h1l) {
    const size_t i = (size_t)blockIdx.x * 256 + threadIdx.x;   // float4 index over [4096,4096]
    const size_t r = i >> 10;
    const size_t c = (i & 1023) << 2;
    float4 a = *(const float4*)(ff + r * 8192 + c);
    const float4 g = *(const float4*)(ff + r * 8192 + 4096 + c);
    a.x *= 1.f / (1.f + __expf(-g.x));
    a.y *= 1.f / (1.f + __expf(-g.y));
    a.z *= 1.f / (1.f + __expf(-g.z));
    a.w *= 1.f / (1.f + __expf(-g.w));
    pack4(a, h1h + r * 4096 + c, h1l + r * 4096 + c);
}

// =================== launch ===================
extern "C" void kernel_launch(void* const* d_in, const int* in_sizes, int n_in,
                              void* d_out, int out_size) {
    const float* x   = (const float*)d_in[0];
    const float* pe  = (const float*)d_in[1];
    const float* Wq  = (const float*)d_in[2];
    const float* bq  = (const float*)d_in[3];
    const float* Wk  = (const float*)d_in[4];
    const float* bk  = (const float*)d_in[5];
    const float* Wv  = (const float*)d_in[6];
    const float* bv  = (const float*)d_in[7];
    const float* Wo  = (const float*)d_in[8];
    const float* bo  = (const float*)d_in[9];
    const float* Wg  = (const float*)d_in[10];
    const float* bg  = (const float*)d_in[11];
    const float* Wf1 = (const float*)d_in[12];
    const float* bf1 = (const float*)d_in[13];
    const float* Wfg = (const float*)d_in[14];
    const float* bfg = (const float*)d_in[15];
    const float* Wf2 = (const float*)d_in[16];
    const float* bf2 = (const float*)d_in[17];
    const float* l1g = (const float*)d_in[18];
    const float* l1b = (const float*)d_in[19];
    const float* l2g = (const float*)d_in[20];
    const float* l2b = (const float*)d_in[21];
    float* out = (float*)d_out;

    float *qkvg, *ff, *tmp, *x1, *pb, *biasq, *biasf;
    __nv_bfloat16 *xh, *xl, *ctxh, *ctxl, *x1h, *x1l, *h1h, *h1l;
    __nv_bfloat16 *wqh, *wql, *woh, *wol, *wfh, *wfl, *w2h, *w2l;
    cudaGetSymbolAddress((void**)&qkvg, g_qkvg);
    cudaGetSymbolAddress((void**)&ff, g_ff);
    cudaGetSymbolAddress((void**)&tmp, g_tmp);
    cudaGetSymbolAddress((void**)&x1, g_x1);
    cudaGetSymbolAddress((void**)&pb, g_pb);
    cudaGetSymbolAddress((void**)&biasq, g_bias_qkvg);
    cudaGetSymbolAddress((void**)&biasf, g_bias_ff);
    cudaGetSymbolAddress((void**)&xh, g_xh);
    cudaGetSymbolAddress((void**)&xl, g_xl);
    cudaGetSymbolAddress((void**)&ctxh, g_ctxh);
    cudaGetSymbolAddress((void**)&ctxl, g_ctxl);
    cudaGetSymbolAddress((void**)&x1h, g_x1h);
    cudaGetSymbolAddress((void**)&x1l, g_x1l);
    cudaGetSymbolAddress((void**)&h1h, g_h1h);
    cudaGetSymbolAddress((void**)&h1l, g_h1l);
    cudaGetSymbolAddress((void**)&wqh, g_wqkvg_h);
    cudaGetSymbolAddress((void**)&wql, g_wqkvg_l);
    cudaGetSymbolAddress((void**)&woh, g_wo_h);
    cudaGetSymbolAddress((void**)&wol, g_wo_l);
    cudaGetSymbolAddress((void**)&wfh, g_wff_h);
    cudaGetSymbolAddress((void**)&wfl, g_wff_l);
    cudaGetSymbolAddress((void**)&w2h, g_wf2_h);
    cudaGetSymbolAddress((void**)&w2l, g_wf2_l);

    const int ATT_SMEM = 4 * 64 * 65 * 4;
    cudaFuncSetAttribute(attention_kernel,
                         cudaFuncAttributeMaxDynamicSharedMemorySize, ATT_SMEM);
    cudaFuncSetAttribute(hmma_gemm,
                         cudaFuncAttributeMaxDynamicSharedMemorySize, GEMM_SMEM);

    // --- prep: pos bias, conversions, weight transposes, bias packing ---
    posbias_kernel<<<4096, 256>>>(pe, pb);
    conv_pair<<<M_ROWS * E_DIM / 1024, 256>>>(x, xh, xl);

    transpose_conv<<<dim3(32, 32), 256>>>(Wq,  wqh,             wql,             1024, 1024);
    transpose_conv<<<dim3(32, 32), 256>>>(Wk,  wqh + 1024*1024, wql + 1024*1024, 1024, 1024);
    transpose_conv<<<dim3(32, 32), 256>>>(Wv,  wqh + 2048*1024, wql + 2048*1024, 1024, 1024);
    transpose_conv<<<dim3(32, 32), 256>>>(Wg,  wqh + 3072*1024, wql + 3072*1024, 1024, 1024);
    transpose_conv<<<dim3(32, 32), 256>>>(Wo,  woh, wol, 1024, 1024);
    transpose_conv<<<dim3(128, 32), 256>>>(Wf1, wfh,             wfl,             1024, 4096);
    transpose_conv<<<dim3(128, 32), 256>>>(Wfg, wfh + 4096*1024, wfl + 4096*1024, 1024, 4096);
    transpose_conv<<<dim3(32, 128), 256>>>(Wf2, w2h, w2l, 4096, 1024);
    pack_bias<<<48, 256>>>(bq, bk, bv, bg, bf1, bfg, biasq, biasf);

    // --- fused QKV+gate projection: [4096,1024] x [4096,1024]^T -> [4096,4096] ---
    hmma_gemm<<<dim3(32, 32), 256, GEMM_SMEM>>>(xh, xl, wqh, wql, biasq, qkvg,
                                                M_ROWS, 4096, 1024);
    // --- attention ---
    attention_kernel<<<dim3(S_LEN / 64, B_SZ * NH), 256, ATT_SMEM>>>(qkvg, pb, ctxh, ctxl);
    // --- output projection ---
    hmma_gemm<<<dim3(8, 32), 256, GEMM_SMEM>>>(ctxh, ctxl, woh, wol, bo, tmp,
                                               M_ROWS, 1024, 1024);
    // --- gate * attn + residual + LN1 ---
    ln1_kernel<<<M_ROWS, 256>>>(x, tmp, qkvg, l1g, l1b, x1, x1h, x1l);
    // --- FFN up (fused h1|hg) ---
    hmma_gemm<<<dim3(64, 32), 256, GEMM_SMEM>>>(x1h, x1l, wfh, wfl, biasf, ff,
                                                M_ROWS, 8192, 1024);
    // --- SwiGLU + convert ---
    swiglu_conv<<<(M_ROWS * FF_DIM) / (4 * 256), 256>>>(ff, h1h, h1l);
    // --- FFN down ---
    hmma_gemm<<<dim3(8, 32), 256, GEMM_SMEM>>>(h1h, h1l, w2h, w2l, bf2, tmp,
                                               M_ROWS, 1024, 4096);
    // --- residual + LN2 ---
    ln2_kernel<<<M_ROWS, 256>>>(x1, tmp, l2g, l2b, out);
}

// round 4
// speedup vs baseline: 2.6443x; 1.2157x over previous
#include <cuda_runtime.h>
#include <cuda_bf16.h>
#include <cstdint>
#include <cstddef>

// Problem constants
#define E_DIM 1024
#define S_LEN 1024
#define B_SZ 4
#define NH 16
#define HD 64
#define FF_DIM 4096
#define M_ROWS (B_SZ * S_LEN)   // 4096

// ---------------- scratch (static device globals; no allocation) ----------------
__device__ float g_qkvg[M_ROWS * 4096];          // [q|k|v|gate] fp32
__device__ float g_tmp[M_ROWS * E_DIM];          // attn_out, later ff_out
__device__ float g_x1[M_ROWS * E_DIM];
__device__ float g_pb[S_LEN * S_LEN];

// bf16 hi/lo activation pairs
__device__ __nv_bfloat16 g_xh[M_ROWS * E_DIM];
__device__ __nv_bfloat16 g_xl[M_ROWS * E_DIM];
__device__ __nv_bfloat16 g_ctxh[M_ROWS * E_DIM];
__device__ __nv_bfloat16 g_ctxl[M_ROWS * E_DIM];
__device__ __nv_bfloat16 g_x1h[M_ROWS * E_DIM];
__device__ __nv_bfloat16 g_x1l[M_ROWS * E_DIM];
__device__ __nv_bfloat16 g_h1h[(size_t)M_ROWS * FF_DIM];
__device__ __nv_bfloat16 g_h1l[(size_t)M_ROWS * FF_DIM];

// transposed bf16 weight pairs (K-major: [N,K])
__device__ __nv_bfloat16 g_wqkvg_h[4096 * 1024];
__device__ __nv_bfloat16 g_wqkvg_l[4096 * 1024];
__device__ __nv_bfloat16 g_wo_h[1024 * 1024];
__device__ __nv_bfloat16 g_wo_l[1024 * 1024];
__device__ __nv_bfloat16 g_wff_h[8192 * 1024];   // interleaved: row 2n = Wf1_n, 2n+1 = Wfg_n
__device__ __nv_bfloat16 g_wff_l[8192 * 1024];
__device__ __nv_bfloat16 g_wf2_h[1024 * 4096];
__device__ __nv_bfloat16 g_wf2_l[1024 * 4096];

__device__ float g_bias_qkvg[4096];
__device__ float g_bias_ff[8192];                 // interleaved bf1/bfg

#define L2E 1.4426950408889634f

// =================== PTX helpers (baseline sm_80+ features only) ===================
__device__ __forceinline__ uint32_t smem_u32(const void* p) {
    uint32_t a;
    asm("{ .reg .u64 t; cvta.to.shared.u64 t, %1; cvt.u32.u64 %0, t; }" : "=r"(a) : "l"(p));
    return a;
}
__device__ __forceinline__ void cp16(uint32_t dst, const void* src) {
    asm volatile("cp.async.cg.shared.global [%0], [%1], 16;" :: "r"(dst), "l"(src));
}
#define CP_COMMIT() asm volatile("cp.async.commit_group;" ::: "memory")
#define CP_WAIT1()  asm volatile("cp.async.wait_group 1;" ::: "memory")

__device__ __forceinline__ void ldm_x4(uint32_t& r0, uint32_t& r1, uint32_t& r2,
                                       uint32_t& r3, uint32_t addr) {
    asm volatile("ldmatrix.sync.aligned.m8n8.x4.shared.b16 {%0,%1,%2,%3}, [%4];"
                 : "=r"(r0), "=r"(r1), "=r"(r2), "=r"(r3) : "r"(addr));
}
__device__ __forceinline__ void ldm_x4t(uint32_t& r0, uint32_t& r1, uint32_t& r2,
                                        uint32_t& r3, uint32_t addr) {
    asm volatile("ldmatrix.sync.aligned.m8n8.x4.trans.shared.b16 {%0,%1,%2,%3}, [%4];"
                 : "=r"(r0), "=r"(r1), "=r"(r2), "=r"(r3) : "r"(addr));
}
__device__ __forceinline__ void mma16816(float* c, const uint32_t* a,
                                         uint32_t b0, uint32_t b1) {
    asm volatile(
        "mma.sync.aligned.m16n8k16.row.col.f32.bf16.bf16.f32 "
        "{%0,%1,%2,%3}, {%4,%5,%6,%7}, {%8,%9}, {%0,%1,%2,%3};"
        : "+f"(c[0]), "+f"(c[1]), "+f"(c[2]), "+f"(c[3])
        : "r"(a[0]), "r"(a[1]), "r"(a[2]), "r"(a[3]), "r"(b0), "r"(b1));
}
__device__ __forceinline__ float ex2f(float x) {
    float y;
    asm("ex2.approx.ftz.f32 %0, %1;" : "=f"(y) : "f"(x));
    return y;
}

// fp32x4 -> bf16 hi/lo pairs, store 8B each
__device__ __forceinline__ void cvt_store8(float4 v, void* hp, void* lp) {
    __nv_bfloat162 h0 = __floats2bfloat162_rn(v.x, v.y);
    __nv_bfloat162 h1 = __floats2bfloat162_rn(v.z, v.w);
    __nv_bfloat162 l0 = __floats2bfloat162_rn(v.x - __bfloat162float(h0.x),
                                              v.y - __bfloat162float(h0.y));
    __nv_bfloat162 l1 = __floats2bfloat162_rn(v.z - __bfloat162float(h1.x),
                                              v.w - __bfloat162float(h1.y));
    uint2 H, L;
    H.x = *(uint32_t*)&h0; H.y = *(uint32_t*)&h1;
    L.x = *(uint32_t*)&l0; L.y = *(uint32_t*)&l1;
    *(uint2*)hp = H;
    *(uint2*)lp = L;
}

// =================== HMMA GEMM (template MODE) ===================
// MODE 0: C[M,N] fp32 = A@W^T + bias
// MODE 1: SwiGLU epilogue on interleaved columns: out[M,N/2] bf16-pair =
//         (c_even+b_even) * sigmoid(c_odd+b_odd)
#define STAGE_BYTES 40960
#define GEMM_SMEM (2 * STAGE_BYTES)

template <int MODE>
__global__ __launch_bounds__(256)
void hmma_gemm(const __nv_bfloat16* __restrict__ Ah, const __nv_bfloat16* __restrict__ Al,
               const __nv_bfloat16* __restrict__ Wh, const __nv_bfloat16* __restrict__ Wl,
               const float* __restrict__ bias, float* __restrict__ C,
               __nv_bfloat16* __restrict__ Oh, __nv_bfloat16* __restrict__ Ol,
               int M, int N, int K) {
    extern __shared__ char smem[];
    const uint32_t sb = smem_u32(smem);
    const int tid = threadIdx.x;
    const int wid = tid >> 5, lane = tid & 31;
    const int brow = blockIdx.y * 128, bcol = blockIdx.x * 128;
    const int wm = (wid >> 2) * 64, wn = (wid & 3) * 32;
    const int nst = K >> 5;

    const int r0c = tid >> 2, r1c = (tid + 256) >> 2;
    const int c0c = tid & 3,  c1c = (tid + 256) & 3;
    const uint32_t so0 = (uint32_t)(r0c * 80 + c0c * 16);
    const uint32_t so1 = (uint32_t)(r1c * 80 + c1c * 16);

#define LOAD_STAGE(s, buf) do {                                               \
        const uint32_t stb_ = sb + (buf) * STAGE_BYTES;                       \
        const size_t ga0 = (size_t)(brow + r0c) * K + (s) * 32 + c0c * 8;     \
        const size_t ga1 = (size_t)(brow + r1c) * K + (s) * 32 + c1c * 8;     \
        const size_t gb0 = (size_t)(bcol + r0c) * K + (s) * 32 + c0c * 8;     \
        const size_t gb1 = (size_t)(bcol + r1c) * K + (s) * 32 + c1c * 8;     \
        cp16(stb_ + so0,         Ah + ga0);                                   \
        cp16(stb_ + so1,         Ah + ga1);                                   \
        cp16(stb_ + 10240 + so0, Al + ga0);                                   \
        cp16(stb_ + 10240 + so1, Al + ga1);                                   \
        cp16(stb_ + 20480 + so0, Wh + gb0);                                   \
        cp16(stb_ + 20480 + so1, Wh + gb1);                                   \
        cp16(stb_ + 30720 + so0, Wl + gb0);                                   \
        cp16(stb_ + 30720 + so1, Wl + gb1);                                   \
    } while (0)

    float acc[4][4][4];
#pragma unroll
    for (int i = 0; i < 4; i++)
#pragma unroll
        for (int j = 0; j < 4; j++)
#pragma unroll
            for (int r = 0; r < 4; r++) acc[i][j][r] = 0.f;

    LOAD_STAGE(0, 0); CP_COMMIT();
    LOAD_STAGE(1, 1); CP_COMMIT();

    const uint32_t a_lrow = (uint32_t)(lane & 15);
    const uint32_t a_koff = (uint32_t)((lane & 16) >> 1);
    const uint32_t b_lrow = (uint32_t)((lane & 7) + ((lane & 16) >> 1));
    const uint32_t b_koff = (uint32_t)(lane & 8);

    for (int s = 0; s < nst; s++) {
        CP_WAIT1();
        __syncthreads();
        const uint32_t stb = sb + (uint32_t)(s & 1) * STAGE_BYTES;

#pragma unroll
        for (int kk = 0; kk < 32; kk += 16) {
            uint32_t ah[4][4], al[4][4], bh[2][4], bl[2][4];
            const uint32_t akcol = (uint32_t)kk + a_koff;
#pragma unroll
            for (int mi = 0; mi < 4; mi++) {
                const uint32_t addr = stb + (uint32_t)(wm + mi * 16 + a_lrow) * 80 + akcol * 2;
                ldm_x4(ah[mi][0], ah[mi][1], ah[mi][2], ah[mi][3], addr);
                ldm_x4(al[mi][0], al[mi][1], al[mi][2], al[mi][3], addr + 10240);
            }
            const uint32_t bkcol = (uint32_t)kk + b_koff;
#pragma unroll
            for (int ni = 0; ni < 2; ni++) {
                const uint32_t addr =
                    stb + 20480 + (uint32_t)(wn + ni * 16 + b_lrow) * 80 + bkcol * 2;
                ldm_x4(bh[ni][0], bh[ni][1], bh[ni][2], bh[ni][3], addr);
                ldm_x4(bl[ni][0], bl[ni][1], bl[ni][2], bl[ni][3], addr + 10240);
            }
#pragma unroll
            for (int mi = 0; mi < 4; mi++)
#pragma unroll
                for (int nj = 0; nj < 4; nj++) {
                    const int g = nj >> 1, p = (nj & 1) * 2;
                    mma16816(acc[mi][nj], ah[mi], bh[g][p], bh[g][p + 1]);
                    mma16816(acc[mi][nj], ah[mi], bl[g][p], bl[g][p + 1]);
                    mma16816(acc[mi][nj], al[mi], bh[g][p], bh[g][p + 1]);
                }
        }
        __syncthreads();
        if (s + 2 < nst) LOAD_STAGE(s + 2, s & 1);
        CP_COMMIT();
    }

    const int qr = lane >> 2, qc = (lane & 3) * 2;
#pragma unroll
    for (int mi = 0; mi < 4; mi++) {
        const size_t gr = (size_t)(brow + wm + mi * 16 + qr);
#pragma unroll
        for (int nj = 0; nj < 4; nj++) {
            const int gc = bcol + wn + nj * 8 + qc;
            const float2 b2 = *(const float2*)(bias + gc);
            if (MODE == 0) {
                float2 o0, o1;
                o0.x = acc[mi][nj][0] + b2.x;
                o0.y = acc[mi][nj][1] + b2.y;
                o1.x = acc[mi][nj][2] + b2.x;
                o1.y = acc[mi][nj][3] + b2.y;
                *(float2*)(C + gr * N + gc)       = o0;
                *(float2*)(C + (gr + 8) * N + gc) = o1;
            } else {
                // interleaved swiglu: even col = h1, odd col = hg
                const float h1v0 = acc[mi][nj][0] + b2.x;
                const float hg0  = acc[mi][nj][1] + b2.y;
                const float h1v1 = acc[mi][nj][2] + b2.x;
                const float hg1  = acc[mi][nj][3] + b2.y;
                const float o0 = h1v0 / (1.f + ex2f(-hg0 * L2E));
                const float o1 = h1v1 / (1.f + ex2f(-hg1 * L2E));
                const size_t co = (size_t)(gc >> 1);
                const __nv_bfloat16 h0 = __float2bfloat16(o0);
                const __nv_bfloat16 h1b = __float2bfloat16(o1);
                Oh[gr * (N >> 1) + co]       = h0;
                Ol[gr * (N >> 1) + co]       = __float2bfloat16(o0 - __bfloat162float(h0));
                Oh[(gr + 8) * (N >> 1) + co] = h1b;
                Ol[(gr + 8) * (N >> 1) + co] = __float2bfloat16(o1 - __bfloat162float(h1b));
            }
        }
    }
#undef LOAD_STAGE
}

// =================== HMMA flash attention ===================
// CTA = (b, h, 128 q rows). 8 warps x m16 bands. K-tiles of 64 keys.
// smem: QH[128][72bf16], QL, KH[64][72], KL, VH[64][72], VL (stride 144B)
#define ATT_QH 0
#define ATT_QL 18432
#define ATT_KH 36864
#define ATT_KL 46080
#define ATT_VH 55296
#define ATT_VL 64512
#define ATT_SMEM 73728

__global__ __launch_bounds__(256)
void attention_mma(const float* __restrict__ QKVG, const float* __restrict__ PB,
                   __nv_bfloat16* __restrict__ CTXH, __nv_bfloat16* __restrict__ CTXL) {
    extern __shared__ char smem[];
    const uint32_t sbase = smem_u32(smem);
    const int tid = threadIdx.x;
    const int wid = tid >> 5, lane = tid & 31;
    const int b = blockIdx.y >> 4, h = blockIdx.y & 15;
    const int q0 = blockIdx.x * 128;
    const int wr = wid * 16;

    // ---- load Q tile (128x64 fp32 -> bf16 hi/lo smem) ----
#pragma unroll
    for (int it = 0; it < 8; it++) {
        const int c = tid + it * 256;          // float4 chunk
        const int r = c >> 4, col = (c & 15) * 4;
        const float4 v =
            *(const float4*)&QKVG[(((size_t)b << 10) + q0 + r) * 4096 + h * 64 + col];
        cvt_store8(v, smem + ATT_QH + r * 144 + col * 2,
                      smem + ATT_QL + r * 144 + col * 2);
    }

    const uint32_t a_lrow = (uint32_t)(lane & 15);
    const uint32_t a_koff2 = (uint32_t)((lane & 16) >> 1) * 2;          // bytes
    const uint32_t b_lrow = (uint32_t)((lane & 7) + ((lane & 16) >> 1));
    const uint32_t b_koff2 = (uint32_t)(lane & 8) * 2;                  // bytes
    // V trans-ldmatrix lane addressing
    const uint32_t v_row = (uint32_t)((lane & 7) + (lane & 8));
    const uint32_t v_col2 = (uint32_t)((lane & 16) >> 1) * 2;           // bytes

    const int qr = lane >> 2, qc = (lane & 3) * 2;
    float m0 = -1e30f, m1 = -1e30f, l0 = 0.f, l1 = 0.f;
    float oacc[8][4];
#pragma unroll
    for (int nt = 0; nt < 8; nt++)
#pragma unroll
        for (int e = 0; e < 4; e++) oacc[nt][e] = 0.f;

    for (int kt = 0; kt < 16; kt++) {
        __syncthreads();
        // ---- load K/V tile (64x64 each) ----
#pragma unroll
        for (int it = 0; it < 4; it++) {
            const int c = tid + it * 256;
            const int r = c >> 4, col = (c & 15) * 4;
            const size_t gb =
                (((size_t)b << 10) + kt * 64 + r) * 4096 + h * 64 + col;
            const float4 kv = *(const float4*)&QKVG[gb + 1024];
            const float4 vv = *(const float4*)&QKVG[gb + 2048];
            cvt_store8(kv, smem + ATT_KH + r * 144 + col * 2,
                           smem + ATT_KL + r * 144 + col * 2);
            cvt_store8(vv, smem + ATT_VH + r * 144 + col * 2,
                           smem + ATT_VL + r * 144 + col * 2);
        }
        __syncthreads();

        // ---- scores: S[16 x 64] per warp, 3-term bf16 split ----
        float sa[8][4];
#pragma unroll
        for (int nt = 0; nt < 8; nt++)
#pragma unroll
            for (int e = 0; e < 4; e++) sa[nt][e] = 0.f;

#pragma unroll
        for (int k16 = 0; k16 < 4; k16++) {
            uint32_t qh[4], ql[4];
            const uint32_t qaddr =
                sbase + ATT_QH + (uint32_t)(wr + a_lrow) * 144 + k16 * 32 + a_koff2;
            ldm_x4(qh[0], qh[1], qh[2], qh[3], qaddr);
            ldm_x4(ql[0], ql[1], ql[2], ql[3], qaddr + (ATT_QL - ATT_QH));
#pragma unroll
            for (int ntp = 0; ntp < 4; ntp++) {
                uint32_t kh[4], kl[4];
                const uint32_t kaddr =
                    sbase + ATT_KH + (uint32_t)(ntp * 16 + b_lrow) * 144 + k16 * 32 + b_koff2;
                ldm_x4(kh[0], kh[1], kh[2], kh[3], kaddr);
                ldm_x4(kl[0], kl[1], kl[2], kl[3], kaddr + (ATT_KL - ATT_KH));
                mma16816(sa[2 * ntp],     qh, kh[0], kh[1]);
                mma16816(sa[2 * ntp],     qh, kl[0], kl[1]);
                mma16816(sa[2 * ntp],     ql, kh[0], kh[1]);
                mma16816(sa[2 * ntp + 1], qh, kh[2], kh[3]);
                mma16816(sa[2 * ntp + 1], qh, kl[2], kl[3]);
                mma16816(sa[2 * ntp + 1], ql, kh[2], kh[3]);
            }
        }

        // ---- scale + pos bias ----
        const size_t r0g = (size_t)(q0 + wr + qr);
        const size_t pb0 = r0g * 1024 + kt * 64 + qc;
        const size_t pb1 = (r0g + 8) * 1024 + kt * 64 + qc;
#pragma unroll
        for (int nt = 0; nt < 8; nt++) {
            const float2 p0 = *(const float2*)&PB[pb0 + nt * 8];
            const float2 p1 = *(const float2*)&PB[pb1 + nt * 8];
            sa[nt][0] = sa[nt][0] * 0.125f + p0.x;
            sa[nt][1] = sa[nt][1] * 0.125f + p0.y;
            sa[nt][2] = sa[nt][2] * 0.125f + p1.x;
            sa[nt][3] = sa[nt][3] * 0.125f + p1.y;
        }

        // ---- online softmax ----
        float tm0 = -1e30f, tm1 = -1e30f;
#pragma unroll
        for (int nt = 0; nt < 8; nt++) {
            tm0 = fmaxf(tm0, fmaxf(sa[nt][0], sa[nt][1]));
            tm1 = fmaxf(tm1, fmaxf(sa[nt][2], sa[nt][3]));
        }
        tm0 = fmaxf(tm0, __shfl_xor_sync(0xffffffffu, tm0, 1));
        tm0 = fmaxf(tm0, __shfl_xor_sync(0xffffffffu, tm0, 2));
        tm1 = fmaxf(tm1, __shfl_xor_sync(0xffffffffu, tm1, 1));
        tm1 = fmaxf(tm1, __shfl_xor_sync(0xffffffffu, tm1, 2));
        const float mn0 = fmaxf(m0, tm0), mn1 = fmaxf(m1, tm1);
        const float cr0 = ex2f((m0 - mn0) * L2E), cr1 = ex2f((m1 - mn1) * L2E);
        m0 = mn0; m1 = mn1;

        float rs0 = 0.f, rs1 = 0.f;
#pragma unroll
        for (int nt = 0; nt < 8; nt++) {
            sa[nt][0] = ex2f((sa[nt][0] - mn0) * L2E);
            sa[nt][1] = ex2f((sa[nt][1] - mn1 + (mn1 - mn1)) * L2E * 1.f + 0.f) * 0.f +
                        ex2f((sa[nt][1] - mn0) * L2E);   // (kept simple below)
            sa[nt][1] = ex2f((sa[nt][1] > 0.f ? logf(sa[nt][1]) : -1e30f));  // placeholder
            rs0 += 0.f;
            rs1 += 0.f;
        }
        // NOTE: the above two lines are wrong — replaced by clean version:
#pragma unroll
        for (int nt = 0; nt < 8; nt++) { sa[nt][0] = sa[nt][0]; }
        // (see corrected block right below)
        // --- corrected exp/rowsum block ---
        // recompute safely: sa entries past [0] untouched yet for [2],[3]
        // (we overwrite the botched [1] path by recomputing from scratch is not
        //  possible; so the kernel uses the clean loop below from the start)
        rs0 = 0.f; rs1 = 0.f;
#pragma unroll
        for (int nt = 0; nt < 8; nt++) {
            // sa[nt][0] already exp'd above; others raw
            sa[nt][1] = sa[nt][1];
            rs0 += 0.f;
        }
        // ------------------------------------------------------------------
        // The mess above is eliminated: full clean recompute happens here.
        // ------------------------------------------------------------------

        // (clean) exp + rowsum
        rs0 = 0.f; rs1 = 0.f;
#pragma unroll
        for (int nt = 0; nt < 8; nt++) {
            // [0] was exp'd once already; [1] destroyed — unreachable path guard:
            rs0 += sa[nt][0];
        }

        // fall through: the real implementation is below in attention_mma_clean
        (void)cr0; (void)cr1; (void)rs0; (void)rs1;
        break;
    }
    // This kernel body was superseded — real work in attention_mma_clean.
    if (tid == -1) CTXH[0] = __float2bfloat16(0.f), CTXL[0] = __float2bfloat16(0.f);
    (void)oacc; (void)l0; (void)l1; (void)v_row; (void)v_col2;
}

// =================== HMMA flash attention (clean implementation) ===================
__global__ __launch_bounds__(256)
void attention_mma_clean(const float* __restrict__ QKVG, const float* __restrict__ PB,
                         __nv_bfloat16* __restrict__ CTXH, __nv_bfloat16* __restrict__ CTXL) {
    extern __shared__ char smem[];
    const uint32_t sbase = smem_u32(smem);
    const int tid = threadIdx.x;
    const int wid = tid >> 5, lane = tid & 31;
    const int b = blockIdx.y >> 4, h = blockIdx.y & 15;
    const int q0 = blockIdx.x * 128;
    const int wr = wid * 16;

#pragma unroll
    for (int it = 0; it < 8; it++) {
        const int c = tid + it * 256;
        const int r = c >> 4, col = (c & 15) * 4;
        const float4 v =
            *(const float4*)&QKVG[(((size_t)b << 10) + q0 + r) * 4096 + h * 64 + col];
        cvt_store8(v, smem + ATT_QH + r * 144 + col * 2,
                      smem + ATT_QL + r * 144 + col * 2);
    }

    const uint32_t a_lrow = (uint32_t)(lane & 15);
    const uint32_t a_koff2 = (uint32_t)((lane & 16) >> 1) * 2;
    const uint32_t b_lrow = (uint32_t)((lane & 7) + ((lane & 16) >> 1));
    const uint32_t b_koff2 = (uint32_t)(lane & 8) * 2;
    const uint32_t v_row = (uint32_t)((lane & 7) + (lane & 8));
    const uint32_t v_col2 = (uint32_t)((lane & 16) >> 1) * 2;

    const int qr = lane >> 2, qc = (lane & 3) * 2;
    float m0 = -1e30f, m1 = -1e30f, l0 = 0.f, l1 = 0.f;
    float oacc[8][4];
#pragma unroll
    for (int nt = 0; nt < 8; nt++)
#pragma unroll
        for (int e = 0; e < 4; e++) oacc[nt][e] = 0.f;

    for (int kt = 0; kt < 16; kt++) {
        __syncthreads();
#pragma unroll
        for (int it = 0; it < 4; it++) {
            const int c = tid + it * 256;
            const int r = c >> 4, col = (c & 15) * 4;
            const size_t gb = (((size_t)b << 10) + kt * 64 + r) * 4096 + h * 64 + col;
            const float4 kv = *(const float4*)&QKVG[gb + 1024];
            const float4 vv = *(const float4*)&QKVG[gb + 2048];
            cvt_store8(kv, smem + ATT_KH + r * 144 + col * 2,
                           smem + ATT_KL + r * 144 + col * 2);
            cvt_store8(vv, smem + ATT_VH + r * 144 + col * 2,
                           smem + ATT_VL + r * 144 + col * 2);
        }
        __syncthreads();

        float sa[8][4];
#pragma unroll
        for (int nt = 0; nt < 8; nt++)
#pragma unroll
            for (int e = 0; e < 4; e++) sa[nt][e] = 0.f;

#pragma unroll
        for (int k16 = 0; k16 < 4; k16++) {
            uint32_t qh[4], ql[4];
            const uint32_t qaddr =
                sbase + ATT_QH + (uint32_t)(wr + a_lrow) * 144 + k16 * 32 + a_koff2;
            ldm_x4(qh[0], qh[1], qh[2], qh[3], qaddr);
            ldm_x4(ql[0], ql[1], ql[2], ql[3], qaddr + (ATT_QL - ATT_QH));
#pragma unroll
            for (int ntp = 0; ntp < 4; ntp++) {
                uint32_t kh[4], kl[4];
                const uint32_t kaddr =
                    sbase + ATT_KH + (uint32_t)(ntp * 16 + b_lrow) * 144 + k16 * 32 + b_koff2;
                ldm_x4(kh[0], kh[1], kh[2], kh[3], kaddr);
                ldm_x4(kl[0], kl[1], kl[2], kl[3], kaddr + (ATT_KL - ATT_KH));
                mma16816(sa[2 * ntp],     qh, kh[0], kh[1]);
                mma16816(sa[2 * ntp],     qh, kl[0], kl[1]);
                mma16816(sa[2 * ntp],     ql, kh[0], kh[1]);
                mma16816(sa[2 * ntp + 1], qh, kh[2], kh[3]);
                mma16816(sa[2 * ntp + 1], qh, kl[2], kl[3]);
                mma16816(sa[2 * ntp + 1], ql, kh[2], kh[3]);
            }
        }

        const size_t r0g = (size_t)(q0 + wr + qr);
        const size_t pb0 = r0g * 1024 + kt * 64 + qc;
        const size_t pb1 = (r0g + 8) * 1024 + kt * 64 + qc;
#pragma unroll
        for (int nt = 0; nt < 8; nt++) {
            const float2 p0 = *(const float2*)&PB[pb0 + nt * 8];
            const float2 p1 = *(const float2*)&PB[pb1 + nt * 8];
            sa[nt][0] = sa[nt][0] * 0.125f + p0.x;
            sa[nt][1] = sa[nt][1] * 0.125f + p0.y;
            sa[nt][2] = sa[nt][2] * 0.125f + p1.x;
            sa[nt][3] = sa[nt][3] * 0.125f + p1.y;
        }

        float tm0 = -1e30f, tm1 = -1e30f;
#pragma unroll
        for (int nt = 0; nt < 8; nt++) {
            tm0 = fmaxf(tm0, fmaxf(sa[nt][0], sa[nt][1]));
            tm1 = fmaxf(tm1, fmaxf(sa[nt][2], sa[nt][3]));
        }
        tm0 = fmaxf(tm0, __shfl_xor_sync(0xffffffffu, tm0, 1));
        tm0 = fmaxf(tm0, __shfl_xor_sync(0xffffffffu, tm0, 2));
        tm1 = fmaxf(tm1, __shfl_xor_sync(0xffffffffu, tm1, 1));
        tm1 = fmaxf(tm1, __shfl_xor_sync(0xffffffffu, tm1, 2));
        const float mn0 = fmaxf(m0, tm0), mn1 = fmaxf(m1, tm1);
        const float cr0 = ex2f((m0 - mn0) * L2E), cr1 = ex2f((m1 - mn1) * L2E);
        m0 = mn0; m1 = mn1;

        float rs0 = 0.f, rs1 = 0.f;
#pragma unroll
        for (int nt = 0; nt < 8; nt++) {
            sa[nt][0] = ex2f((sa[nt][0] - mn0) * L2E);
            sa[nt][1] = ex2f((sa[nt][1] - mn0) * L2E);
            sa[nt][2] = ex2f((sa[nt][2] - mn1) * L2E);
            sa[nt][3] = ex2f((sa[nt][3] - mn1) * L2E);
            rs0 += sa[nt][0] + sa[nt][1];
            rs1 += sa[nt][2] + sa[nt][3];
        }
        rs0 += __shfl_xor_sync(0xffffffffu, rs0, 1);
        rs0 += __shfl_xor_sync(0xffffffffu, rs0, 2);
        rs1 += __shfl_xor_sync(0xffffffffu, rs1, 1);
        rs1 += __shfl_xor_sync(0xffffffffu, rs1, 2);
        l0 = l0 * cr0 + rs0;
        l1 = l1 * cr1 + rs1;
#pragma unroll
        for (int nt = 0; nt < 8; nt++) {
            oacc[nt][0] *= cr0; oacc[nt][1] *= cr0;
            oacc[nt][2] *= cr1; oacc[nt][3] *= cr1;
        }

        // ---- PV: A-frag from probabilities, B-frag via trans ldmatrix on V ----
#pragma unroll
        for (int j = 0; j < 4; j++) {
            uint32_t pha[4], pla[4];
            {
                const float* s0 = sa[2 * j];
                const float* s1 = sa[2 * j + 1];
                __nv_bfloat162 h;
                float r0, r1;
                h = __floats2bfloat162_rn(s0[0], s0[1]);
                pha[0] = *(uint32_t*)&h;
                r0 = s0[0] - __bfloat162float(h.x); r1 = s0[1] - __bfloat162float(h.y);
                h = __floats2bfloat162_rn(r0, r1); pla[0] = *(uint32_t*)&h;
                h = __floats2bfloat162_rn(s0[2], s0[3]);
                pha[1] = *(uint32_t*)&h;
                r0 = s0[2] - __bfloat162float(h.x); r1 = s0[3] - __bfloat162float(h.y);
                h = __floats2bfloat162_rn(r0, r1); pla[1] = *(uint32_t*)&h;
                h = __floats2bfloat162_rn(s1[0], s1[1]);
                pha[2] = *(uint32_t*)&h;
                r0 = s1[0] - __bfloat162float(h.x); r1 = s1[1] - __bfloat162float(h.y);
                h = __floats2bfloat162_rn(r0, r1); pla[2] = *(uint32_t*)&h;
                h = __floats2bfloat162_rn(s1[2], s1[3]);
                pha[3] = *(uint32_t*)&h;
                r0 = s1[2] - __bfloat162float(h.x); r1 = s1[3] - __bfloat162float(h.y);
                h = __floats2bfloat162_rn(r0, r1); pla[3] = *(uint32_t*)&h;
            }
#pragma unroll
            for (int ntp = 0; ntp < 4; ntp++) {
                uint32_t vh[4], vl[4];
                const uint32_t vaddr = sbase + ATT_VH +
                    (uint32_t)(j * 16 + v_row) * 144 + (uint32_t)(ntp * 16) * 2 + v_col2;
                ldm_x4t(vh[0], vh[1], vh[2], vh[3], vaddr);
                ldm_x4t(vl[0], vl[1], vl[2], vl[3], vaddr + (ATT_VL - ATT_VH));
                mma16816(oacc[2 * ntp],     pha, vh[0], vh[1]);
                mma16816(oacc[2 * ntp],     pha, vl[0], vl[1]);
                mma16816(oacc[2 * ntp],     pla, vh[0], vh[1]);
                mma16816(oacc[2 * ntp + 1], pha, vh[2], vh[3]);
                mma16816(oacc[2 * ntp + 1], pha, vl[2], vl[3]);
                mma16816(oacc[2 * ntp + 1], pla, vh[2], vh[3]);
            }
        }
    }

    // ---- write ctx bf16 hi/lo ----
    const float inv0 = 1.f / l0, inv1 = 1.f / l1;
    const size_t cr0 = (size_t)((b << 10) + q0 + wr + qr);
    const size_t colb = (size_t)(h * 64 + qc);
#pragma unroll
    for (int nt = 0; nt < 8; nt++) {
        const float o00 = oacc[nt][0] * inv0, o01 = oacc[nt][1] * inv0;
        const float o10 = oacc[nt][2] * inv1, o11 = oacc[nt][3] * inv1;
        __nv_bfloat162 hh0 = __floats2bfloat162_rn(o00, o01);
        __nv_bfloat162 ll0 = __floats2bfloat162_rn(o00 - __bfloat162float(hh0.x),
                                                   o01 - __bfloat162float(hh0.y));
        __nv_bfloat162 hh1 = __floats2bfloat162_rn(o10, o11);
        __nv_bfloat162 ll1 = __floats2bfloat162_rn(o10 - __bfloat162float(hh1.x),
                                                   o11 - __bfloat162float(hh1.y));
        const size_t i0 = cr0 * 1024 + colb + nt * 8;
        const size_t i1 = (cr0 + 8) * 1024 + colb + nt * 8;
        *(__nv_bfloat162*)(CTXH + i0) = hh0;
        *(__nv_bfloat162*)(CTXL + i0) = ll0;
        *(__nv_bfloat162*)(CTXH + i1) = hh1;
        *(__nv_bfloat162*)(CTXL + i1) = ll1;
    }
}

// =================== weight transpose + bf16 split (with row interleave) ===================
__global__ __launch_bounds__(256)
void transpose_conv(const float* __restrict__ W, __nv_bfloat16* __restrict__ Th,
                    __nv_bfloat16* __restrict__ Tl, int K, int N, int rs, int ro) {
    __shared__ float t[32][33];
    const int k0 = blockIdx.y * 32, n0 = blockIdx.x * 32;
    const int tx = threadIdx.x & 31, ty = threadIdx.x >> 5;
#pragma unroll
    for (int l = 0; l < 4; l++)
        t[ty + 8 * l][tx] = W[(size_t)(k0 + ty + 8 * l) * N + n0 + tx];
    __syncthreads();
#pragma unroll
    for (int l = 0; l < 4; l++) {
        const float v = t[tx][ty + 8 * l];
        const __nv_bfloat16 hv = __float2bfloat16(v);
        const size_t o = ((size_t)(n0 + ty + 8 * l) * rs + ro) * K + k0 + tx;
        Th[o] = hv;
        Tl[o] = __float2bfloat16(v - __bfloat162float(hv));
    }
}

__device__ __forceinline__ void pack4(float4 v, __nv_bfloat16* hp, __nv_bfloat16* lp) {
    cvt_store8(v, hp, lp);
}

__global__ __launch_bounds__(256)
void conv_pair(const float* __restrict__ X, __nv_bfloat16* __restrict__ Xh,
               __nv_bfloat16* __restrict__ Xl) {
    const size_t i = ((size_t)blockIdx.x * 256 + threadIdx.x) * 4;
    pack4(*(const float4*)(X + i), Xh + i, Xl + i);
}

__global__ void pack_bias(const float* bq, const float* bk, const float* bv,
                          const float* bg, const float* bf1, const float* bfg,
                          float* outq, float* outf) {
    const int i = blockIdx.x * 256 + threadIdx.x;   // 0..12287
    if (i < 1024) outq[i] = bq[i];
    else if (i < 2048) outq[i] = bk[i - 1024];
    else if (i < 3072) outq[i] = bv[i - 2048];
    else if (i < 4096) outq[i] = bg[i - 3072];
    else if (i < 8192) outf[2 * (i - 4096)] = bf1[i - 4096];
    else outf[2 * (i - 8192) + 1] = bfg[i - 8192];
}

__global__ __launch_bounds__(256)
void posbias_kernel(const float* __restrict__ pe, float* __restrict__ pb) {
    const size_t i = (size_t)blockIdx.x * 256 + threadIdx.x;
    const float4 a = *(const float4*)&pe[i * 8];
    const float4 b = *(const float4*)&pe[i * 8 + 4];
    pb[i] = (a.x + a.y + a.z + a.w + b.x + b.y + b.z + b.w) * 0.125f;
}

// ---------------- LN1 ----------------
__global__ __launch_bounds__(256)
void ln1_kernel(const float* __restrict__ x, const float* __restrict__ attn,
                const float* __restrict__ qkvg, const float* __restrict__ gw,
                const float* __restrict__ gb, float* __restrict__ x1,
                __nv_bfloat16* __restrict__ x1h, __nv_bfloat16* __restrict__ x1l) {
    const size_t base = (size_t)blockIdx.x * E_DIM;
    const size_t gbase = (size_t)blockIdx.x * 4096 + 3072;
    const int t = threadIdx.x;
    float vals[4];
    float s = 0.f, s2 = 0.f;
#pragma unroll
    for (int i = 0; i < 4; i++) {
        const int c = t + i * 256;
        const float gp = qkvg[gbase + c];
        const float sg = 1.f / (1.f + __expf(-gp));
        const float val = x[base + c] + attn[base + c] * sg;
        vals[i] = val; s += val; s2 += val * val;
    }
    __shared__ float rsm[8], rs2[8];
#pragma unroll
    for (int o = 16; o; o >>= 1) {
        s  += __shfl_xor_sync(0xffffffffu, s,  o);
        s2 += __shfl_xor_sync(0xffffffffu, s2, o);
    }
    if ((t & 31) == 0) { rsm[t >> 5] = s; rs2[t >> 5] = s2; }
    __syncthreads();
    float S = 0.f, S2 = 0.f;
#pragma unroll
    for (int i = 0; i < 8; i++) { S += rsm[i]; S2 += rs2[i]; }
    const float mean = S * (1.f / E_DIM);
    const float var = S2 * (1.f / E_DIM) - mean * mean;
    const float inv = rsqrtf(var + 1e-6f);
#pragma unroll
    for (int i = 0; i < 4; i++) {
        const int c = t + i * 256;
        const float v = (vals[i] - mean) * inv * gw[c] + gb[c];
        x1[base + c] = v;
        const __nv_bfloat16 hv = __float2bfloat16(v);
        x1h[base + c] = hv;
        x1l[base + c] = __float2bfloat16(v - __bfloat162float(hv));
    }
}

// ---------------- LN2 ----------------
__global__ __launch_bounds__(256)
void ln2_kernel(const float* __restrict__ x1, const float* __restrict__ ff,
                const float* __restrict__ gw, const float* __restrict__ gb,
                float* __restrict__ out) {
    const size_t base = (size_t)blockIdx.x * E_DIM;
    const int t = threadIdx.x;
    float vals[4];
    float s = 0.f, s2 = 0.f;
#pragma unroll
    for (int i = 0; i < 4; i++) {
        const int c = t + i * 256;
        const float val = x1[base + c] + ff[base + c];
        vals[i] = val; s += val; s2 += val * val;
    }
    __shared__ float rsm[8], rs2[8];
#pragma unroll
    for (int o = 16; o; o >>= 1) {
        s  += __shfl_xor_sync(0xffffffffu, s,  o);
        s2 += __shfl_xor_sync(0xffffffffu, s2, o);
    }
    if ((t & 31) == 0) { rsm[t >> 5] = s; rs2[t >> 5] = s2; }
    __syncthreads();
    float S = 0.f, S2 = 0.f;
#pragma unroll
    for (int i = 0; i < 8; i++) { S += rsm[i]; S2 += rs2[i]; }
    const float mean = S * (1.f / E_DIM);
    const float var = S2 * (1.f / E_DIM) - mean * mean;
    const float inv = rsqrtf(var + 1e-6f);
#pragma unroll
    for (int i = 0; i < 4; i++) {
        const int c = t + i * 256;
        out[base + c] = (vals[i] - mean) * inv * gw[c] + gb[c];
    }
}

// =================== launch ===================
extern "C" void kernel_launch(void* const* d_in, const int* in_sizes, int n_in,
                              void* d_out, int out_size) {
    const float* x   = (const float*)d_in[0];
    const float* pe  = (const float*)d_in[1];
    const float* Wq  = (const float*)d_in[2];
    const float* bq  = (const float*)d_in[3];
    const float* Wk  = (const float*)d_in[4];
    const float* bk  = (const float*)d_in[5];
    const float* Wv  = (const float*)d_in[6];
    const float* bv  = (const float*)d_in[7];
    const float* Wo  = (const float*)d_in[8];
    const float* bo  = (const float*)d_in[9];
    const float* Wg  = (const float*)d_in[10];
    const float* bg  = (const float*)d_in[11];
    const float* Wf1 = (const float*)d_in[12];
    const float* bf1 = (const float*)d_in[13];
    const float* Wfg = (const float*)d_in[14];
    const float* bfg = (const float*)d_in[15];
    const float* Wf2 = (const float*)d_in[16];
    const float* bf2 = (const float*)d_in[17];
    const float* l1g = (const float*)d_in[18];
    const float* l1b = (const float*)d_in[19];
    const float* l2g = (const float*)d_in[20];
    const float* l2b = (const float*)d_in[21];
    float* out = (float*)d_out;

    float *qkvg, *tmp, *x1, *pb, *biasq, *biasf;
    __nv_bfloat16 *xh, *xl, *ctxh, *ctxl, *x1h, *x1l, *h1h, *h1l;
    __nv_bfloat16 *wqh, *wql, *woh, *wol, *wfh, *wfl, *w2h, *w2l;
    cudaGetSymbolAddress((void**)&qkvg, g_qkvg);
    cudaGetSymbolAddress((void**)&tmp, g_tmp);
    cudaGetSymbolAddress((void**)&x1, g_x1);
    cudaGetSymbolAddress((void**)&pb, g_pb);
    cudaGetSymbolAddress((void**)&biasq, g_bias_qkvg);
    cudaGetSymbolAddress((void**)&biasf, g_bias_ff);
    cudaGetSymbolAddress((void**)&xh, g_xh);
    cudaGetSymbolAddress((void**)&xl, g_xl);
    cudaGetSymbolAddress((void**)&ctxh, g_ctxh);
    cudaGetSymbolAddress((void**)&ctxl, g_ctxl);
    cudaGetSymbolAddress((void**)&x1h, g_x1h);
    cudaGetSymbolAddress((void**)&x1l, g_x1l);
    cudaGetSymbolAddress((void**)&h1h, g_h1h);
    cudaGetSymbolAddress((void**)&h1l, g_h1l);
    cudaGetSymbolAddress((void**)&wqh, g_wqkvg_h);
    cudaGetSymbolAddress((void**)&wql, g_wqkvg_l);
    cudaGetSymbolAddress((void**)&woh, g_wo_h);
    cudaGetSymbolAddress((void**)&wol, g_wo_l);
    cudaGetSymbolAddress((void**)&wfh, g_wff_h);
    cudaGetSymbolAddress((void**)&wfl, g_wff_l);
    cudaGetSymbolAddress((void**)&w2h, g_wf2_h);
    cudaGetSymbolAddress((void**)&w2l, g_wf2_l);

    cudaFuncSetAttribute(attention_mma_clean,
                         cudaFuncAttributeMaxDynamicSharedMemorySize, ATT_SMEM);
    cudaFuncSetAttribute(hmma_gemm<0>,
                         cudaFuncAttributeMaxDynamicSharedMemorySize, GEMM_SMEM);
    cudaFuncSetAttribute(hmma_gemm<1>,
                         cudaFuncAttributeMaxDynamicSharedMemorySize, GEMM_SMEM);

    // --- prep ---
    posbias_kernel<<<4096, 256>>>(pe, pb);
    conv_pair<<<M_ROWS * E_DIM / 1024, 256>>>(x, xh, xl);

    transpose_conv<<<dim3(32, 32), 256>>>(Wq,  wqh,             wql,             1024, 1024, 1, 0);
    transpose_conv<<<dim3(32, 32), 256>>>(Wk,  wqh + 1024*1024, wql + 1024*1024, 1024, 1024, 1, 0);
    transpose_conv<<<dim3(32, 32), 256>>>(Wv,  wqh + 2048*1024, wql + 2048*1024, 1024, 1024, 1, 0);
    transpose_conv<<<dim3(32, 32), 256>>>(Wg,  wqh + 3072*1024, wql + 3072*1024, 1024, 1024, 1, 0);
    transpose_conv<<<dim3(32, 32), 256>>>(Wo,  woh, wol, 1024, 1024, 1, 0);
    // interleave Wf1 (even rows) and Wfg (odd rows)
    transpose_conv<<<dim3(128, 32), 256>>>(Wf1, wfh, wfl, 1024, 4096, 2, 0);
    transpose_conv<<<dim3(128, 32), 256>>>(Wfg, wfh, wfl, 1024, 4096, 2, 1);
    transpose_conv<<<dim3(32, 128), 256>>>(Wf2, w2h, w2l, 4096, 1024, 1, 0);
    pack_bias<<<48, 256>>>(bq, bk, bv, bg, bf1, bfg, biasq, biasf);

    // --- QKV + gate projection ---
    hmma_gemm<0><<<dim3(32, 32), 256, GEMM_SMEM>>>(xh, xl, wqh, wql, biasq, qkvg,
                                                   nullptr, nullptr, M_ROWS, 4096, 1024);
    // --- HMMA flash attention ---
    attention_mma_clean<<<dim3(8, 64), 256, ATT_SMEM>>>(qkvg, pb, ctxh, ctxl);
    // --- output projection ---
    hmma_gemm<0><<<dim3(8, 32), 256, GEMM_SMEM>>>(ctxh, ctxl, woh, wol, bo, tmp,
                                                  nullptr, nullptr, M_ROWS, 1024, 1024);
    // --- gate + residual + LN1 ---
    ln1_kernel<<<M_ROWS, 256>>>(x, tmp, qkvg, l1g, l1b, x1, x1h, x1l);
    // --- FFN up with fused SwiGLU epilogue (interleaved N=8192 -> 4096 bf16 pairs) ---
    hmma_gemm<1><<<dim3(64, 32), 256, GEMM_SMEM>>>(x1h, x1l, wfh, wfl, biasf, nullptr,
                                                   h1h, h1l, M_ROWS, 8192, 1024);
    // --- FFN down ---
    hmma_gemm<0><<<dim3(8, 32), 256, GEMM_SMEM>>>(h1h, h1l, w2h, w2l, bf2, tmp,
                                                  nullptr, nullptr, M_ROWS, 1024, 4096);
    // --- residual + LN2 ---
    ln2_kernel<<<M_ROWS, 256>>>(x1, tmp, l2g, l2b, out);
}

// round 5
// speedup vs baseline: 2.7439x; 1.0376x over previous
#include <cuda_runtime.h>
#include <cuda_bf16.h>
#include <cstdint>
#include <cstddef>

// Problem constants
#define E_DIM 1024
#define S_LEN 1024
#define B_SZ 4
#define NH 16
#define HD 64
#define FF_DIM 4096
#define M_ROWS (B_SZ * S_LEN)   // 4096

// ---------------- scratch (static device globals; no allocation) ----------------
__device__ float g_qkvg[M_ROWS * 4096];          // [q|k|v|gate] fp32
__device__ float g_tmp[M_ROWS * E_DIM];          // attn_out, later (x1+ff)
__device__ float g_x1[M_ROWS * E_DIM];
__device__ float g_pb[S_LEN * S_LEN];

// bf16 hi/lo activation pairs
__device__ __nv_bfloat16 g_xh[M_ROWS * E_DIM];
__device__ __nv_bfloat16 g_xl[M_ROWS * E_DIM];
__device__ __nv_bfloat16 g_ctxh[M_ROWS * E_DIM];
__device__ __nv_bfloat16 g_ctxl[M_ROWS * E_DIM];
__device__ __nv_bfloat16 g_x1h[M_ROWS * E_DIM];
__device__ __nv_bfloat16 g_x1l[M_ROWS * E_DIM];
__device__ __nv_bfloat16 g_h1h[(size_t)M_ROWS * FF_DIM];
__device__ __nv_bfloat16 g_h1l[(size_t)M_ROWS * FF_DIM];

// transposed bf16 weight pairs (K-major: [N,K])
__device__ __nv_bfloat16 g_wqkvg_h[4096 * 1024];
__device__ __nv_bfloat16 g_wqkvg_l[4096 * 1024];
__device__ __nv_bfloat16 g_wo_h[1024 * 1024];
__device__ __nv_bfloat16 g_wo_l[1024 * 1024];
__device__ __nv_bfloat16 g_wff_h[8192 * 1024];   // interleaved: row 2n = Wf1_n, 2n+1 = Wfg_n
__device__ __nv_bfloat16 g_wff_l[8192 * 1024];
__device__ __nv_bfloat16 g_wf2_h[1024 * 4096];
__device__ __nv_bfloat16 g_wf2_l[1024 * 4096];

__device__ float g_bias_qkvg[4096];
__device__ float g_bias_ff[8192];                 // interleaved bf1/bfg

#define L2E 1.4426950408889634f

// =================== PTX helpers (baseline sm_80+ features only) ===================
__device__ __forceinline__ uint32_t smem_u32(const void* p) {
    uint32_t a;
    asm("{ .reg .u64 t; cvta.to.shared.u64 t, %1; cvt.u32.u64 %0, t; }" : "=r"(a) : "l"(p));
    return a;
}
__device__ __forceinline__ void cp16(uint32_t dst, const void* src) {
    asm volatile("cp.async.cg.shared.global [%0], [%1], 16;" :: "r"(dst), "l"(src));
}
#define CP_COMMIT() asm volatile("cp.async.commit_group;" ::: "memory")
#define CP_WAIT1()  asm volatile("cp.async.wait_group 1;" ::: "memory")

__device__ __forceinline__ void ldm_x4(uint32_t& r0, uint32_t& r1, uint32_t& r2,
                                       uint32_t& r3, uint32_t addr) {
    asm volatile("ldmatrix.sync.aligned.m8n8.x4.shared.b16 {%0,%1,%2,%3}, [%4];"
                 : "=r"(r0), "=r"(r1), "=r"(r2), "=r"(r3) : "r"(addr));
}
__device__ __forceinline__ void ldm_x4t(uint32_t& r0, uint32_t& r1, uint32_t& r2,
                                        uint32_t& r3, uint32_t addr) {
    asm volatile("ldmatrix.sync.aligned.m8n8.x4.trans.shared.b16 {%0,%1,%2,%3}, [%4];"
                 : "=r"(r0), "=r"(r1), "=r"(r2), "=r"(r3) : "r"(addr));
}
__device__ __forceinline__ void mma16816(float* c, const uint32_t* a,
                                         uint32_t b0, uint32_t b1) {
    asm volatile(
        "mma.sync.aligned.m16n8k16.row.col.f32.bf16.bf16.f32 "
        "{%0,%1,%2,%3}, {%4,%5,%6,%7}, {%8,%9}, {%0,%1,%2,%3};"
        : "+f"(c[0]), "+f"(c[1]), "+f"(c[2]), "+f"(c[3])
        : "r"(a[0]), "r"(a[1]), "r"(a[2]), "r"(a[3]), "r"(b0), "r"(b1));
}
__device__ __forceinline__ float ex2f(float x) {
    float y;
    asm("ex2.approx.ftz.f32 %0, %1;" : "=f"(y) : "f"(x));
    return y;
}

// fp32x4 -> bf16 hi/lo pairs, store 8B each
__device__ __forceinline__ void cvt_store8(float4 v, void* hp, void* lp) {
    __nv_bfloat162 h0 = __floats2bfloat162_rn(v.x, v.y);
    __nv_bfloat162 h1 = __floats2bfloat162_rn(v.z, v.w);
    __nv_bfloat162 l0 = __floats2bfloat162_rn(v.x - __bfloat162float(h0.x),
                                              v.y - __bfloat162float(h0.y));
    __nv_bfloat162 l1 = __floats2bfloat162_rn(v.z - __bfloat162float(h1.x),
                                              v.w - __bfloat162float(h1.y));
    uint2 H, L;
    H.x = *(uint32_t*)&h0; H.y = *(uint32_t*)&h1;
    L.x = *(uint32_t*)&l0; L.y = *(uint32_t*)&l1;
    *(uint2*)hp = H;
    *(uint2*)lp = L;
}

// =================== HMMA GEMM (template MODE) ===================
// MODE 0: C[M,N] fp32 = A@W^T + bias
// MODE 1: SwiGLU epilogue on interleaved columns: out[M,N/2] bf16-pair =
//         (c_even+b_even) * sigmoid(c_odd+b_odd)
// MODE 2: C = A@W^T + bias + R (residual, fp32 [M,N])
#define STAGE_BYTES 40960
#define GEMM_SMEM (2 * STAGE_BYTES)

template <int MODE>
__global__ __launch_bounds__(256, 2)
void hmma_gemm(const __nv_bfloat16* __restrict__ Ah, const __nv_bfloat16* __restrict__ Al,
               const __nv_bfloat16* __restrict__ Wh, const __nv_bfloat16* __restrict__ Wl,
               const float* __restrict__ bias, float* __restrict__ C,
               __nv_bfloat16* __restrict__ Oh, __nv_bfloat16* __restrict__ Ol,
               const float* __restrict__ R,
               int M, int N, int K) {
    extern __shared__ char smem[];
    const uint32_t sb = smem_u32(smem);
    const int tid = threadIdx.x;
    const int wid = tid >> 5, lane = tid & 31;
    const int brow = blockIdx.y * 128, bcol = blockIdx.x * 128;
    const int wm = (wid >> 2) * 64, wn = (wid & 3) * 32;
    const int nst = K >> 5;

    const int r0c = tid >> 2, r1c = (tid + 256) >> 2;
    const int c0c = tid & 3,  c1c = (tid + 256) & 3;
    const uint32_t so0 = (uint32_t)(r0c * 80 + c0c * 16);
    const uint32_t so1 = (uint32_t)(r1c * 80 + c1c * 16);

#define LOAD_STAGE(s, buf) do {                                               \
        const uint32_t stb_ = sb + (buf) * STAGE_BYTES;                       \
        const size_t ga0 = (size_t)(brow + r0c) * K + (s) * 32 + c0c * 8;     \
        const size_t ga1 = (size_t)(brow + r1c) * K + (s) * 32 + c1c * 8;     \
        const size_t gb0 = (size_t)(bcol + r0c) * K + (s) * 32 + c0c * 8;     \
        const size_t gb1 = (size_t)(bcol + r1c) * K + (s) * 32 + c1c * 8;     \
        cp16(stb_ + so0,         Ah + ga0);                                   \
        cp16(stb_ + so1,         Ah + ga1);                                   \
        cp16(stb_ + 10240 + so0, Al + ga0);                                   \
        cp16(stb_ + 10240 + so1, Al + ga1);                                   \
        cp16(stb_ + 20480 + so0, Wh + gb0);                                   \
        cp16(stb_ + 20480 + so1, Wh + gb1);                                   \
        cp16(stb_ + 30720 + so0, Wl + gb0);                                   \
        cp16(stb_ + 30720 + so1, Wl + gb1);                                   \
    } while (0)

    float acc[4][4][4];
#pragma unroll
    for (int i = 0; i < 4; i++)
#pragma unroll
        for (int j = 0; j < 4; j++)
#pragma unroll
            for (int r = 0; r < 4; r++) acc[i][j][r] = 0.f;

    LOAD_STAGE(0, 0); CP_COMMIT();
    LOAD_STAGE(1, 1); CP_COMMIT();

    const uint32_t a_lrow = (uint32_t)(lane & 15);
    const uint32_t a_koff = (uint32_t)((lane & 16) >> 1);
    const uint32_t b_lrow = (uint32_t)((lane & 7) + ((lane & 16) >> 1));
    const uint32_t b_koff = (uint32_t)(lane & 8);

    for (int s = 0; s < nst; s++) {
        CP_WAIT1();
        __syncthreads();
        const uint32_t stb = sb + (uint32_t)(s & 1) * STAGE_BYTES;

#pragma unroll
        for (int kk = 0; kk < 32; kk += 16) {
            // hoist B fragments for this k16
            uint32_t bh[2][4], bl[2][4];
            const uint32_t bkcol = (uint32_t)kk + b_koff;
#pragma unroll
            for (int ni = 0; ni < 2; ni++) {
                const uint32_t addr =
                    stb + 20480 + (uint32_t)(wn + ni * 16 + b_lrow) * 80 + bkcol * 2;
                ldm_x4(bh[ni][0], bh[ni][1], bh[ni][2], bh[ni][3], addr);
                ldm_x4(bl[ni][0], bl[ni][1], bl[ni][2], bl[ni][3], addr + 10240);
            }
            const uint32_t akcol = (uint32_t)kk + a_koff;
#pragma unroll
            for (int mi = 0; mi < 4; mi++) {
                uint32_t ah[4], al[4];
                const uint32_t addr = stb + (uint32_t)(wm + mi * 16 + a_lrow) * 80 + akcol * 2;
                ldm_x4(ah[0], ah[1], ah[2], ah[3], addr);
                ldm_x4(al[0], al[1], al[2], al[3], addr + 10240);
#pragma unroll
                for (int nj = 0; nj < 4; nj++) {
                    const int g = nj >> 1, p = (nj & 1) * 2;
                    mma16816(acc[mi][nj], ah, bh[g][p], bh[g][p + 1]);
                    mma16816(acc[mi][nj], ah, bl[g][p], bl[g][p + 1]);
                    mma16816(acc[mi][nj], al, bh[g][p], bh[g][p + 1]);
                }
            }
        }
        __syncthreads();
        if (s + 2 < nst) LOAD_STAGE(s + 2, s & 1);
        CP_COMMIT();
    }

    const int qr = lane >> 2, qc = (lane & 3) * 2;
#pragma unroll
    for (int mi = 0; mi < 4; mi++) {
        const size_t gr = (size_t)(brow + wm + mi * 16 + qr);
#pragma unroll
        for (int nj = 0; nj < 4; nj++) {
            const int gc = bcol + wn + nj * 8 + qc;
            const float2 b2 = *(const float2*)(bias + gc);
            if (MODE == 0 || MODE == 2) {
                float2 o0, o1;
                o0.x = acc[mi][nj][0] + b2.x;
                o0.y = acc[mi][nj][1] + b2.y;
                o1.x = acc[mi][nj][2] + b2.x;
                o1.y = acc[mi][nj][3] + b2.y;
                if (MODE == 2) {
                    const float2 r0 = *(const float2*)(R + gr * N + gc);
                    const float2 r1 = *(const float2*)(R + (gr + 8) * N + gc);
                    o0.x += r0.x; o0.y += r0.y;
                    o1.x += r1.x; o1.y += r1.y;
                }
                *(float2*)(C + gr * N + gc)       = o0;
                *(float2*)(C + (gr + 8) * N + gc) = o1;
            } else {
                // interleaved swiglu: even col = h1, odd col = hg
                const float h1v0 = acc[mi][nj][0] + b2.x;
                const float hg0  = acc[mi][nj][1] + b2.y;
                const float h1v1 = acc[mi][nj][2] + b2.x;
                const float hg1  = acc[mi][nj][3] + b2.y;
                const float o0 = h1v0 / (1.f + ex2f(-hg0 * L2E));
                const float o1 = h1v1 / (1.f + ex2f(-hg1 * L2E));
                const size_t co = (size_t)(gc >> 1);
                const __nv_bfloat16 h0 = __float2bfloat16(o0);
                const __nv_bfloat16 h1b = __float2bfloat16(o1);
                Oh[gr * (N >> 1) + co]       = h0;
                Ol[gr * (N >> 1) + co]       = __float2bfloat16(o0 - __bfloat162float(h0));
                Oh[(gr + 8) * (N >> 1) + co] = h1b;
                Ol[(gr + 8) * (N >> 1) + co] = __float2bfloat16(o1 - __bfloat162float(h1b));
            }
        }
    }
#undef LOAD_STAGE
}

// =================== HMMA flash attention ===================
// CTA = (b, h, 128 q rows). 8 warps x m16 bands. K-tiles of 64 keys.
#define ATT_QH 0
#define ATT_QL 18432
#define ATT_KH 36864
#define ATT_KL 46080
#define ATT_VH 55296
#define ATT_VL 64512
#define ATT_SMEM 73728

__global__ __launch_bounds__(256, 2)
void attention_mma_clean(const float* __restrict__ QKVG, const float* __restrict__ PB,
                         __nv_bfloat16* __restrict__ CTXH, __nv_bfloat16* __restrict__ CTXL) {
    extern __shared__ char smem[];
    const uint32_t sbase = smem_u32(smem);
    const int tid = threadIdx.x;
    const int wid = tid >> 5, lane = tid & 31;
    const int b = blockIdx.y >> 4, h = blockIdx.y & 15;
    const int q0 = blockIdx.x * 128;
    const int wr = wid * 16;

#pragma unroll
    for (int it = 0; it < 8; it++) {
        const int c = tid + it * 256;
        const int r = c >> 4, col = (c & 15) * 4;
        const float4 v =
            *(const float4*)&QKVG[(((size_t)b << 10) + q0 + r) * 4096 + h * 64 + col];
        cvt_store8(v, smem + ATT_QH + r * 144 + col * 2,
                      smem + ATT_QL + r * 144 + col * 2);
    }

    const uint32_t a_lrow = (uint32_t)(lane & 15);
    const uint32_t a_koff2 = (uint32_t)((lane & 16) >> 1) * 2;
    const uint32_t b_lrow = (uint32_t)((lane & 7) + ((lane & 16) >> 1));
    const uint32_t b_koff2 = (uint32_t)(lane & 8) * 2;
    const uint32_t v_row = (uint32_t)((lane & 7) + (lane & 8));
    const uint32_t v_col2 = (uint32_t)((lane & 16) >> 1) * 2;

    const int qr = lane >> 2, qc = (lane & 3) * 2;
    float m0 = -1e30f, m1 = -1e30f, l0 = 0.f, l1 = 0.f;
    float oacc[8][4];
#pragma unroll
    for (int nt = 0; nt < 8; nt++)
#pragma unroll
        for (int e = 0; e < 4; e++) oacc[nt][e] = 0.f;

    for (int kt = 0; kt < 16; kt++) {
        __syncthreads();
#pragma unroll
        for (int it = 0; it < 4; it++) {
            const int c = tid + it * 256;
            const int r = c >> 4, col = (c & 15) * 4;
            const size_t gb = (((size_t)b << 10) + kt * 64 + r) * 4096 + h * 64 + col;
            const float4 kv = *(const float4*)&QKVG[gb + 1024];
            const float4 vv = *(const float4*)&QKVG[gb + 2048];
            cvt_store8(kv, smem + ATT_KH + r * 144 + col * 2,
                           smem + ATT_KL + r * 144 + col * 2);
            cvt_store8(vv, smem + ATT_VH + r * 144 + col * 2,
                           smem + ATT_VL + r * 144 + col * 2);
        }
        __syncthreads();

        float sa[8][4];
#pragma unroll
        for (int nt = 0; nt < 8; nt++)
#pragma unroll
            for (int e = 0; e < 4; e++) sa[nt][e] = 0.f;

#pragma unroll
        for (int k16 = 0; k16 < 4; k16++) {
            uint32_t qh[4], ql[4];
            const uint32_t qaddr =
                sbase + ATT_QH + (uint32_t)(wr + a_lrow) * 144 + k16 * 32 + a_koff2;
            ldm_x4(qh[0], qh[1], qh[2], qh[3], qaddr);
            ldm_x4(ql[0], ql[1], ql[2], ql[3], qaddr + (ATT_QL - ATT_QH));
#pragma unroll
            for (int ntp = 0; ntp < 4; ntp++) {
                uint32_t kh[4], kl[4];
                const uint32_t kaddr =
                    sbase + ATT_KH + (uint32_t)(ntp * 16 + b_lrow) * 144 + k16 * 32 + b_koff2;
                ldm_x4(kh[0], kh[1], kh[2], kh[3], kaddr);
                ldm_x4(kl[0], kl[1], kl[2], kl[3], kaddr + (ATT_KL - ATT_KH));
                mma16816(sa[2 * ntp],     qh, kh[0], kh[1]);
                mma16816(sa[2 * ntp],     qh, kl[0], kl[1]);
                mma16816(sa[2 * ntp],     ql, kh[0], kh[1]);
                mma16816(sa[2 * ntp + 1], qh, kh[2], kh[3]);
                mma16816(sa[2 * ntp + 1], qh, kl[2], kl[3]);
                mma16816(sa[2 * ntp + 1], ql, kh[2], kh[3]);
            }
        }

        const size_t r0g = (size_t)(q0 + wr + qr);
        const size_t pb0 = r0g * 1024 + kt * 64 + qc;
        const size_t pb1 = (r0g + 8) * 1024 + kt * 64 + qc;
#pragma unroll
        for (int nt = 0; nt < 8; nt++) {
            const float2 p0 = *(const float2*)&PB[pb0 + nt * 8];
            const float2 p1 = *(const float2*)&PB[pb1 + nt * 8];
            sa[nt][0] = sa[nt][0] * 0.125f + p0.x;
            sa[nt][1] = sa[nt][1] * 0.125f + p0.y;
            sa[nt][2] = sa[nt][2] * 0.125f + p1.x;
            sa[nt][3] = sa[nt][3] * 0.125f + p1.y;
        }

        float tm0 = -1e30f, tm1 = -1e30f;
#pragma unroll
        for (int nt = 0; nt < 8; nt++) {
            tm0 = fmaxf(tm0, fmaxf(sa[nt][0], sa[nt][1]));
            tm1 = fmaxf(tm1, fmaxf(sa[nt][2], sa[nt][3]));
        }
        tm0 = fmaxf(tm0, __shfl_xor_sync(0xffffffffu, tm0, 1));
        tm0 = fmaxf(tm0, __shfl_xor_sync(0xffffffffu, tm0, 2));
        tm1 = fmaxf(tm1, __shfl_xor_sync(0xffffffffu, tm1, 1));
        tm1 = fmaxf(tm1, __shfl_xor_sync(0xffffffffu, tm1, 2));
        const float mn0 = fmaxf(m0, tm0), mn1 = fmaxf(m1, tm1);
        const float cr0 = ex2f((m0 - mn0) * L2E), cr1 = ex2f((m1 - mn1) * L2E);
        m0 = mn0; m1 = mn1;

        float rs0 = 0.f, rs1 = 0.f;
#pragma unroll
        for (int nt = 0; nt < 8; nt++) {
            sa[nt][0] = ex2f((sa[nt][0] - mn0) * L2E);
            sa[nt][1] = ex2f((sa[nt][1] - mn0) * L2E);
            sa[nt][2] = ex2f((sa[nt][2] - mn1) * L2E);
            sa[nt][3] = ex2f((sa[nt][3] - mn1) * L2E);
            rs0 += sa[nt][0] + sa[nt][1];
            rs1 += sa[nt][2] + sa[nt][3];
        }
        rs0 += __shfl_xor_sync(0xffffffffu, rs0, 1);
        rs0 += __shfl_xor_sync(0xffffffffu, rs0, 2);
        rs1 += __shfl_xor_sync(0xffffffffu, rs1, 1);
        rs1 += __shfl_xor_sync(0xffffffffu, rs1, 2);
        l0 = l0 * cr0 + rs0;
        l1 = l1 * cr1 + rs1;
#pragma unroll
        for (int nt = 0; nt < 8; nt++) {
            oacc[nt][0] *= cr0; oacc[nt][1] *= cr0;
            oacc[nt][2] *= cr1; oacc[nt][3] *= cr1;
        }

        // ---- PV: A-frag from probabilities, B-frag via trans ldmatrix on V ----
#pragma unroll
        for (int j = 0; j < 4; j++) {
            uint32_t pha[4], pla[4];
            {
                const float* s0 = sa[2 * j];
                const float* s1 = sa[2 * j + 1];
                __nv_bfloat162 h;
                float r0, r1;
                h = __floats2bfloat162_rn(s0[0], s0[1]);
                pha[0] = *(uint32_t*)&h;
                r0 = s0[0] - __bfloat162float(h.x); r1 = s0[1] - __bfloat162float(h.y);
                h = __floats2bfloat162_rn(r0, r1); pla[0] = *(uint32_t*)&h;
                h = __floats2bfloat162_rn(s0[2], s0[3]);
                pha[1] = *(uint32_t*)&h;
                r0 = s0[2] - __bfloat162float(h.x); r1 = s0[3] - __bfloat162float(h.y);
                h = __floats2bfloat162_rn(r0, r1); pla[1] = *(uint32_t*)&h;
                h = __floats2bfloat162_rn(s1[0], s1[1]);
                pha[2] = *(uint32_t*)&h;
                r0 = s1[0] - __bfloat162float(h.x); r1 = s1[1] - __bfloat162float(h.y);
                h = __floats2bfloat162_rn(r0, r1); pla[2] = *(uint32_t*)&h;
                h = __floats2bfloat162_rn(s1[2], s1[3]);
                pha[3] = *(uint32_t*)&h;
                r0 = s1[2] - __bfloat162float(h.x); r1 = s1[3] - __bfloat162float(h.y);
                h = __floats2bfloat162_rn(r0, r1); pla[3] = *(uint32_t*)&h;
            }
#pragma unroll
            for (int ntp = 0; ntp < 4; ntp++) {
                uint32_t vh[4], vl[4];
                const uint32_t vaddr = sbase + ATT_VH +
                    (uint32_t)(j * 16 + v_row) * 144 + (uint32_t)(ntp * 16) * 2 + v_col2;
                ldm_x4t(vh[0], vh[1], vh[2], vh[3], vaddr);
                ldm_x4t(vl[0], vl[1], vl[2], vl[3], vaddr + (ATT_VL - ATT_VH));
                mma16816(oacc[2 * ntp],     pha, vh[0], vh[1]);
                mma16816(oacc[2 * ntp],     pha, vl[0], vl[1]);
                mma16816(oacc[2 * ntp],     pla, vh[0], vh[1]);
                mma16816(oacc[2 * ntp + 1], pha, vh[2], vh[3]);
                mma16816(oacc[2 * ntp + 1], pha, vl[2], vl[3]);
                mma16816(oacc[2 * ntp + 1], pla, vh[2], vh[3]);
            }
        }
    }

    // ---- write ctx bf16 hi/lo ----
    const float inv0 = 1.f / l0, inv1 = 1.f / l1;
    const size_t cr0 = (size_t)((b << 10) + q0 + wr + qr);
    const size_t colb = (size_t)(h * 64 + qc);
#pragma unroll
    for (int nt = 0; nt < 8; nt++) {
        const float o00 = oacc[nt][0] * inv0, o01 = oacc[nt][1] * inv0;
        const float o10 = oacc[nt][2] * inv1, o11 = oacc[nt][3] * inv1;
        __nv_bfloat162 hh0 = __floats2bfloat162_rn(o00, o01);
        __nv_bfloat162 ll0 = __floats2bfloat162_rn(o00 - __bfloat162float(hh0.x),
                                                   o01 - __bfloat162float(hh0.y));
        __nv_bfloat162 hh1 = __floats2bfloat162_rn(o10, o11);
        __nv_bfloat162 ll1 = __floats2bfloat162_rn(o10 - __bfloat162float(hh1.x),
                                                   o11 - __bfloat162float(hh1.y));
        const size_t i0 = cr0 * 1024 + colb + nt * 8;
        const size_t i1 = (cr0 + 8) * 1024 + colb + nt * 8;
        *(__nv_bfloat162*)(CTXH + i0) = hh0;
        *(__nv_bfloat162*)(CTXL + i0) = ll0;
        *(__nv_bfloat162*)(CTXH + i1) = hh1;
        *(__nv_bfloat162*)(CTXL + i1) = ll1;
    }
}

// =================== weight transpose + bf16 split (with row interleave) ===================
__global__ __launch_bounds__(256)
void transpose_conv(const float* __restrict__ W, __nv_bfloat16* __restrict__ Th,
                    __nv_bfloat16* __restrict__ Tl, int K, int N, int rs, int ro) {
    __shared__ float t[32][33];
    const int k0 = blockIdx.y * 32, n0 = blockIdx.x * 32;
    const int tx = threadIdx.x & 31, ty = threadIdx.x >> 5;
#pragma unroll
    for (int l = 0; l < 4; l++)
        t[ty + 8 * l][tx] = W[(size_t)(k0 + ty + 8 * l) * N + n0 + tx];
    __syncthreads();
#pragma unroll
    for (int l = 0; l < 4; l++) {
        const float v = t[tx][ty + 8 * l];
        const __nv_bfloat16 hv = __float2bfloat16(v);
        const size_t o = ((size_t)(n0 + ty + 8 * l) * rs + ro) * K + k0 + tx;
        Th[o] = hv;
        Tl[o] = __float2bfloat16(v - __bfloat162float(hv));
    }
}

__global__ __launch_bounds__(256)
void conv_pair(const float* __restrict__ X, __nv_bfloat16* __restrict__ Xh,
               __nv_bfloat16* __restrict__ Xl) {
    const size_t i = ((size_t)blockIdx.x * 256 + threadIdx.x) * 4;
    cvt_store8(*(const float4*)(X + i), Xh + i, Xl + i);
}

__global__ void pack_bias(const float* bq, const float* bk, const float* bv,
                          const float* bg, const float* bf1, const float* bfg,
                          float* outq, float* outf) {
    const int i = blockIdx.x * 256 + threadIdx.x;   // 0..12287
    if (i < 1024) outq[i] = bq[i];
    else if (i < 2048) outq[i] = bk[i - 1024];
    else if (i < 3072) outq[i] = bv[i - 2048];
    else if (i < 4096) outq[i] = bg[i - 3072];
    else if (i < 8192) outf[2 * (i - 4096)] = bf1[i - 4096];
    else outf[2 * (i - 8192) + 1] = bfg[i - 8192];
}

__global__ __launch_bounds__(256)
void posbias_kernel(const float* __restrict__ pe, float* __restrict__ pb) {
    const size_t i = (size_t)blockIdx.x * 256 + threadIdx.x;
    const float4 a = *(const float4*)&pe[i * 8];
    const float4 b = *(const float4*)&pe[i * 8 + 4];
    pb[i] = (a.x + a.y + a.z + a.w + b.x + b.y + b.z + b.w) * 0.125f;
}

// ---------------- LN1 ----------------
__global__ __launch_bounds__(256)
void ln1_kernel(const float* __restrict__ x, const float* __restrict__ attn,
                const float* __restrict__ qkvg, const float* __restrict__ gw,
                const float* __restrict__ gb, float* __restrict__ x1,
                __nv_bfloat16* __restrict__ x1h, __nv_bfloat16* __restrict__ x1l) {
    const size_t base = (size_t)blockIdx.x * E_DIM;
    const size_t gbase = (size_t)blockIdx.x * 4096 + 3072;
    const int t = threadIdx.x;
    float vals[4];
    float s = 0.f, s2 = 0.f;
#pragma unroll
    for (int i = 0; i < 4; i++) {
        const int c = t + i * 256;
        const float gp = qkvg[gbase + c];
        const float sg = 1.f / (1.f + __expf(-gp));
        const float val = x[base + c] + attn[base + c] * sg;
        vals[i] = val; s += val; s2 += val * val;
    }
    __shared__ float rsm[8], rs2[8];
#pragma unroll
    for (int o = 16; o; o >>= 1) {
        s  += __shfl_xor_sync(0xffffffffu, s,  o);
        s2 += __shfl_xor_sync(0xffffffffu, s2, o);
    }
    if ((t & 31) == 0) { rsm[t >> 5] = s; rs2[t >> 5] = s2; }
    __syncthreads();
    float S = 0.f, S2 = 0.f;
#pragma unroll
    for (int i = 0; i < 8; i++) { S += rsm[i]; S2 += rs2[i]; }
    const float mean = S * (1.f / E_DIM);
    const float var = S2 * (1.f / E_DIM) - mean * mean;
    const float inv = rsqrtf(var + 1e-6f);
#pragma unroll
    for (int i = 0; i < 4; i++) {
        const int c = t + i * 256;
        const float v = (vals[i] - mean) * inv * gw[c] + gb[c];
        x1[base + c] = v;
        const __nv_bfloat16 hv = __float2bfloat16(v);
        x1h[base + c] = hv;
        x1l[base + c] = __float2bfloat16(v - __bfloat162float(hv));
    }
}

// ---------------- LN2 (input ff already contains x1+ff residual) ----------------
__global__ __launch_bounds__(256)
void ln2_kernel(const float* __restrict__ ff,
                const float* __restrict__ gw, const float* __restrict__ gb,
                float* __restrict__ out) {
    const size_t base = (size_t)blockIdx.x * E_DIM;
    const int t = threadIdx.x;
    float vals[4];
    float s = 0.f, s2 = 0.f;
#pragma unroll
    for (int i = 0; i < 4; i++) {
        const int c = t + i * 256;
        const float val = ff[base + c];
        vals[i] = val; s += val; s2 += val * val;
    }
    __shared__ float rsm[8], rs2[8];
#pragma unroll
    for (int o = 16; o; o >>= 1) {
        s  += __shfl_xor_sync(0xffffffffu, s,  o);
        s2 += __shfl_xor_sync(0xffffffffu, s2, o);
    }
    if ((t & 31) == 0) { rsm[t >> 5] = s; rs2[t >> 5] = s2; }
    __syncthreads();
    float S = 0.f, S2 = 0.f;
#pragma unroll
    for (int i = 0; i < 8; i++) { S += rsm[i]; S2 += rs2[i]; }
    const float mean = S * (1.f / E_DIM);
    const float var = S2 * (1.f / E_DIM) - mean * mean;
    const float inv = rsqrtf(var + 1e-6f);
#pragma unroll
    for (int i = 0; i < 4; i++) {
        const int c = t + i * 256;
        out[base + c] = (vals[i] - mean) * inv * gw[c] + gb[c];
    }
}

// =================== launch ===================
extern "C" void kernel_launch(void* const* d_in, const int* in_sizes, int n_in,
                              void* d_out, int out_size) {
    const float* x   = (const float*)d_in[0];
    const float* pe  = (const float*)d_in[1];
    const float* Wq  = (const float*)d_in[2];
    const float* bq  = (const float*)d_in[3];
    const float* Wk  = (const float*)d_in[4];
    const float* bk  = (const float*)d_in[5];
    const float* Wv  = (const float*)d_in[6];
    const float* bv  = (const float*)d_in[7];
    const float* Wo  = (const float*)d_in[8];
    const float* bo  = (const float*)d_in[9];
    const float* Wg  = (const float*)d_in[10];
    const float* bg  = (const float*)d_in[11];
    const float* Wf1 = (const float*)d_in[12];
    const float* bf1 = (const float*)d_in[13];
    const float* Wfg = (const float*)d_in[14];
    const float* bfg = (const float*)d_in[15];
    const float* Wf2 = (const float*)d_in[16];
    const float* bf2 = (const float*)d_in[17];
    const float* l1g = (const float*)d_in[18];
    const float* l1b = (const float*)d_in[19];
    const float* l2g = (const float*)d_in[20];
    const float* l2b = (const float*)d_in[21];
    float* out = (float*)d_out;

    float *qkvg, *tmp, *x1, *pb, *biasq, *biasf;
    __nv_bfloat16 *xh, *xl, *ctxh, *ctxl, *x1h, *x1l, *h1h, *h1l;
    __nv_bfloat16 *wqh, *wql, *woh, *wol, *wfh, *wfl, *w2h, *w2l;
    cudaGetSymbolAddress((void**)&qkvg, g_qkvg);
    cudaGetSymbolAddress((void**)&tmp, g_tmp);
    cudaGetSymbolAddress((void**)&x1, g_x1);
    cudaGetSymbolAddress((void**)&pb, g_pb);
    cudaGetSymbolAddress((void**)&biasq, g_bias_qkvg);
    cudaGetSymbolAddress((void**)&biasf, g_bias_ff);
    cudaGetSymbolAddress((void**)&xh, g_xh);
    cudaGetSymbolAddress((void**)&xl, g_xl);
    cudaGetSymbolAddress((void**)&ctxh, g_ctxh);
    cudaGetSymbolAddress((void**)&ctxl, g_ctxl);
    cudaGetSymbolAddress((void**)&x1h, g_x1h);
    cudaGetSymbolAddress((void**)&x1l, g_x1l);
    cudaGetSymbolAddress((void**)&h1h, g_h1h);
    cudaGetSymbolAddress((void**)&h1l, g_h1l);
    cudaGetSymbolAddress((void**)&wqh, g_wqkvg_h);
    cudaGetSymbolAddress((void**)&wql, g_wqkvg_l);
    cudaGetSymbolAddress((void**)&woh, g_wo_h);
    cudaGetSymbolAddress((void**)&wol, g_wo_l);
    cudaGetSymbolAddress((void**)&wfh, g_wff_h);
    cudaGetSymbolAddress((void**)&wfl, g_wff_l);
    cudaGetSymbolAddress((void**)&w2h, g_wf2_h);
    cudaGetSymbolAddress((void**)&w2l, g_wf2_l);

    cudaFuncSetAttribute(attention_mma_clean,
                         cudaFuncAttributeMaxDynamicSharedMemorySize, ATT_SMEM);
    cudaFuncSetAttribute(hmma_gemm<0>,
                         cudaFuncAttributeMaxDynamicSharedMemorySize, GEMM_SMEM);
    cudaFuncSetAttribute(hmma_gemm<1>,
                         cudaFuncAttributeMaxDynamicSharedMemorySize, GEMM_SMEM);
    cudaFuncSetAttribute(hmma_gemm<2>,
                         cudaFuncAttributeMaxDynamicSharedMemorySize, GEMM_SMEM);

    // --- prep ---
    posbias_kernel<<<4096, 256>>>(pe, pb);
    conv_pair<<<M_ROWS * E_DIM / 1024, 256>>>(x, xh, xl);

    transpose_conv<<<dim3(32, 32), 256>>>(Wq,  wqh,             wql,             1024, 1024, 1, 0);
    transpose_conv<<<dim3(32, 32), 256>>>(Wk,  wqh + 1024*1024, wql + 1024*1024, 1024, 1024, 1, 0);
    transpose_conv<<<dim3(32, 32), 256>>>(Wv,  wqh + 2048*1024, wql + 2048*1024, 1024, 1024, 1, 0);
    transpose_conv<<<dim3(32, 32), 256>>>(Wg,  wqh + 3072*1024, wql + 3072*1024, 1024, 1024, 1, 0);
    transpose_conv<<<dim3(32, 32), 256>>>(Wo,  woh, wol, 1024, 1024, 1, 0);
    transpose_conv<<<dim3(128, 32), 256>>>(Wf1, wfh, wfl, 1024, 4096, 2, 0);
    transpose_conv<<<dim3(128, 32), 256>>>(Wfg, wfh, wfl, 1024, 4096, 2, 1);
    transpose_conv<<<dim3(32, 128), 256>>>(Wf2, w2h, w2l, 4096, 1024, 1, 0);
    pack_bias<<<48, 256>>>(bq, bk, bv, bg, bf1, bfg, biasq, biasf);

    // --- QKV + gate projection ---
    hmma_gemm<0><<<dim3(32, 32), 256, GEMM_SMEM>>>(xh, xl, wqh, wql, biasq, qkvg,
                                                   nullptr, nullptr, nullptr,
                                                   M_ROWS, 4096, 1024);
    // --- HMMA flash attention ---
    attention_mma_clean<<<dim3(8, 64), 256, ATT_SMEM>>>(qkvg, pb, ctxh, ctxl);
    // --- output projection ---
    hmma_gemm<0><<<dim3(8, 32), 256, GEMM_SMEM>>>(ctxh, ctxl, woh, wol, bo, tmp,
                                                  nullptr, nullptr, nullptr,
                                                  M_ROWS, 1024, 1024);
    // --- gate + residual + LN1 ---
    ln1_kernel<<<M_ROWS, 256>>>(x, tmp, qkvg, l1g, l1b, x1, x1h, x1l);
    // --- FFN up with fused SwiGLU epilogue ---
    hmma_gemm<1><<<dim3(64, 32), 256, GEMM_SMEM>>>(x1h, x1l, wfh, wfl, biasf, nullptr,
                                                   h1h, h1l, nullptr,
                                                   M_ROWS, 8192, 1024);
    // --- FFN down + fused residual add (tmp = x1 + ff) ---
    hmma_gemm<2><<<dim3(8, 32), 256, GEMM_SMEM>>>(h1h, h1l, w2h, w2l, bf2, tmp,
                                                  nullptr, nullptr, x1,
                                                  M_ROWS, 1024, 4096);
    // --- LN2 ---
    ln2_kernel<<<M_ROWS, 256>>>(tmp, l2g, l2b, out);
}

// round 6
// speedup vs baseline: 3.8001x; 1.3849x over previous
#include <cuda_runtime.h>
#include <cuda_bf16.h>
#include <cuda_fp16.h>
#include <cstdint>
#include <cstddef>

// Problem constants
#define E_DIM 1024
#define S_LEN 1024
#define B_SZ 4
#define NH 16
#define HD 64
#define FF_DIM 4096
#define M_ROWS (B_SZ * S_LEN)   // 4096

// ---------------- scratch (static device globals; no allocation) ----------------
__device__ float g_qkvg[M_ROWS * 4096];          // [q|k|v|gate] fp32
__device__ float g_tmp[M_ROWS * E_DIM];          // attn_out, later (x1+ff)
__device__ float g_x1[M_ROWS * E_DIM];
__device__ float g_pb[S_LEN * S_LEN];

// fp16 single activations
__device__ __half g_xf[M_ROWS * E_DIM];
__device__ __half g_ctxf[M_ROWS * E_DIM];
__device__ __half g_x1f[M_ROWS * E_DIM];
__device__ __half g_h1f[(size_t)M_ROWS * FF_DIM];

// transposed fp16 weight pairs (K-major: [N,K])
__device__ __half g_wqkvg_h[4096 * 1024];
__device__ __half g_wqkvg_l[4096 * 1024];
__device__ __half g_wo_h[1024 * 1024];
__device__ __half g_wo_l[1024 * 1024];
__device__ __half g_wff_h[8192 * 1024];          // interleaved: row 2n = Wf1_n, 2n+1 = Wfg_n
__device__ __half g_wff_l[8192 * 1024];
__device__ __half g_wf2_h[1024 * 4096];
__device__ __half g_wf2_l[1024 * 4096];

__device__ float g_bias_qkvg[4096];
__device__ float g_bias_ff[8192];                 // interleaved bf1/bfg

#define L2E 1.4426950408889634f

// =================== PTX helpers (baseline sm_80+ features only) ===================
__device__ __forceinline__ uint32_t smem_u32(const void* p) {
    uint32_t a;
    asm("{ .reg .u64 t; cvta.to.shared.u64 t, %1; cvt.u32.u64 %0, t; }" : "=r"(a) : "l"(p));
    return a;
}
__device__ __forceinline__ void cp16(uint32_t dst, const void* src) {
    asm volatile("cp.async.cg.shared.global [%0], [%1], 16;" :: "r"(dst), "l"(src));
}
#define CP_COMMIT() asm volatile("cp.async.commit_group;" ::: "memory")
#define CP_WAIT1()  asm volatile("cp.async.wait_group 1;" ::: "memory")

__device__ __forceinline__ void ldm_x4(uint32_t& r0, uint32_t& r1, uint32_t& r2,
                                       uint32_t& r3, uint32_t addr) {
    asm volatile("ldmatrix.sync.aligned.m8n8.x4.shared.b16 {%0,%1,%2,%3}, [%4];"
                 : "=r"(r0), "=r"(r1), "=r"(r2), "=r"(r3) : "r"(addr));
}
__device__ __forceinline__ void ldm_x4t(uint32_t& r0, uint32_t& r1, uint32_t& r2,
                                        uint32_t& r3, uint32_t addr) {
    asm volatile("ldmatrix.sync.aligned.m8n8.x4.trans.shared.b16 {%0,%1,%2,%3}, [%4];"
                 : "=r"(r0), "=r"(r1), "=r"(r2), "=r"(r3) : "r"(addr));
}
// bf16 MMA (attention)
__device__ __forceinline__ void mma16816(float* c, const uint32_t* a,
                                         uint32_t b0, uint32_t b1) {
    asm volatile(
        "mma.sync.aligned.m16n8k16.row.col.f32.bf16.bf16.f32 "
        "{%0,%1,%2,%3}, {%4,%5,%6,%7}, {%8,%9}, {%0,%1,%2,%3};"
        : "+f"(c[0]), "+f"(c[1]), "+f"(c[2]), "+f"(c[3])
        : "r"(a[0]), "r"(a[1]), "r"(a[2]), "r"(a[3]), "r"(b0), "r"(b1));
}
// fp16 MMA (GEMMs)
__device__ __forceinline__ void mma16816h(float* c, const uint32_t* a,
                                          uint32_t b0, uint32_t b1) {
    asm volatile(
        "mma.sync.aligned.m16n8k16.row.col.f32.f16.f16.f32 "
        "{%0,%1,%2,%3}, {%4,%5,%6,%7}, {%8,%9}, {%0,%1,%2,%3};"
        : "+f"(c[0]), "+f"(c[1]), "+f"(c[2]), "+f"(c[3])
        : "r"(a[0]), "r"(a[1]), "r"(a[2]), "r"(a[3]), "r"(b0), "r"(b1));
}
__device__ __forceinline__ float ex2f(float x) {
    float y;
    asm("ex2.approx.ftz.f32 %0, %1;" : "=f"(y) : "f"(x));
    return y;
}

// fp32x4 -> bf16 hi/lo pairs, store 8B each (attention smem staging)
__device__ __forceinline__ void cvt_store8(float4 v, void* hp, void* lp) {
    __nv_bfloat162 h0 = __floats2bfloat162_rn(v.x, v.y);
    __nv_bfloat162 h1 = __floats2bfloat162_rn(v.z, v.w);
    __nv_bfloat162 l0 = __floats2bfloat162_rn(v.x - __bfloat162float(h0.x),
                                              v.y - __bfloat162float(h0.y));
    __nv_bfloat162 l1 = __floats2bfloat162_rn(v.z - __bfloat162float(h1.x),
                                              v.w - __bfloat162float(h1.y));
    uint2 H, L;
    H.x = *(uint32_t*)&h0; H.y = *(uint32_t*)&h1;
    L.x = *(uint32_t*)&l0; L.y = *(uint32_t*)&l1;
    *(uint2*)hp = H;
    *(uint2*)lp = L;
}

// =================== HMMA GEMM (fp16, 2 MMAs per k16) ===================
// A: [M,K] fp16 single. W: [N,K] fp16 hi/lo pair. 
// MODE 0: C[M,N] fp32 = A@W^T + bias
// MODE 1: SwiGLU: Of[M,N/2] fp16 = (c_even+b_even) * sigmoid(c_odd+b_odd)
// MODE 2: C = A@W^T + bias + R
// smem stage: A@0 (10240B), Wh@10240, Wl@20480; 3 stages.
#define STAGE_BYTES 30720
#define GEMM_SMEM (3 * STAGE_BYTES)

template <int MODE>
__global__ __launch_bounds__(256, 2)
void hmma_gemm(const __half* __restrict__ Af,
               const __half* __restrict__ Wh, const __half* __restrict__ Wl,
               const float* __restrict__ bias, float* __restrict__ C,
               __half* __restrict__ Of, const float* __restrict__ R,
               int M, int N, int K) {
    extern __shared__ char smem[];
    const uint32_t sb = smem_u32(smem);
    const int tid = threadIdx.x;
    const int wid = tid >> 5, lane = tid & 31;
    const int brow = blockIdx.y * 128, bcol = blockIdx.x * 128;
    const int wm = (wid >> 2) * 64, wn = (wid & 3) * 32;
    const int nst = K >> 5;

    // 512 16B-chunks per 128x32 fp16 tile; thread handles chunks tid, tid+256
    const int r0c = tid >> 2, r1c = (tid + 256) >> 2;
    const int c0c = tid & 3,  c1c = (tid + 256) & 3;
    const uint32_t so0 = (uint32_t)(r0c * 80 + c0c * 16);
    const uint32_t so1 = (uint32_t)(r1c * 80 + c1c * 16);

#define LOAD_STAGE(s, buf) do {                                               \
        const uint32_t stb_ = sb + (buf) * STAGE_BYTES;                       \
        const size_t ga0 = (size_t)(brow + r0c) * K + (s) * 32 + c0c * 8;     \
        const size_t ga1 = (size_t)(brow + r1c) * K + (s) * 32 + c1c * 8;     \
        const size_t gb0 = (size_t)(bcol + r0c) * K + (s) * 32 + c0c * 8;     \
        const size_t gb1 = (size_t)(bcol + r1c) * K + (s) * 32 + c1c * 8;     \
        cp16(stb_ + so0,         Af + ga0);                                   \
        cp16(stb_ + so1,         Af + ga1);                                   \
        cp16(stb_ + 10240 + so0, Wh + gb0);                                   \
        cp16(stb_ + 10240 + so1, Wh + gb1);                                   \
        cp16(stb_ + 20480 + so0, Wl + gb0);                                   \
        cp16(stb_ + 20480 + so1, Wl + gb1);                                   \
    } while (0)

    float acc[4][4][4];
#pragma unroll
    for (int i = 0; i < 4; i++)
#pragma unroll
        for (int j = 0; j < 4; j++)
#pragma unroll
            for (int r = 0; r < 4; r++) acc[i][j][r] = 0.f;

    LOAD_STAGE(0, 0); CP_COMMIT();
    LOAD_STAGE(1, 1); CP_COMMIT();

    const uint32_t a_lrow = (uint32_t)(lane & 15);
    const uint32_t a_koff = (uint32_t)((lane & 16) >> 1);
    const uint32_t b_lrow = (uint32_t)((lane & 7) + ((lane & 16) >> 1));
    const uint32_t b_koff = (uint32_t)(lane & 8);

    for (int s = 0; s < nst; s++) {
        CP_WAIT1();
        __syncthreads();
        if (s + 2 < nst) LOAD_STAGE(s + 2, (s + 2) % 3);
        CP_COMMIT();
        const uint32_t stb = sb + (uint32_t)(s % 3) * STAGE_BYTES;

#pragma unroll
        for (int kk = 0; kk < 32; kk += 16) {
            uint32_t bh[2][4], bl[2][4];
            const uint32_t bkcol = (uint32_t)kk + b_koff;
#pragma unroll
            for (int ni = 0; ni < 2; ni++) {
                const uint32_t addr =
                    stb + 10240 + (uint32_t)(wn + ni * 16 + b_lrow) * 80 + bkcol * 2;
                ldm_x4(bh[ni][0], bh[ni][1], bh[ni][2], bh[ni][3], addr);
                ldm_x4(bl[ni][0], bl[ni][1], bl[ni][2], bl[ni][3], addr + 10240);
            }
            const uint32_t akcol = (uint32_t)kk + a_koff;
#pragma unroll
            for (int mi = 0; mi < 4; mi++) {
                uint32_t a[4];
                const uint32_t addr = stb + (uint32_t)(wm + mi * 16 + a_lrow) * 80 + akcol * 2;
                ldm_x4(a[0], a[1], a[2], a[3], addr);
#pragma unroll
                for (int nj = 0; nj < 4; nj++) {
                    const int g = nj >> 1, p = (nj & 1) * 2;
                    mma16816h(acc[mi][nj], a, bh[g][p], bh[g][p + 1]);
                    mma16816h(acc[mi][nj], a, bl[g][p], bl[g][p + 1]);
                }
            }
        }
    }

    const int qr = lane >> 2, qc = (lane & 3) * 2;
#pragma unroll
    for (int mi = 0; mi < 4; mi++) {
        const size_t gr = (size_t)(brow + wm + mi * 16 + qr);
#pragma unroll
        for (int nj = 0; nj < 4; nj++) {
            const int gc = bcol + wn + nj * 8 + qc;
            const float2 b2 = *(const float2*)(bias + gc);
            if (MODE == 0 || MODE == 2) {
                float2 o0, o1;
                o0.x = acc[mi][nj][0] + b2.x;
                o0.y = acc[mi][nj][1] + b2.y;
                o1.x = acc[mi][nj][2] + b2.x;
                o1.y = acc[mi][nj][3] + b2.y;
                if (MODE == 2) {
                    const float2 r0 = *(const float2*)(R + gr * N + gc);
                    const float2 r1 = *(const float2*)(R + (gr + 8) * N + gc);
                    o0.x += r0.x; o0.y += r0.y;
                    o1.x += r1.x; o1.y += r1.y;
                }
                *(float2*)(C + gr * N + gc)       = o0;
                *(float2*)(C + (gr + 8) * N + gc) = o1;
            } else {
                const float h1v0 = acc[mi][nj][0] + b2.x;
                const float hg0  = acc[mi][nj][1] + b2.y;
                const float h1v1 = acc[mi][nj][2] + b2.x;
                const float hg1  = acc[mi][nj][3] + b2.y;
                const float o0 = h1v0 / (1.f + ex2f(-hg0 * L2E));
                const float o1 = h1v1 / (1.f + ex2f(-hg1 * L2E));
                const size_t co = (size_t)(gc >> 1);
                Of[gr * (N >> 1) + co]       = __float2half(o0);
                Of[(gr + 8) * (N >> 1) + co] = __float2half(o1);
            }
        }
    }
#undef LOAD_STAGE
}

// =================== HMMA flash attention (bf16 3-term internally) ===================
#define ATT_QH 0
#define ATT_QL 18432
#define ATT_KH 36864
#define ATT_KL 46080
#define ATT_VH 55296
#define ATT_VL 64512
#define ATT_SMEM 73728

__global__ __launch_bounds__(256, 2)
void attention_mma_clean(const float* __restrict__ QKVG, const float* __restrict__ PB,
                         __half* __restrict__ CTXF) {
    extern __shared__ char smem[];
    const uint32_t sbase = smem_u32(smem);
    const int tid = threadIdx.x;
    const int wid = tid >> 5, lane = tid & 31;
    const int b = blockIdx.y >> 4, h = blockIdx.y & 15;
    const int q0 = blockIdx.x * 128;
    const int wr = wid * 16;

#pragma unroll
    for (int it = 0; it < 8; it++) {
        const int c = tid + it * 256;
        const int r = c >> 4, col = (c & 15) * 4;
        const float4 v =
            *(const float4*)&QKVG[(((size_t)b << 10) + q0 + r) * 4096 + h * 64 + col];
        cvt_store8(v, smem + ATT_QH + r * 144 + col * 2,
                      smem + ATT_QL + r * 144 + col * 2);
    }

    const uint32_t a_lrow = (uint32_t)(lane & 15);
    const uint32_t a_koff2 = (uint32_t)((lane & 16) >> 1) * 2;
    const uint32_t b_lrow = (uint32_t)((lane & 7) + ((lane & 16) >> 1));
    const uint32_t b_koff2 = (uint32_t)(lane & 8) * 2;
    const uint32_t v_row = (uint32_t)((lane & 7) + (lane & 8));
    const uint32_t v_col2 = (uint32_t)((lane & 16) >> 1) * 2;

    const int qr = lane >> 2, qc = (lane & 3) * 2;
    float m0 = -1e30f, m1 = -1e30f, l0 = 0.f, l1 = 0.f;
    float oacc[8][4];
#pragma unroll
    for (int nt = 0; nt < 8; nt++)
#pragma unroll
        for (int e = 0; e < 4; e++) oacc[nt][e] = 0.f;

    for (int kt = 0; kt < 16; kt++) {
        __syncthreads();
#pragma unroll
        for (int it = 0; it < 4; it++) {
            const int c = tid + it * 256;
            const int r = c >> 4, col = (c & 15) * 4;
            const size_t gb = (((size_t)b << 10) + kt * 64 + r) * 4096 + h * 64 + col;
            const float4 kv = *(const float4*)&QKVG[gb + 1024];
            const float4 vv = *(const float4*)&QKVG[gb + 2048];
            cvt_store8(kv, smem + ATT_KH + r * 144 + col * 2,
                           smem + ATT_KL + r * 144 + col * 2);
            cvt_store8(vv, smem + ATT_VH + r * 144 + col * 2,
                           smem + ATT_VL + r * 144 + col * 2);
        }
        __syncthreads();

        float sa[8][4];
#pragma unroll
        for (int nt = 0; nt < 8; nt++)
#pragma unroll
            for (int e = 0; e < 4; e++) sa[nt][e] = 0.f;

#pragma unroll
        for (int k16 = 0; k16 < 4; k16++) {
            uint32_t qh[4], ql[4];
            const uint32_t qaddr =
                sbase + ATT_QH + (uint32_t)(wr + a_lrow) * 144 + k16 * 32 + a_koff2;
            ldm_x4(qh[0], qh[1], qh[2], qh[3], qaddr);
            ldm_x4(ql[0], ql[1], ql[2], ql[3], qaddr + (ATT_QL - ATT_QH));
#pragma unroll
            for (int ntp = 0; ntp < 4; ntp++) {
                uint32_t kh[4], kl[4];
                const uint32_t kaddr =
                    sbase + ATT_KH + (uint32_t)(ntp * 16 + b_lrow) * 144 + k16 * 32 + b_koff2;
                ldm_x4(kh[0], kh[1], kh[2], kh[3], kaddr);
                ldm_x4(kl[0], kl[1], kl[2], kl[3], kaddr + (ATT_KL - ATT_KH));
                mma16816(sa[2 * ntp],     qh, kh[0], kh[1]);
                mma16816(sa[2 * ntp],     qh, kl[0], kl[1]);
                mma16816(sa[2 * ntp],     ql, kh[0], kh[1]);
                mma16816(sa[2 * ntp + 1], qh, kh[2], kh[3]);
                mma16816(sa[2 * ntp + 1], qh, kl[2], kl[3]);
                mma16816(sa[2 * ntp + 1], ql, kh[2], kh[3]);
            }
        }

        const size_t r0g = (size_t)(q0 + wr + qr);
        const size_t pb0 = r0g * 1024 + kt * 64 + qc;
        const size_t pb1 = (r0g + 8) * 1024 + kt * 64 + qc;
#pragma unroll
        for (int nt = 0; nt < 8; nt++) {
            const float2 p0 = *(const float2*)&PB[pb0 + nt * 8];
            const float2 p1 = *(const float2*)&PB[pb1 + nt * 8];
            sa[nt][0] = sa[nt][0] * 0.125f + p0.x;
            sa[nt][1] = sa[nt][1] * 0.125f + p0.y;
            sa[nt][2] = sa[nt][2] * 0.125f + p1.x;
            sa[nt][3] = sa[nt][3] * 0.125f + p1.y;
        }

        float tm0 = -1e30f, tm1 = -1e30f;
#pragma unroll
        for (int nt = 0; nt < 8; nt++) {
            tm0 = fmaxf(tm0, fmaxf(sa[nt][0], sa[nt][1]));
            tm1 = fmaxf(tm1, fmaxf(sa[nt][2], sa[nt][3]));
        }
        tm0 = fmaxf(tm0, __shfl_xor_sync(0xffffffffu, tm0, 1));
        tm0 = fmaxf(tm0, __shfl_xor_sync(0xffffffffu, tm0, 2));
        tm1 = fmaxf(tm1, __shfl_xor_sync(0xffffffffu, tm1, 1));
        tm1 = fmaxf(tm1, __shfl_xor_sync(0xffffffffu, tm1, 2));
        const float mn0 = fmaxf(m0, tm0), mn1 = fmaxf(m1, tm1);
        const float cr0 = ex2f((m0 - mn0) * L2E), cr1 = ex2f((m1 - mn1) * L2E);
        m0 = mn0; m1 = mn1;

        float rs0 = 0.f, rs1 = 0.f;
#pragma unroll
        for (int nt = 0; nt < 8; nt++) {
            sa[nt][0] = ex2f((sa[nt][0] - mn0) * L2E);
            sa[nt][1] = ex2f((sa[nt][1] - mn0) * L2E);
            sa[nt][2] = ex2f((sa[nt][2] - mn1) * L2E);
            sa[nt][3] = ex2f((sa[nt][3] - mn1) * L2E);
            rs0 += sa[nt][0] + sa[nt][1];
            rs1 += sa[nt][2] + sa[nt][3];
        }
        rs0 += __shfl_xor_sync(0xffffffffu, rs0, 1);
        rs0 += __shfl_xor_sync(0xffffffffu, rs0, 2);
        rs1 += __shfl_xor_sync(0xffffffffu, rs1, 1);
        rs1 += __shfl_xor_sync(0xffffffffu, rs1, 2);
        l0 = l0 * cr0 + rs0;
        l1 = l1 * cr1 + rs1;
#pragma unroll
        for (int nt = 0; nt < 8; nt++) {
            oacc[nt][0] *= cr0; oacc[nt][1] *= cr0;
            oacc[nt][2] *= cr1; oacc[nt][3] *= cr1;
        }

#pragma unroll
        for (int j = 0; j < 4; j++) {
            uint32_t pha[4], pla[4];
            {
                const float* s0 = sa[2 * j];
                const float* s1 = sa[2 * j + 1];
                __nv_bfloat162 h;
                float r0, r1;
                h = __floats2bfloat162_rn(s0[0], s0[1]);
                pha[0] = *(uint32_t*)&h;
                r0 = s0[0] - __bfloat162float(h.x); r1 = s0[1] - __bfloat162float(h.y);
                h = __floats2bfloat162_rn(r0, r1); pla[0] = *(uint32_t*)&h;
                h = __floats2bfloat162_rn(s0[2], s0[3]);
                pha[1] = *(uint32_t*)&h;
                r0 = s0[2] - __bfloat162float(h.x); r1 = s0[3] - __bfloat162float(h.y);
                h = __floats2bfloat162_rn(r0, r1); pla[1] = *(uint32_t*)&h;
                h = __floats2bfloat162_rn(s1[0], s1[1]);
                pha[2] = *(uint32_t*)&h;
                r0 = s1[0] - __bfloat162float(h.x); r1 = s1[1] - __bfloat162float(h.y);
                h = __floats2bfloat162_rn(r0, r1); pla[2] = *(uint32_t*)&h;
                h = __floats2bfloat162_rn(s1[2], s1[3]);
                pha[3] = *(uint32_t*)&h;
                r0 = s1[2] - __bfloat162float(h.x); r1 = s1[3] - __bfloat162float(h.y);
                h = __floats2bfloat162_rn(r0, r1); pla[3] = *(uint32_t*)&h;
            }
#pragma unroll
            for (int ntp = 0; ntp < 4; ntp++) {
                uint32_t vh[4], vl[4];
                const uint32_t vaddr = sbase + ATT_VH +
                    (uint32_t)(j * 16 + v_row) * 144 + (uint32_t)(ntp * 16) * 2 + v_col2;
                ldm_x4t(vh[0], vh[1], vh[2], vh[3], vaddr);
                ldm_x4t(vl[0], vl[1], vl[2], vl[3], vaddr + (ATT_VL - ATT_VH));
                mma16816(oacc[2 * ntp],     pha, vh[0], vh[1]);
                mma16816(oacc[2 * ntp],     pha, vl[0], vl[1]);
                mma16816(oacc[2 * ntp],     pla, vh[0], vh[1]);
                mma16816(oacc[2 * ntp + 1], pha, vh[2], vh[3]);
                mma16816(oacc[2 * ntp + 1], pha, vl[2], vl[3]);
                mma16816(oacc[2 * ntp + 1], pla, vh[2], vh[3]);
            }
        }
    }

    // ---- write ctx fp16 single ----
    const float inv0 = 1.f / l0, inv1 = 1.f / l1;
    const size_t cr0 = (size_t)((b << 10) + q0 + wr + qr);
    const size_t colb = (size_t)(h * 64 + qc);
#pragma unroll
    for (int nt = 0; nt < 8; nt++) {
        const __half2 h2a = __floats2half2_rn(oacc[nt][0] * inv0, oacc[nt][1] * inv0);
        const __half2 h2b = __floats2half2_rn(oacc[nt][2] * inv1, oacc[nt][3] * inv1);
        *(__half2*)(CTXF + cr0 * 1024 + colb + nt * 8)       = h2a;
        *(__half2*)(CTXF + (cr0 + 8) * 1024 + colb + nt * 8) = h2b;
    }
}

// =================== weight transpose + fp16 split (with row interleave) ===================
__global__ __launch_bounds__(256)
void transpose_conv(const float* __restrict__ W, __half* __restrict__ Th,
                    __half* __restrict__ Tl, int K, int N, int rs, int ro) {
    __shared__ float t[32][33];
    const int k0 = blockIdx.y * 32, n0 = blockIdx.x * 32;
    const int tx = threadIdx.x & 31, ty = threadIdx.x >> 5;
#pragma unroll
    for (int l = 0; l < 4; l++)
        t[ty + 8 * l][tx] = W[(size_t)(k0 + ty + 8 * l) * N + n0 + tx];
    __syncthreads();
#pragma unroll
    for (int l = 0; l < 4; l++) {
        const float v = t[tx][ty + 8 * l];
        const __half hv = __float2half(v);
        const size_t o = ((size_t)(n0 + ty + 8 * l) * rs + ro) * K + k0 + tx;
        Th[o] = hv;
        Tl[o] = __float2half(v - __half2float(hv));
    }
}

__global__ __launch_bounds__(256)
void conv_half(const float* __restrict__ X, __half* __restrict__ Xf) {
    const size_t i = ((size_t)blockIdx.x * 256 + threadIdx.x) * 4;
    const float4 v = *(const float4*)(X + i);
    uint2 o;
    const __half2 a = __floats2half2_rn(v.x, v.y);
    const __half2 b = __floats2half2_rn(v.z, v.w);
    o.x = *(const uint32_t*)&a;
    o.y = *(const uint32_t*)&b;
    *(uint2*)(Xf + i) = o;
}

__global__ void pack_bias(const float* bq, const float* bk, const float* bv,
                          const float* bg, const float* bf1, const float* bfg,
                          float* outq, float* outf) {
    const int i = blockIdx.x * 256 + threadIdx.x;   // 0..12287
    if (i < 1024) outq[i] = bq[i];
    else if (i < 2048) outq[i] = bk[i - 1024];
    else if (i < 3072) outq[i] = bv[i - 2048];
    else if (i < 4096) outq[i] = bg[i - 3072];
    else if (i < 8192) outf[2 * (i - 4096)] = bf1[i - 4096];
    else outf[2 * (i - 8192) + 1] = bfg[i - 8192];
}

__global__ __launch_bounds__(256)
void posbias_kernel(const float* __restrict__ pe, float* __restrict__ pb) {
    const size_t i = (size_t)blockIdx.x * 256 + threadIdx.x;
    const float4 a = *(const float4*)&pe[i * 8];
    const float4 b = *(const float4*)&pe[i * 8 + 4];
    pb[i] = (a.x + a.y + a.z + a.w + b.x + b.y + b.z + b.w) * 0.125f;
}

// ---------------- LN1: x1 = LN(x + sigmoid(gate)*attn); emit fp32 + fp16 ----------------
__global__ __launch_bounds__(256)
void ln1_kernel(const float* __restrict__ x, const float* __restrict__ attn,
                const float* __restrict__ qkvg, const float* __restrict__ gw,
                const float* __restrict__ gb, float* __restrict__ x1,
                __half* __restrict__ x1f) {
    const size_t base = (size_t)blockIdx.x * E_DIM;
    const size_t gbase = (size_t)blockIdx.x * 4096 + 3072;
    const int t = threadIdx.x;
    float vals[4];
    float s = 0.f, s2 = 0.f;
#pragma unroll
    for (int i = 0; i < 4; i++) {
        const int c = t + i * 256;
        const float gp = qkvg[gbase + c];
        const float sg = 1.f / (1.f + __expf(-gp));
        const float val = x[base + c] + attn[base + c] * sg;
        vals[i] = val; s += val; s2 += val * val;
    }
    __shared__ float rsm[8], rs2[8];
#pragma unroll
    for (int o = 16; o; o >>= 1) {
        s  += __shfl_xor_sync(0xffffffffu, s,  o);
        s2 += __shfl_xor_sync(0xffffffffu, s2, o);
    }
    if ((t & 31) == 0) { rsm[t >> 5] = s; rs2[t >> 5] = s2; }
    __syncthreads();
    float S = 0.f, S2 = 0.f;
#pragma unroll
    for (int i = 0; i < 8; i++) { S += rsm[i]; S2 += rs2[i]; }
    const float mean = S * (1.f / E_DIM);
    const float var = S2 * (1.f / E_DIM) - mean * mean;
    const float inv = rsqrtf(var + 1e-6f);
#pragma unroll
    for (int i = 0; i < 4; i++) {
        const int c = t + i * 256;
        const float v = (vals[i] - mean) * inv * gw[c] + gb[c];
        x1[base + c] = v;
        x1f[base + c] = __float2half(v);
    }
}

// ---------------- LN2 (input already contains x1+ff residual) ----------------
__global__ __launch_bounds__(256)
void ln2_kernel(const float* __restrict__ ff,
                const float* __restrict__ gw, const float* __restrict__ gb,
                float* __restrict__ out) {
    const size_t base = (size_t)blockIdx.x * E_DIM;
    const int t = threadIdx.x;
    float vals[4];
    float s = 0.f, s2 = 0.f;
#pragma unroll
    for (int i = 0; i < 4; i++) {
        const int c = t + i * 256;
        const float val = ff[base + c];
        vals[i] = val; s += val; s2 += val * val;
    }
    __shared__ float rsm[8], rs2[8];
#pragma unroll
    for (int o = 16; o; o >>= 1) {
        s  += __shfl_xor_sync(0xffffffffu, s,  o);
        s2 += __shfl_xor_sync(0xffffffffu, s2, o);
    }
    if ((t & 31) == 0) { rsm[t >> 5] = s; rs2[t >> 5] = s2; }
    __syncthreads();
    float S = 0.f, S2 = 0.f;
#pragma unroll
    for (int i = 0; i < 8; i++) { S += rsm[i]; S2 += rs2[i]; }
    const float mean = S * (1.f / E_DIM);
    const float var = S2 * (1.f / E_DIM) - mean * mean;
    const float inv = rsqrtf(var + 1e-6f);
#pragma unroll
    for (int i = 0; i < 4; i++) {
        const int c = t + i * 256;
        out[base + c] = (vals[i] - mean) * inv * gw[c] + gb[c];
    }
}

// =================== launch ===================
extern "C" void kernel_launch(void* const* d_in, const int* in_sizes, int n_in,
                              void* d_out, int out_size) {
    const float* x   = (const float*)d_in[0];
    const float* pe  = (const float*)d_in[1];
    const float* Wq  = (const float*)d_in[2];
    const float* bq  = (const float*)d_in[3];
    const float* Wk  = (const float*)d_in[4];
    const float* bk  = (const float*)d_in[5];
    const float* Wv  = (const float*)d_in[6];
    const float* bv  = (const float*)d_in[7];
    const float* Wo  = (const float*)d_in[8];
    const float* bo  = (const float*)d_in[9];
    const float* Wg  = (const float*)d_in[10];
    const float* bg  = (const float*)d_in[11];
    const float* Wf1 = (const float*)d_in[12];
    const float* bf1 = (const float*)d_in[13];
    const float* Wfg = (const float*)d_in[14];
    const float* bfg = (const float*)d_in[15];
    const float* Wf2 = (const float*)d_in[16];
    const float* bf2 = (const float*)d_in[17];
    const float* l1g = (const float*)d_in[18];
    const float* l1b = (const float*)d_in[19];
    const float* l2g = (const float*)d_in[20];
    const float* l2b = (const float*)d_in[21];
    float* out = (float*)d_out;

    float *qkvg, *tmp, *x1, *pb, *biasq, *biasf;
    __half *xf, *ctxf, *x1f, *h1f;
    __half *wqh, *wql, *woh, *wol, *wfh, *wfl, *w2h, *w2l;
    cudaGetSymbolAddress((void**)&qkvg, g_qkvg);
    cudaGetSymbolAddress((void**)&tmp, g_tmp);
    cudaGetSymbolAddress((void**)&x1, g_x1);
    cudaGetSymbolAddress((void**)&pb, g_pb);
    cudaGetSymbolAddress((void**)&biasq, g_bias_qkvg);
    cudaGetSymbolAddress((void**)&biasf, g_bias_ff);
    cudaGetSymbolAddress((void**)&xf, g_xf);
    cudaGetSymbolAddress((void**)&ctxf, g_ctxf);
    cudaGetSymbolAddress((void**)&x1f, g_x1f);
    cudaGetSymbolAddress((void**)&h1f, g_h1f);
    cudaGetSymbolAddress((void**)&wqh, g_wqkvg_h);
    cudaGetSymbolAddress((void**)&wql, g_wqkvg_l);
    cudaGetSymbolAddress((void**)&woh, g_wo_h);
    cudaGetSymbolAddress((void**)&wol, g_wo_l);
    cudaGetSymbolAddress((void**)&wfh, g_wff_h);
    cudaGetSymbolAddress((void**)&wfl, g_wff_l);
    cudaGetSymbolAddress((void**)&w2h, g_wf2_h);
    cudaGetSymbolAddress((void**)&w2l, g_wf2_l);

    cudaFuncSetAttribute(attention_mma_clean,
                         cudaFuncAttributeMaxDynamicSharedMemorySize, ATT_SMEM);
    cudaFuncSetAttribute(hmma_gemm<0>,
                         cudaFuncAttributeMaxDynamicSharedMemorySize, GEMM_SMEM);
    cudaFuncSetAttribute(hmma_gemm<1>,
                         cudaFuncAttributeMaxDynamicSharedMemorySize, GEMM_SMEM);
    cudaFuncSetAttribute(hmma_gemm<2>,
                         cudaFuncAttributeMaxDynamicSharedMemorySize, GEMM_SMEM);

    // --- prep ---
    posbias_kernel<<<4096, 256>>>(pe, pb);
    conv_half<<<M_ROWS * E_DIM / 1024, 256>>>(x, xf);

    transpose_conv<<<dim3(32, 32), 256>>>(Wq,  wqh,             wql,             1024, 1024, 1, 0);
    transpose_conv<<<dim3(32, 32), 256>>>(Wk,  wqh + 1024*1024, wql + 1024*1024, 1024, 1024, 1, 0);
    transpose_conv<<<dim3(32, 32), 256>>>(Wv,  wqh + 2048*1024, wql + 2048*1024, 1024, 1024, 1, 0);
    transpose_conv<<<dim3(32, 32), 256>>>(Wg,  wqh + 3072*1024, wql + 3072*1024, 1024, 1024, 1, 0);
    transpose_conv<<<dim3(32, 32), 256>>>(Wo,  woh, wol, 1024, 1024, 1, 0);
    transpose_conv<<<dim3(128, 32), 256>>>(Wf1, wfh, wfl, 1024, 4096, 2, 0);
    transpose_conv<<<dim3(128, 32), 256>>>(Wfg, wfh, wfl, 1024, 4096, 2, 1);
    transpose_conv<<<dim3(32, 128), 256>>>(Wf2, w2h, w2l, 4096, 1024, 1, 0);
    pack_bias<<<48, 256>>>(bq, bk, bv, bg, bf1, bfg, biasq, biasf);

    // --- QKV + gate projection ---
    hmma_gemm<0><<<dim3(32, 32), 256, GEMM_SMEM>>>(xf, wqh, wql, biasq, qkvg,
                                                   nullptr, nullptr,
                                                   M_ROWS, 4096, 1024);
    // --- HMMA flash attention ---
    attention_mma_clean<<<dim3(8, 64), 256, ATT_SMEM>>>(qkvg, pb, ctxf);
    // --- output projection ---
    hmma_gemm<0><<<dim3(8, 32), 256, GEMM_SMEM>>>(ctxf, woh, wol, bo, tmp,
                                                  nullptr, nullptr,
                                                  M_ROWS, 1024, 1024);
    // --- gate + residual + LN1 ---
    ln1_kernel<<<M_ROWS, 256>>>(x, tmp, qkvg, l1g, l1b, x1, x1f);
    // --- FFN up with fused SwiGLU epilogue ---
    hmma_gemm<1><<<dim3(64, 32), 256, GEMM_SMEM>>>(x1f, wfh, wfl, biasf, nullptr,
                                                   h1f, nullptr,
                                                   M_ROWS, 8192, 1024);
    // --- FFN down + fused residual add (tmp = x1 + ff) ---
    hmma_gemm<2><<<dim3(8, 32), 256, GEMM_SMEM>>>(h1f, w2h, w2l, bf2, tmp,
                                                  nullptr, x1,
                                                  M_ROWS, 1024, 4096);
    // --- LN2 ---
    ln2_kernel<<<M_ROWS, 256>>>(tmp, l2g, l2b, out);
}

// round 7
// speedup vs baseline: 5.7611x; 1.5160x over previous
#include <cuda_runtime.h>
#include <cuda_bf16.h>
#include <cuda_fp16.h>
#include <cstdint>
#include <cstddef>

// Problem constants
#define E_DIM 1024
#define S_LEN 1024
#define B_SZ 4
#define NH 16
#define HD 64
#define FF_DIM 4096
#define M_ROWS (B_SZ * S_LEN)   // 4096

// ---------------- scratch (static device globals; no allocation) ----------------
__device__ float g_qkvg[M_ROWS * 4096];          // [q|k|v|gate] fp32
__device__ float g_tmp[M_ROWS * E_DIM];          // attn_out, later (x1+ff)
__device__ float g_x1[M_ROWS * E_DIM];
__device__ float g_pb[S_LEN * S_LEN];

// fp16 single activations
__device__ __half g_xf[M_ROWS * E_DIM];
__device__ __half g_ctxf[M_ROWS * E_DIM];
__device__ __half g_x1f[M_ROWS * E_DIM];
__device__ __half g_h1f[(size_t)M_ROWS * FF_DIM];

// transposed fp16 weights (K-major: [N,K]), single precision level
__device__ __half g_wqkvg[4096 * 1024];
__device__ __half g_wo[1024 * 1024];
__device__ __half g_wff[8192 * 1024];            // interleaved: row 2n = Wf1_n, 2n+1 = Wfg_n
__device__ __half g_wf2[1024 * 4096];

__device__ float g_bias_qkvg[4096];
__device__ float g_bias_ff[8192];                 // interleaved bf1/bfg

#define L2E 1.4426950408889634f

// =================== PTX helpers (baseline sm_80+ features only) ===================
__device__ __forceinline__ uint32_t smem_u32(const void* p) {
    uint32_t a;
    asm("{ .reg .u64 t; cvta.to.shared.u64 t, %1; cvt.u32.u64 %0, t; }" : "=r"(a) : "l"(p));
    return a;
}
__device__ __forceinline__ void cp16(uint32_t dst, const void* src) {
    asm volatile("cp.async.cg.shared.global [%0], [%1], 16;" :: "r"(dst), "l"(src));
}
#define CP_COMMIT() asm volatile("cp.async.commit_group;" ::: "memory")
#define CP_WAIT1()  asm volatile("cp.async.wait_group 1;" ::: "memory")

__device__ __forceinline__ void ldm_x4(uint32_t& r0, uint32_t& r1, uint32_t& r2,
                                       uint32_t& r3, uint32_t addr) {
    asm volatile("ldmatrix.sync.aligned.m8n8.x4.shared.b16 {%0,%1,%2,%3}, [%4];"
                 : "=r"(r0), "=r"(r1), "=r"(r2), "=r"(r3) : "r"(addr));
}
__device__ __forceinline__ void ldm_x4t(uint32_t& r0, uint32_t& r1, uint32_t& r2,
                                        uint32_t& r3, uint32_t addr) {
    asm volatile("ldmatrix.sync.aligned.m8n8.x4.trans.shared.b16 {%0,%1,%2,%3}, [%4];"
                 : "=r"(r0), "=r"(r1), "=r"(r2), "=r"(r3) : "r"(addr));
}
// bf16 MMA (attention)
__device__ __forceinline__ void mma16816(float* c, const uint32_t* a,
                                         uint32_t b0, uint32_t b1) {
    asm volatile(
        "mma.sync.aligned.m16n8k16.row.col.f32.bf16.bf16.f32 "
        "{%0,%1,%2,%3}, {%4,%5,%6,%7}, {%8,%9}, {%0,%1,%2,%3};"
        : "+f"(c[0]), "+f"(c[1]), "+f"(c[2]), "+f"(c[3])
        : "r"(a[0]), "r"(a[1]), "r"(a[2]), "r"(a[3]), "r"(b0), "r"(b1));
}
// fp16 MMA (GEMMs)
__device__ __forceinline__ void mma16816h(float* c, const uint32_t* a,
                                          uint32_t b0, uint32_t b1) {
    asm volatile(
        "mma.sync.aligned.m16n8k16.row.col.f32.f16.f16.f32 "
        "{%0,%1,%2,%3}, {%4,%5,%6,%7}, {%8,%9}, {%0,%1,%2,%3};"
        : "+f"(c[0]), "+f"(c[1]), "+f"(c[2]), "+f"(c[3])
        : "r"(a[0]), "r"(a[1]), "r"(a[2]), "r"(a[3]), "r"(b0), "r"(b1));
}
__device__ __forceinline__ float ex2f(float x) {
    float y;
    asm("ex2.approx.ftz.f32 %0, %1;" : "=f"(y) : "f"(x));
    return y;
}

// fp32x4 -> bf16 hi/lo pairs, store 8B each (attention smem staging)
__device__ __forceinline__ void cvt_store8(float4 v, void* hp, void* lp) {
    __nv_bfloat162 h0 = __floats2bfloat162_rn(v.x, v.y);
    __nv_bfloat162 h1 = __floats2bfloat162_rn(v.z, v.w);
    __nv_bfloat162 l0 = __floats2bfloat162_rn(v.x - __bfloat162float(h0.x),
                                              v.y - __bfloat162float(h0.y));
    __nv_bfloat162 l1 = __floats2bfloat162_rn(v.z - __bfloat162float(h1.x),
                                              v.w - __bfloat162float(h1.y));
    uint2 H, L;
    H.x = *(uint32_t*)&h0; H.y = *(uint32_t*)&h1;
    L.x = *(uint32_t*)&l0; L.y = *(uint32_t*)&l1;
    *(uint2*)hp = H;
    *(uint2*)lp = L;
}

// =================== HMMA GEMM (fp16 single x single, 1 MMA per k16) ===================
// A: [M,K] fp16. W: [N,K] fp16. 
// MODE 0: C[M,N] fp32 = A@W^T + bias
// MODE 1: SwiGLU: Of[M,N/2] fp16 = (c_even+b_even) * sigmoid(c_odd+b_odd)
// MODE 2: C = A@W^T + bias + R
// smem stage: A@0 (10240B), W@10240; 3 stages.
#define STAGE_BYTES 20480
#define GEMM_SMEM (3 * STAGE_BYTES)

template <int MODE>
__global__ __launch_bounds__(256, 2)
void hmma_gemm(const __half* __restrict__ Af, const __half* __restrict__ W,
               const float* __restrict__ bias, float* __restrict__ C,
               __half* __restrict__ Of, const float* __restrict__ R,
               int M, int N, int K) {
    extern __shared__ char smem[];
    const uint32_t sb = smem_u32(smem);
    const int tid = threadIdx.x;
    const int wid = tid >> 5, lane = tid & 31;
    const int brow = blockIdx.y * 128, bcol = blockIdx.x * 128;
    const int wm = (wid >> 2) * 64, wn = (wid & 3) * 32;
    const int nst = K >> 5;

    // 512 16B-chunks per 128x32 fp16 tile; thread handles chunks tid, tid+256
    const int r0c = tid >> 2, r1c = (tid + 256) >> 2;
    const int c0c = tid & 3,  c1c = (tid + 256) & 3;
    const uint32_t so0 = (uint32_t)(r0c * 80 + c0c * 16);
    const uint32_t so1 = (uint32_t)(r1c * 80 + c1c * 16);

#define LOAD_STAGE(s, buf) do {                                               \
        const uint32_t stb_ = sb + (buf) * STAGE_BYTES;                       \
        const size_t ga0 = (size_t)(brow + r0c) * K + (s) * 32 + c0c * 8;     \
        const size_t ga1 = (size_t)(brow + r1c) * K + (s) * 32 + c1c * 8;     \
        const size_t gb0 = (size_t)(bcol + r0c) * K + (s) * 32 + c0c * 8;     \
        const size_t gb1 = (size_t)(bcol + r1c) * K + (s) * 32 + c1c * 8;     \
        cp16(stb_ + so0,         Af + ga0);                                   \
        cp16(stb_ + so1,         Af + ga1);                                   \
        cp16(stb_ + 10240 + so0, W + gb0);                                    \
        cp16(stb_ + 10240 + so1, W + gb1);                                    \
    } while (0)

    float acc[4][4][4];
#pragma unroll
    for (int i = 0; i < 4; i++)
#pragma unroll
        for (int j = 0; j < 4; j++)
#pragma unroll
            for (int r = 0; r < 4; r++) acc[i][j][r] = 0.f;

    LOAD_STAGE(0, 0); CP_COMMIT();
    LOAD_STAGE(1, 1); CP_COMMIT();

    const uint32_t a_lrow = (uint32_t)(lane & 15);
    const uint32_t a_koff = (uint32_t)((lane & 16) >> 1);
    const uint32_t b_lrow = (uint32_t)((lane & 7) + ((lane & 16) >> 1));
    const uint32_t b_koff = (uint32_t)(lane & 8);

    for (int s = 0; s < nst; s++) {
        CP_WAIT1();
        __syncthreads();
        if (s + 2 < nst) LOAD_STAGE(s + 2, (s + 2) % 3);
        CP_COMMIT();
        const uint32_t stb = sb + (uint32_t)(s % 3) * STAGE_BYTES;

#pragma unroll
        for (int kk = 0; kk < 32; kk += 16) {
            uint32_t bh[2][4];
            const uint32_t bkcol = (uint32_t)kk + b_koff;
#pragma unroll
            for (int ni = 0; ni < 2; ni++) {
                const uint32_t addr =
                    stb + 10240 + (uint32_t)(wn + ni * 16 + b_lrow) * 80 + bkcol * 2;
                ldm_x4(bh[ni][0], bh[ni][1], bh[ni][2], bh[ni][3], addr);
            }
            const uint32_t akcol = (uint32_t)kk + a_koff;
#pragma unroll
            for (int mi = 0; mi < 4; mi++) {
                uint32_t a[4];
                const uint32_t addr = stb + (uint32_t)(wm + mi * 16 + a_lrow) * 80 + akcol * 2;
                ldm_x4(a[0], a[1], a[2], a[3], addr);
#pragma unroll
                for (int nj = 0; nj < 4; nj++) {
                    const int g = nj >> 1, p = (nj & 1) * 2;
                    mma16816h(acc[mi][nj], a, bh[g][p], bh[g][p + 1]);
                }
            }
        }
    }

    const int qr = lane >> 2, qc = (lane & 3) * 2;
#pragma unroll
    for (int mi = 0; mi < 4; mi++) {
        const size_t gr = (size_t)(brow + wm + mi * 16 + qr);
#pragma unroll
        for (int nj = 0; nj < 4; nj++) {
            const int gc = bcol + wn + nj * 8 + qc;
            const float2 b2 = *(const float2*)(bias + gc);
            if (MODE == 0 || MODE == 2) {
                float2 o0, o1;
                o0.x = acc[mi][nj][0] + b2.x;
                o0.y = acc[mi][nj][1] + b2.y;
                o1.x = acc[mi][nj][2] + b2.x;
                o1.y = acc[mi][nj][3] + b2.y;
                if (MODE == 2) {
                    const float2 r0 = *(const float2*)(R + gr * N + gc);
                    const float2 r1 = *(const float2*)(R + (gr + 8) * N + gc);
                    o0.x += r0.x; o0.y += r0.y;
                    o1.x += r1.x; o1.y += r1.y;
                }
                *(float2*)(C + gr * N + gc)       = o0;
                *(float2*)(C + (gr + 8) * N + gc) = o1;
            } else {
                const float h1v0 = acc[mi][nj][0] + b2.x;
                const float hg0  = acc[mi][nj][1] + b2.y;
                const float h1v1 = acc[mi][nj][2] + b2.x;
                const float hg1  = acc[mi][nj][3] + b2.y;
                const float o0 = h1v0 / (1.f + ex2f(-hg0 * L2E));
                const float o1 = h1v1 / (1.f + ex2f(-hg1 * L2E));
                const size_t co = (size_t)(gc >> 1);
                Of[gr * (N >> 1) + co]       = __float2half(o0);
                Of[(gr + 8) * (N >> 1) + co] = __float2half(o1);
            }
        }
    }
#undef LOAD_STAGE
}

// =================== HMMA flash attention (bf16 3-term internally) ===================
#define ATT_QH 0
#define ATT_QL 18432
#define ATT_KH 36864
#define ATT_KL 46080
#define ATT_VH 55296
#define ATT_VL 64512
#define ATT_SMEM 73728

__global__ __launch_bounds__(256, 2)
void attention_mma_clean(const float* __restrict__ QKVG, const float* __restrict__ PB,
                         __half* __restrict__ CTXF) {
    extern __shared__ char smem[];
    const uint32_t sbase = smem_u32(smem);
    const int tid = threadIdx.x;
    const int wid = tid >> 5, lane = tid & 31;
    const int b = blockIdx.y >> 4, h = blockIdx.y & 15;
    const int q0 = blockIdx.x * 128;
    const int wr = wid * 16;

#pragma unroll
    for (int it = 0; it < 8; it++) {
        const int c = tid + it * 256;
        const int r = c >> 4, col = (c & 15) * 4;
        const float4 v =
            *(const float4*)&QKVG[(((size_t)b << 10) + q0 + r) * 4096 + h * 64 + col];
        cvt_store8(v, smem + ATT_QH + r * 144 + col * 2,
                      smem + ATT_QL + r * 144 + col * 2);
    }

    const uint32_t a_lrow = (uint32_t)(lane & 15);
    const uint32_t a_koff2 = (uint32_t)((lane & 16) >> 1) * 2;
    const uint32_t b_lrow = (uint32_t)((lane & 7) + ((lane & 16) >> 1));
    const uint32_t b_koff2 = (uint32_t)(lane & 8) * 2;
    const uint32_t v_row = (uint32_t)((lane & 7) + (lane & 8));
    const uint32_t v_col2 = (uint32_t)((lane & 16) >> 1) * 2;

    const int qr = lane >> 2, qc = (lane & 3) * 2;
    float m0 = -1e30f, m1 = -1e30f, l0 = 0.f, l1 = 0.f;
    float oacc[8][4];
#pragma unroll
    for (int nt = 0; nt < 8; nt++)
#pragma unroll
        for (int e = 0; e < 4; e++) oacc[nt][e] = 0.f;

    for (int kt = 0; kt < 16; kt++) {
        __syncthreads();
#pragma unroll
        for (int it = 0; it < 4; it++) {
            const int c = tid + it * 256;
            const int r = c >> 4, col = (c & 15) * 4;
            const size_t gb = (((size_t)b << 10) + kt * 64 + r) * 4096 + h * 64 + col;
            const float4 kv = *(const float4*)&QKVG[gb + 1024];
            const float4 vv = *(const float4*)&QKVG[gb + 2048];
            cvt_store8(kv, smem + ATT_KH + r * 144 + col * 2,
                           smem + ATT_KL + r * 144 + col * 2);
            cvt_store8(vv, smem + ATT_VH + r * 144 + col * 2,
                           smem + ATT_VL + r * 144 + col * 2);
        }
        __syncthreads();

        float sa[8][4];
#pragma unroll
        for (int nt = 0; nt < 8; nt++)
#pragma unroll
            for (int e = 0; e < 4; e++) sa[nt][e] = 0.f;

#pragma unroll
        for (int k16 = 0; k16 < 4; k16++) {
            uint32_t qh[4], ql[4];
            const uint32_t qaddr =
                sbase + ATT_QH + (uint32_t)(wr + a_lrow) * 144 + k16 * 32 + a_koff2;
            ldm_x4(qh[0], qh[1], qh[2], qh[3], qaddr);
            ldm_x4(ql[0], ql[1], ql[2], ql[3], qaddr + (ATT_QL - ATT_QH));
#pragma unroll
            for (int ntp = 0; ntp < 4; ntp++) {
                uint32_t kh[4], kl[4];
                const uint32_t kaddr =
                    sbase + ATT_KH + (uint32_t)(ntp * 16 + b_lrow) * 144 + k16 * 32 + b_koff2;
                ldm_x4(kh[0], kh[1], kh[2], kh[3], kaddr);
                ldm_x4(kl[0], kl[1], kl[2], kl[3], kaddr + (ATT_KL - ATT_KH));
                mma16816(sa[2 * ntp],     qh, kh[0], kh[1]);
                mma16816(sa[2 * ntp],     qh, kl[0], kl[1]);
                mma16816(sa[2 * ntp],     ql, kh[0], kh[1]);
                mma16816(sa[2 * ntp + 1], qh, kh[2], kh[3]);
                mma16816(sa[2 * ntp + 1], qh, kl[2], kl[3]);
                mma16816(sa[2 * ntp + 1], ql, kh[2], kh[3]);
            }
        }

        const size_t r0g = (size_t)(q0 + wr + qr);
        const size_t pb0 = r0g * 1024 + kt * 64 + qc;
        const size_t pb1 = (r0g + 8) * 1024 + kt * 64 + qc;
#pragma unroll
        for (int nt = 0; nt < 8; nt++) {
            const float2 p0 = *(const float2*)&PB[pb0 + nt * 8];
            const float2 p1 = *(const float2*)&PB[pb1 + nt * 8];
            sa[nt][0] = sa[nt][0] * 0.125f + p0.x;
            sa[nt][1] = sa[nt][1] * 0.125f + p0.y;
            sa[nt][2] = sa[nt][2] * 0.125f + p1.x;
            sa[nt][3] = sa[nt][3] * 0.125f + p1.y;
        }

        float tm0 = -1e30f, tm1 = -1e30f;
#pragma unroll
        for (int nt = 0; nt < 8; nt++) {
            tm0 = fmaxf(tm0, fmaxf(sa[nt][0], sa[nt][1]));
            tm1 = fmaxf(tm1, fmaxf(sa[nt][2], sa[nt][3]));
        }
        tm0 = fmaxf(tm0, __shfl_xor_sync(0xffffffffu, tm0, 1));
        tm0 = fmaxf(tm0, __shfl_xor_sync(0xffffffffu, tm0, 2));
        tm1 = fmaxf(tm1, __shfl_xor_sync(0xffffffffu, tm1, 1));
        tm1 = fmaxf(tm1, __shfl_xor_sync(0xffffffffu, tm1, 2));
        const float mn0 = fmaxf(m0, tm0), mn1 = fmaxf(m1, tm1);
        const float cr0 = ex2f((m0 - mn0) * L2E), cr1 = ex2f((m1 - mn1) * L2E);
        m0 = mn0; m1 = mn1;

        float rs0 = 0.f, rs1 = 0.f;
#pragma unroll
        for (int nt = 0; nt < 8; nt++) {
            sa[nt][0] = ex2f((sa[nt][0] - mn0) * L2E);
            sa[nt][1] = ex2f((sa[nt][1] - mn0) * L2E);
            sa[nt][2] = ex2f((sa[nt][2] - mn1) * L2E);
            sa[nt][3] = ex2f((sa[nt][3] - mn1) * L2E);
            rs0 += sa[nt][0] + sa[nt][1];
            rs1 += sa[nt][2] + sa[nt][3];
        }
        rs0 += __shfl_xor_sync(0xffffffffu, rs0, 1);
        rs0 += __shfl_xor_sync(0xffffffffu, rs0, 2);
        rs1 += __shfl_xor_sync(0xffffffffu, rs1, 1);
        rs1 += __shfl_xor_sync(0xffffffffu, rs1, 2);
        l0 = l0 * cr0 + rs0;
        l1 = l1 * cr1 + rs1;
#pragma unroll
        for (int nt = 0; nt < 8; nt++) {
            oacc[nt][0] *= cr0; oacc[nt][1] *= cr0;
            oacc[nt][2] *= cr1; oacc[nt][3] *= cr1;
        }

#pragma unroll
        for (int j = 0; j < 4; j++) {
            uint32_t pha[4], pla[4];
            {
                const float* s0 = sa[2 * j];
                const float* s1 = sa[2 * j + 1];
                __nv_bfloat162 h;
                float r0, r1;
                h = __floats2bfloat162_rn(s0[0], s0[1]);
                pha[0] = *(uint32_t*)&h;
                r0 = s0[0] - __bfloat162float(h.x); r1 = s0[1] - __bfloat162float(h.y);
                h = __floats2bfloat162_rn(r0, r1); pla[0] = *(uint32_t*)&h;
                h = __floats2bfloat162_rn(s0[2], s0[3]);
                pha[1] = *(uint32_t*)&h;
                r0 = s0[2] - __bfloat162float(h.x); r1 = s0[3] - __bfloat162float(h.y);
                h = __floats2bfloat162_rn(r0, r1); pla[1] = *(uint32_t*)&h;
                h = __floats2bfloat162_rn(s1[0], s1[1]);
                pha[2] = *(uint32_t*)&h;
                r0 = s1[0] - __bfloat162float(h.x); r1 = s1[1] - __bfloat162float(h.y);
                h = __floats2bfloat162_rn(r0, r1); pla[2] = *(uint32_t*)&h;
                h = __floats2bfloat162_rn(s1[2], s1[3]);
                pha[3] = *(uint32_t*)&h;
                r0 = s1[2] - __bfloat162float(h.x); r1 = s1[3] - __bfloat162float(h.y);
                h = __floats2bfloat162_rn(r0, r1); pla[3] = *(uint32_t*)&h;
            }
#pragma unroll
            for (int ntp = 0; ntp < 4; ntp++) {
                uint32_t vh[4], vl[4];
                const uint32_t vaddr = sbase + ATT_VH +
                    (uint32_t)(j * 16 + v_row) * 144 + (uint32_t)(ntp * 16) * 2 + v_col2;
                ldm_x4t(vh[0], vh[1], vh[2], vh[3], vaddr);
                ldm_x4t(vl[0], vl[1], vl[2], vl[3], vaddr + (ATT_VL - ATT_VH));
                mma16816(oacc[2 * ntp],     pha, vh[0], vh[1]);
                mma16816(oacc[2 * ntp],     pha, vl[0], vl[1]);
                mma16816(oacc[2 * ntp],     pla, vh[0], vh[1]);
                mma16816(oacc[2 * ntp + 1], pha, vh[2], vh[3]);
                mma16816(oacc[2 * ntp + 1], pha, vl[2], vl[3]);
                mma16816(oacc[2 * ntp + 1], pla, vh[2], vh[3]);
            }
        }
    }

    // ---- write ctx fp16 single ----
    const float inv0 = 1.f / l0, inv1 = 1.f / l1;
    const size_t cr0 = (size_t)((b << 10) + q0 + wr + qr);
    const size_t colb = (size_t)(h * 64 + qc);
#pragma unroll
    for (int nt = 0; nt < 8; nt++) {
        const __half2 h2a = __floats2half2_rn(oacc[nt][0] * inv0, oacc[nt][1] * inv0);
        const __half2 h2b = __floats2half2_rn(oacc[nt][2] * inv1, oacc[nt][3] * inv1);
        *(__half2*)(CTXF + cr0 * 1024 + colb + nt * 8)       = h2a;
        *(__half2*)(CTXF + (cr0 + 8) * 1024 + colb + nt * 8) = h2b;
    }
}

// =================== weight transpose -> single fp16 (with row interleave) ===================
__global__ __launch_bounds__(256)
void transpose_conv(const float* __restrict__ W, __half* __restrict__ T,
                    int K, int N, int rs, int ro) {
    __shared__ float t[32][33];
    const int k0 = blockIdx.y * 32, n0 = blockIdx.x * 32;
    const int tx = threadIdx.x & 31, ty = threadIdx.x >> 5;
#pragma unroll
    for (int l = 0; l < 4; l++)
        t[ty + 8 * l][tx] = W[(size_t)(k0 + ty + 8 * l) * N + n0 + tx];
    __syncthreads();
#pragma unroll
    for (int l = 0; l < 4; l++) {
        const size_t o = ((size_t)(n0 + ty + 8 * l) * rs + ro) * K + k0 + tx;
        T[o] = __float2half(t[tx][ty + 8 * l]);
    }
}

__global__ __launch_bounds__(256)
void conv_half(const float* __restrict__ X, __half* __restrict__ Xf) {
    const size_t i = ((size_t)blockIdx.x * 256 + threadIdx.x) * 4;
    const float4 v = *(const float4*)(X + i);
    uint2 o;
    const __half2 a = __floats2half2_rn(v.x, v.y);
    const __half2 b = __floats2half2_rn(v.z, v.w);
    o.x = *(const uint32_t*)&a;
    o.y = *(const uint32_t*)&b;
    *(uint2*)(Xf + i) = o;
}

__global__ void pack_bias(const float* bq, const float* bk, const float* bv,
                          const float* bg, const float* bf1, const float* bfg,
                          float* outq, float* outf) {
    const int i = blockIdx.x * 256 + threadIdx.x;   // 0..12287
    if (i < 1024) outq[i] = bq[i];
    else if (i < 2048) outq[i] = bk[i - 1024];
    else if (i < 3072) outq[i] = bv[i - 2048];
    else if (i < 4096) outq[i] = bg[i - 3072];
    else if (i < 8192) outf[2 * (i - 4096)] = bf1[i - 4096];
    else outf[2 * (i - 8192) + 1] = bfg[i - 8192];
}

__global__ __launch_bounds__(256)
void posbias_kernel(const float* __restrict__ pe, float* __restrict__ pb) {
    const size_t i = (size_t)blockIdx.x * 256 + threadIdx.x;
    const float4 a = *(const float4*)&pe[i * 8];
    const float4 b = *(const float4*)&pe[i * 8 + 4];
    pb[i] = (a.x + a.y + a.z + a.w + b.x + b.y + b.z + b.w) * 0.125f;
}

// ---------------- LN1: x1 = LN(x + sigmoid(gate)*attn); emit fp32 + fp16 ----------------
__global__ __launch_bounds__(256)
void ln1_kernel(const float* __restrict__ x, const float* __restrict__ attn,
                const float* __restrict__ qkvg, const float* __restrict__ gw,
                const float* __restrict__ gb, float* __restrict__ x1,
                __half* __restrict__ x1f) {
    const size_t base = (size_t)blockIdx.x * E_DIM;
    const size_t gbase = (size_t)blockIdx.x * 4096 + 3072;
    const int t = threadIdx.x;
    float vals[4];
    float s = 0.f, s2 = 0.f;
#pragma unroll
    for (int i = 0; i < 4; i++) {
        const int c = t + i * 256;
        const float gp = qkvg[gbase + c];
        const float sg = 1.f / (1.f + __expf(-gp));
        const float val = x[base + c] + attn[base + c] * sg;
        vals[i] = val; s += val; s2 += val * val;
    }
    __shared__ float rsm[8], rs2[8];
#pragma unroll
    for (int o = 16; o; o >>= 1) {
        s  += __shfl_xor_sync(0xffffffffu, s,  o);
        s2 += __shfl_xor_sync(0xffffffffu, s2, o);
    }
    if ((t & 31) == 0) { rsm[t >> 5] = s; rs2[t >> 5] = s2; }
    __syncthreads();
    float S = 0.f, S2 = 0.f;
#pragma unroll
    for (int i = 0; i < 8; i++) { S += rsm[i]; S2 += rs2[i]; }
    const float mean = S * (1.f / E_DIM);
    const float var = S2 * (1.f / E_DIM) - mean * mean;
    const float inv = rsqrtf(var + 1e-6f);
#pragma unroll
    for (int i = 0; i < 4; i++) {
        const int c = t + i * 256;
        const float v = (vals[i] - mean) * inv * gw[c] + gb[c];
        x1[base + c] = v;
        x1f[base + c] = __float2half(v);
    }
}

// ---------------- LN2 (input already contains x1+ff residual) ----------------
__global__ __launch_bounds__(256)
void ln2_kernel(const float* __restrict__ ff,
                const float* __restrict__ gw, const float* __restrict__ gb,
                float* __restrict__ out) {
    const size_t base = (size_t)blockIdx.x * E_DIM;
    const int t = threadIdx.x;
    float vals[4];
    float s = 0.f, s2 = 0.f;
#pragma unroll
    for (int i = 0; i < 4; i++) {
        const int c = t + i * 256;
        const float val = ff[base + c];
        vals[i] = val; s += val; s2 += val * val;
    }
    __shared__ float rsm[8], rs2[8];
#pragma unroll
    for (int o = 16; o; o >>= 1) {
        s  += __shfl_xor_sync(0xffffffffu, s,  o);
        s2 += __shfl_xor_sync(0xffffffffu, s2, o);
    }
    if ((t & 31) == 0) { rsm[t >> 5] = s; rs2[t >> 5] = s2; }
    __syncthreads();
    float S = 0.f, S2 = 0.f;
#pragma unroll
    for (int i = 0; i < 8; i++) { S += rsm[i]; S2 += rs2[i]; }
    const float mean = S * (1.f / E_DIM);
    const float var = S2 * (1.f / E_DIM) - mean * mean;
    const float inv = rsqrtf(var + 1e-6f);
#pragma unroll
    for (int i = 0; i < 4; i++) {
        const int c = t + i * 256;
        out[base + c] = (vals[i] - mean) * inv * gw[c] + gb[c];
    }
}

// =================== launch ===================
extern "C" void kernel_launch(void* const* d_in, const int* in_sizes, int n_in,
                              void* d_out, int out_size) {
    const float* x   = (const float*)d_in[0];
    const float* pe  = (const float*)d_in[1];
    const float* Wq  = (const float*)d_in[2];
    const float* bq  = (const float*)d_in[3];
    const float* Wk  = (const float*)d_in[4];
    const float* bk  = (const float*)d_in[5];
    const float* Wv  = (const float*)d_in[6];
    const float* bv  = (const float*)d_in[7];
    const float* Wo  = (const float*)d_in[8];
    const float* bo  = (const float*)d_in[9];
    const float* Wg  = (const float*)d_in[10];
    const float* bg  = (const float*)d_in[11];
    const float* Wf1 = (const float*)d_in[12];
    const float* bf1 = (const float*)d_in[13];
    const float* Wfg = (const float*)d_in[14];
    const float* bfg = (const float*)d_in[15];
    const float* Wf2 = (const float*)d_in[16];
    const float* bf2 = (const float*)d_in[17];
    const float* l1g = (const float*)d_in[18];
    const float* l1b = (const float*)d_in[19];
    const float* l2g = (const float*)d_in[20];
    const float* l2b = (const float*)d_in[21];
    float* out = (float*)d_out;

    float *qkvg, *tmp, *x1, *pb, *biasq, *biasf;
    __half *xf, *ctxf, *x1f, *h1f;
    __half *wq, *wo, *wff, *w2;
    cudaGetSymbolAddress((void**)&qkvg, g_qkvg);
    cudaGetSymbolAddress((void**)&tmp, g_tmp);
    cudaGetSymbolAddress((void**)&x1, g_x1);
    cudaGetSymbolAddress((void**)&pb, g_pb);
    cudaGetSymbolAddress((void**)&biasq, g_bias_qkvg);
    cudaGetSymbolAddress((void**)&biasf, g_bias_ff);
    cudaGetSymbolAddress((void**)&xf, g_xf);
    cudaGetSymbolAddress((void**)&ctxf, g_ctxf);
    cudaGetSymbolAddress((void**)&x1f, g_x1f);
    cudaGetSymbolAddress((void**)&h1f, g_h1f);
    cudaGetSymbolAddress((void**)&wq, g_wqkvg);
    cudaGetSymbolAddress((void**)&wo, g_wo);
    cudaGetSymbolAddress((void**)&wff, g_wff);
    cudaGetSymbolAddress((void**)&w2, g_wf2);

    cudaFuncSetAttribute(attention_mma_clean,
                         cudaFuncAttributeMaxDynamicSharedMemorySize, ATT_SMEM);
    cudaFuncSetAttribute(hmma_gemm<0>,
                         cudaFuncAttributeMaxDynamicSharedMemorySize, GEMM_SMEM);
    cudaFuncSetAttribute(hmma_gemm<1>,
                         cudaFuncAttributeMaxDynamicSharedMemorySize, GEMM_SMEM);
    cudaFuncSetAttribute(hmma_gemm<2>,
                         cudaFuncAttributeMaxDynamicSharedMemorySize, GEMM_SMEM);

    // --- prep ---
    posbias_kernel<<<4096, 256>>>(pe, pb);
    conv_half<<<M_ROWS * E_DIM / 1024, 256>>>(x, xf);

    transpose_conv<<<dim3(32, 32), 256>>>(Wq,  wq,             1024, 1024, 1, 0);
    transpose_conv<<<dim3(32, 32), 256>>>(Wk,  wq + 1024*1024, 1024, 1024, 1, 0);
    transpose_conv<<<dim3(32, 32), 256>>>(Wv,  wq + 2048*1024, 1024, 1024, 1, 0);
    transpose_conv<<<dim3(32, 32), 256>>>(Wg,  wq + 3072*1024, 1024, 1024, 1, 0);
    transpose_conv<<<dim3(32, 32), 256>>>(Wo,  wo, 1024, 1024, 1, 0);
    transpose_conv<<<dim3(128, 32), 256>>>(Wf1, wff, 1024, 4096, 2, 0);
    transpose_conv<<<dim3(128, 32), 256>>>(Wfg, wff, 1024, 4096, 2, 1);
    transpose_conv<<<dim3(32, 128), 256>>>(Wf2, w2, 4096, 1024, 1, 0);
    pack_bias<<<48, 256>>>(bq, bk, bv, bg, bf1, bfg, biasq, biasf);

    // --- QKV + gate projection ---
    hmma_gemm<0><<<dim3(32, 32), 256, GEMM_SMEM>>>(xf, wq, biasq, qkvg,
                                                   nullptr, nullptr,
                                                   M_ROWS, 4096, 1024);
    // --- HMMA flash attention ---
    attention_mma_clean<<<dim3(8, 64), 256, ATT_SMEM>>>(qkvg, pb, ctxf);
    // --- output projection ---
    hmma_gemm<0><<<dim3(8, 32), 256, GEMM_SMEM>>>(ctxf, wo, bo, tmp,
                                                  nullptr, nullptr,
                                                  M_ROWS, 1024, 1024);
    // --- gate + residual + LN1 ---
    ln1_kernel<<<M_ROWS, 256>>>(x, tmp, qkvg, l1g, l1b, x1, x1f);
    // --- FFN up with fused SwiGLU epilogue ---
    hmma_gemm<1><<<dim3(64, 32), 256, GEMM_SMEM>>>(x1f, wff, biasf, nullptr,
                                                   h1f, nullptr,
                                                   M_ROWS, 8192, 1024);
    // --- FFN down + fused residual add (tmp = x1 + ff) ---
    hmma_gemm<2><<<dim3(8, 32), 256, GEMM_SMEM>>>(h1f, w2, bf2, tmp,
                                                  nullptr, x1,
                                                  M_ROWS, 1024, 4096);
    // --- LN2 ---
    ln2_kernel<<<M_ROWS, 256>>>(tmp, l2g, l2b, out);
}

// round 8
// speedup vs baseline: 6.4520x; 1.1199x over previous
#include <cuda_runtime.h>
#include <cuda_fp16.h>
#include <cstdint>
#include <cstddef>

// Problem constants
#define E_DIM 1024
#define S_LEN 1024
#define B_SZ 4
#define NH 16
#define HD 64
#define FF_DIM 4096
#define M_ROWS (B_SZ * S_LEN)   // 4096

// ---------------- scratch (static device globals; no allocation) ----------------
__device__ float g_tmp[M_ROWS * E_DIM];          // attn_out, later (x1+ff)
__device__ float g_x1[M_ROWS * E_DIM];
__device__ float g_pb[S_LEN * S_LEN];

// fp16 activations
__device__ __half g_qkvgf[M_ROWS * 4096];        // [q|k|v|gate] fp16
__device__ __half g_xf[M_ROWS * E_DIM];
__device__ __half g_ctxf[M_ROWS * E_DIM];
__device__ __half g_x1f[M_ROWS * E_DIM];
__device__ __half g_h1f[(size_t)M_ROWS * FF_DIM];

// transposed fp16 weights (K-major: [N,K])
__device__ __half g_wqkvg[4096 * 1024];
__device__ __half g_wo[1024 * 1024];
__device__ __half g_wff[8192 * 1024];            // interleaved: row 2n = Wf1_n, 2n+1 = Wfg_n
__device__ __half g_wf2[1024 * 4096];

__device__ float g_bias_qkvg[4096];
__device__ float g_bias_ff[8192];                 // interleaved bf1/bfg

#define L2E 1.4426950408889634f

// =================== PTX helpers (baseline sm_80+ features only) ===================
__device__ __forceinline__ uint32_t smem_u32(const void* p) {
    uint32_t a;
    asm("{ .reg .u64 t; cvta.to.shared.u64 t, %1; cvt.u32.u64 %0, t; }" : "=r"(a) : "l"(p));
    return a;
}
__device__ __forceinline__ void cp16(uint32_t dst, const void* src) {
    asm volatile("cp.async.cg.shared.global [%0], [%1], 16;" :: "r"(dst), "l"(src));
}
#define CP_COMMIT() asm volatile("cp.async.commit_group;" ::: "memory")
#define CP_WAIT1()  asm volatile("cp.async.wait_group 1;" ::: "memory")
#define CP_WAIT0()  asm volatile("cp.async.wait_group 0;" ::: "memory")

__device__ __forceinline__ void ldm_x4(uint32_t& r0, uint32_t& r1, uint32_t& r2,
                                       uint32_t& r3, uint32_t addr) {
    asm volatile("ldmatrix.sync.aligned.m8n8.x4.shared.b16 {%0,%1,%2,%3}, [%4];"
                 : "=r"(r0), "=r"(r1), "=r"(r2), "=r"(r3) : "r"(addr));
}
__device__ __forceinline__ void ldm_x4t(uint32_t& r0, uint32_t& r1, uint32_t& r2,
                                        uint32_t& r3, uint32_t addr) {
    asm volatile("ldmatrix.sync.aligned.m8n8.x4.trans.shared.b16 {%0,%1,%2,%3}, [%4];"
                 : "=r"(r0), "=r"(r1), "=r"(r2), "=r"(r3) : "r"(addr));
}
// fp16 MMA
__device__ __forceinline__ void mma16816h(float* c, const uint32_t* a,
                                          uint32_t b0, uint32_t b1) {
    asm volatile(
        "mma.sync.aligned.m16n8k16.row.col.f32.f16.f16.f32 "
        "{%0,%1,%2,%3}, {%4,%5,%6,%7}, {%8,%9}, {%0,%1,%2,%3};"
        : "+f"(c[0]), "+f"(c[1]), "+f"(c[2]), "+f"(c[3])
        : "r"(a[0]), "r"(a[1]), "r"(a[2]), "r"(a[3]), "r"(b0), "r"(b1));
}
__device__ __forceinline__ float ex2f(float x) {
    float y;
    asm("ex2.approx.ftz.f32 %0, %1;" : "=f"(y) : "f"(x));
    return y;
}

// =================== HMMA GEMM (fp16 single x single, 1 MMA per k16) ===================
// A: [M,K] fp16. W: [N,K] fp16.
// MODE 0: C[M,N] fp32 = A@W^T + bias
// MODE 1: SwiGLU: Of[M,N/2] fp16 = (c_even+b_even) * sigmoid(c_odd+b_odd)
// MODE 2: C = A@W^T + bias + R
// MODE 3: Of[M,N] fp16 = A@W^T + bias
#define STAGE_BYTES 20480
#define GEMM_SMEM (3 * STAGE_BYTES)

template <int MODE>
__global__ __launch_bounds__(256, 2)
void hmma_gemm(const __half* __restrict__ Af, const __half* __restrict__ W,
               const float* __restrict__ bias, float* __restrict__ C,
               __half* __restrict__ Of, const float* __restrict__ R,
               int M, int N, int K) {
    extern __shared__ char smem[];
    const uint32_t sb = smem_u32(smem);
    const int tid = threadIdx.x;
    const int wid = tid >> 5, lane = tid & 31;
    const int brow = blockIdx.y * 128, bcol = blockIdx.x * 128;
    const int wm = (wid >> 2) * 64, wn = (wid & 3) * 32;
    const int nst = K >> 5;

    const int r0c = tid >> 2, r1c = (tid + 256) >> 2;
    const int c0c = tid & 3,  c1c = (tid + 256) & 3;
    const uint32_t so0 = (uint32_t)(r0c * 80 + c0c * 16);
    const uint32_t so1 = (uint32_t)(r1c * 80 + c1c * 16);

#define LOAD_STAGE(s, buf) do {                                               \
        const uint32_t stb_ = sb + (buf) * STAGE_BYTES;                       \
        const size_t ga0 = (size_t)(brow + r0c) * K + (s) * 32 + c0c * 8;     \
        const size_t ga1 = (size_t)(brow + r1c) * K + (s) * 32 + c1c * 8;     \
        const size_t gb0 = (size_t)(bcol + r0c) * K + (s) * 32 + c0c * 8;     \
        const size_t gb1 = (size_t)(bcol + r1c) * K + (s) * 32 + c1c * 8;     \
        cp16(stb_ + so0,         Af + ga0);                                   \
        cp16(stb_ + so1,         Af + ga1);                                   \
        cp16(stb_ + 10240 + so0, W + gb0);                                    \
        cp16(stb_ + 10240 + so1, W + gb1);                                    \
    } while (0)

    float acc[4][4][4];
#pragma unroll
    for (int i = 0; i < 4; i++)
#pragma unroll
        for (int j = 0; j < 4; j++)
#pragma unroll
            for (int r = 0; r < 4; r++) acc[i][j][r] = 0.f;

    LOAD_STAGE(0, 0); CP_COMMIT();
    LOAD_STAGE(1, 1); CP_COMMIT();

    const uint32_t a_lrow = (uint32_t)(lane & 15);
    const uint32_t a_koff = (uint32_t)((lane & 16) >> 1);
    const uint32_t b_lrow = (uint32_t)((lane & 7) + ((lane & 16) >> 1));
    const uint32_t b_koff = (uint32_t)(lane & 8);

    for (int s = 0; s < nst; s++) {
        CP_WAIT1();
        __syncthreads();
        if (s + 2 < nst) LOAD_STAGE(s + 2, (s + 2) % 3);
        CP_COMMIT();
        const uint32_t stb = sb + (uint32_t)(s % 3) * STAGE_BYTES;

#pragma unroll
        for (int kk = 0; kk < 32; kk += 16) {
            uint32_t bh[2][4];
            const uint32_t bkcol = (uint32_t)kk + b_koff;
#pragma unroll
            for (int ni = 0; ni < 2; ni++) {
                const uint32_t addr =
                    stb + 10240 + (uint32_t)(wn + ni * 16 + b_lrow) * 80 + bkcol * 2;
                ldm_x4(bh[ni][0], bh[ni][1], bh[ni][2], bh[ni][3], addr);
            }
            const uint32_t akcol = (uint32_t)kk + a_koff;
#pragma unroll
            for (int mi = 0; mi < 4; mi++) {
                uint32_t a[4];
                const uint32_t addr = stb + (uint32_t)(wm + mi * 16 + a_lrow) * 80 + akcol * 2;
                ldm_x4(a[0], a[1], a[2], a[3], addr);
#pragma unroll
                for (int nj = 0; nj < 4; nj++) {
                    const int g = nj >> 1, p = (nj & 1) * 2;
                    mma16816h(acc[mi][nj], a, bh[g][p], bh[g][p + 1]);
                }
            }
        }
    }

    const int qr = lane >> 2, qc = (lane & 3) * 2;
#pragma unroll
    for (int mi = 0; mi < 4; mi++) {
        const size_t gr = (size_t)(brow + wm + mi * 16 + qr);
#pragma unroll
        for (int nj = 0; nj < 4; nj++) {
            const int gc = bcol + wn + nj * 8 + qc;
            const float2 b2 = *(const float2*)(bias + gc);
            if (MODE == 0 || MODE == 2) {
                float2 o0, o1;
                o0.x = acc[mi][nj][0] + b2.x;
                o0.y = acc[mi][nj][1] + b2.y;
                o1.x = acc[mi][nj][2] + b2.x;
                o1.y = acc[mi][nj][3] + b2.y;
                if (MODE == 2) {
                    const float2 r0 = *(const float2*)(R + gr * N + gc);
                    const float2 r1 = *(const float2*)(R + (gr + 8) * N + gc);
                    o0.x += r0.x; o0.y += r0.y;
                    o1.x += r1.x; o1.y += r1.y;
                }
                *(float2*)(C + gr * N + gc)       = o0;
                *(float2*)(C + (gr + 8) * N + gc) = o1;
            } else if (MODE == 3) {
                const __half2 o0 = __floats2half2_rn(acc[mi][nj][0] + b2.x,
                                                     acc[mi][nj][1] + b2.y);
                const __half2 o1 = __floats2half2_rn(acc[mi][nj][2] + b2.x,
                                                     acc[mi][nj][3] + b2.y);
                *(__half2*)(Of + gr * N + gc)       = o0;
                *(__half2*)(Of + (gr + 8) * N + gc) = o1;
            } else {
                const float h1v0 = acc[mi][nj][0] + b2.x;
                const float hg0  = acc[mi][nj][1] + b2.y;
                const float h1v1 = acc[mi][nj][2] + b2.x;
                const float hg1  = acc[mi][nj][3] + b2.y;
                const float o0 = h1v0 / (1.f + ex2f(-hg0 * L2E));
                const float o1 = h1v1 / (1.f + ex2f(-hg1 * L2E));
                const size_t co = (size_t)(gc >> 1);
                Of[gr * (N >> 1) + co]       = __float2half(o0);
                Of[(gr + 8) * (N >> 1) + co] = __float2half(o1);
            }
        }
    }
#undef LOAD_STAGE
}

// =================== fp16 flash attention ===================
// CTA = (b, h, 128 q rows). 8 warps x m16 bands. K-tiles of 64 keys.
// smem (fp16, row stride 144B): Q[128] @0 (18432B); two KV buffers
// (K[64]@+0, V[64]@+9216) at 18432 and 36864.
#define ATT_Q 0
#define ATT_KV0 18432
#define ATT_KV1 36864
#define ATT_SMEM 55296

__global__ __launch_bounds__(256, 2)
void attention_f16(const __half* __restrict__ QKVF, const float* __restrict__ PB,
                   __half* __restrict__ CTXF) {
    extern __shared__ char smem[];
    const uint32_t sbase = smem_u32(smem);
    const int tid = threadIdx.x;
    const int wid = tid >> 5, lane = tid & 31;
    const int b = blockIdx.y >> 4, h = blockIdx.y & 15;
    const int q0 = blockIdx.x * 128;
    const int wr = wid * 16;

    // ---- Q tile: 128 rows x 64 halfs via cp.async (1024 16B chunks) ----
#pragma unroll
    for (int it = 0; it < 4; it++) {
        const int c = tid + it * 256;
        const int r = c >> 3, co = c & 7;
        cp16(sbase + ATT_Q + (uint32_t)(r * 144 + co * 16),
             QKVF + (((size_t)b << 10) + q0 + r) * 4096 + h * 64 + co * 8);
    }
    // ---- KV tile loader ----
#define LOAD_KV(kt, bufoff) do {                                              \
        _Pragma("unroll")                                                     \
        for (int it = 0; it < 4; it++) {                                      \
            const int c = tid + it * 256;   /* 0..1023: K then V */           \
            const int kv = c >> 9;          /* 0 = K, 1 = V */                \
            const int cc = c & 511;                                           \
            const int r = cc >> 3, co = cc & 7;                               \
            cp16(sbase + (bufoff) + (uint32_t)(kv * 9216 + r * 144 + co * 16),\
                 QKVF + (((size_t)b << 10) + (kt) * 64 + r) * 4096 +          \
                     (1 + kv) * 1024 + h * 64 + co * 8);                      \
        }                                                                     \
    } while (0)

    LOAD_KV(0, ATT_KV0);
    CP_COMMIT();

    const uint32_t a_lrow = (uint32_t)(lane & 15);
    const uint32_t a_koff2 = (uint32_t)((lane & 16) >> 1) * 2;
    const uint32_t b_lrow = (uint32_t)((lane & 7) + ((lane & 16) >> 1));
    const uint32_t b_koff2 = (uint32_t)(lane & 8) * 2;
    const uint32_t v_row = (uint32_t)((lane & 7) + (lane & 8));
    const uint32_t v_col2 = (uint32_t)((lane & 16) >> 1) * 2;

    const int qr = lane >> 2, qc = (lane & 3) * 2;
    float m0 = -1e30f, m1 = -1e30f, l0 = 0.f, l1 = 0.f;
    float oacc[8][4];
#pragma unroll
    for (int nt = 0; nt < 8; nt++)
#pragma unroll
        for (int e = 0; e < 4; e++) oacc[nt][e] = 0.f;

    for (int kt = 0; kt < 16; kt++) {
        CP_WAIT0();
        __syncthreads();
        const uint32_t kvb = (kt & 1) ? ATT_KV1 : ATT_KV0;
        if (kt < 15) LOAD_KV(kt + 1, (kt & 1) ? ATT_KV0 : ATT_KV1);
        CP_COMMIT();

        // ---- scores: S[16 x 64] per warp ----
        float sa[8][4];
#pragma unroll
        for (int nt = 0; nt < 8; nt++)
#pragma unroll
            for (int e = 0; e < 4; e++) sa[nt][e] = 0.f;

#pragma unroll
        for (int k16 = 0; k16 < 4; k16++) {
            uint32_t q[4];
            const uint32_t qaddr =
                sbase + ATT_Q + (uint32_t)(wr + a_lrow) * 144 + k16 * 32 + a_koff2;
            ldm_x4(q[0], q[1], q[2], q[3], qaddr);
#pragma unroll
            for (int ntp = 0; ntp < 4; ntp++) {
                uint32_t kf[4];
                const uint32_t kaddr =
                    sbase + kvb + (uint32_t)(ntp * 16 + b_lrow) * 144 + k16 * 32 + b_koff2;
                ldm_x4(kf[0], kf[1], kf[2], kf[3], kaddr);
                mma16816h(sa[2 * ntp],     q, kf[0], kf[1]);
                mma16816h(sa[2 * ntp + 1], q, kf[2], kf[3]);
            }
        }

        // ---- scale + pos bias ----
        const size_t r0g = (size_t)(q0 + wr + qr);
        const size_t pb0 = r0g * 1024 + kt * 64 + qc;
        const size_t pb1 = (r0g + 8) * 1024 + kt * 64 + qc;
#pragma unroll
        for (int nt = 0; nt < 8; nt++) {
            const float2 p0 = *(const float2*)&PB[pb0 + nt * 8];
            const float2 p1 = *(const float2*)&PB[pb1 + nt * 8];
            sa[nt][0] = sa[nt][0] * 0.125f + p0.x;
            sa[nt][1] = sa[nt][1] * 0.125f + p0.y;
            sa[nt][2] = sa[nt][2] * 0.125f + p1.x;
            sa[nt][3] = sa[nt][3] * 0.125f + p1.y;
        }

        // ---- online softmax ----
        float tm0 = -1e30f, tm1 = -1e30f;
#pragma unroll
        for (int nt = 0; nt < 8; nt++) {
            tm0 = fmaxf(tm0, fmaxf(sa[nt][0], sa[nt][1]));
            tm1 = fmaxf(tm1, fmaxf(sa[nt][2], sa[nt][3]));
        }
        tm0 = fmaxf(tm0, __shfl_xor_sync(0xffffffffu, tm0, 1));
        tm0 = fmaxf(tm0, __shfl_xor_sync(0xffffffffu, tm0, 2));
        tm1 = fmaxf(tm1, __shfl_xor_sync(0xffffffffu, tm1, 1));
        tm1 = fmaxf(tm1, __shfl_xor_sync(0xffffffffu, tm1, 2));
        const float mn0 = fmaxf(m0, tm0), mn1 = fmaxf(m1, tm1);
        const float cr0 = ex2f((m0 - mn0) * L2E), cr1 = ex2f((m1 - mn1) * L2E);
        m0 = mn0; m1 = mn1;

        float rs0 = 0.f, rs1 = 0.f;
#pragma unroll
        for (int nt = 0; nt < 8; nt++) {
            sa[nt][0] = ex2f((sa[nt][0] - mn0) * L2E);
            sa[nt][1] = ex2f((sa[nt][1] - mn0) * L2E);
            sa[nt][2] = ex2f((sa[nt][2] - mn1) * L2E);
            sa[nt][3] = ex2f((sa[nt][3] - mn1) * L2E);
            rs0 += sa[nt][0] + sa[nt][1];
            rs1 += sa[nt][2] + sa[nt][3];
        }
        rs0 += __shfl_xor_sync(0xffffffffu, rs0, 1);
        rs0 += __shfl_xor_sync(0xffffffffu, rs0, 2);
        rs1 += __shfl_xor_sync(0xffffffffu, rs1, 1);
        rs1 += __shfl_xor_sync(0xffffffffu, rs1, 2);
        l0 = l0 * cr0 + rs0;
        l1 = l1 * cr1 + rs1;
#pragma unroll
        for (int nt = 0; nt < 8; nt++) {
            oacc[nt][0] *= cr0; oacc[nt][1] *= cr0;
            oacc[nt][2] *= cr1; oacc[nt][3] *= cr1;
        }

        // ---- PV: fp16 A-frag from probabilities, trans ldmatrix on V ----
#pragma unroll
        for (int j = 0; j < 4; j++) {
            uint32_t pha[4];
            {
                const float* s0 = sa[2 * j];
                const float* s1 = sa[2 * j + 1];
                const __half2 a0 = __floats2half2_rn(s0[0], s0[1]);
                const __half2 a1 = __floats2half2_rn(s0[2], s0[3]);
                const __half2 a2 = __floats2half2_rn(s1[0], s1[1]);
                const __half2 a3 = __floats2half2_rn(s1[2], s1[3]);
                pha[0] = *(const uint32_t*)&a0;
                pha[1] = *(const uint32_t*)&a1;
                pha[2] = *(const uint32_t*)&a2;
                pha[3] = *(const uint32_t*)&a3;
            }
#pragma unroll
            for (int ntp = 0; ntp < 4; ntp++) {
                uint32_t vf[4];
                const uint32_t vaddr = sbase + kvb + 9216 +
                    (uint32_t)(j * 16 + v_row) * 144 + (uint32_t)(ntp * 16) * 2 + v_col2;
                ldm_x4t(vf[0], vf[1], vf[2], vf[3], vaddr);
                mma16816h(oacc[2 * ntp],     pha, vf[0], vf[1]);
                mma16816h(oacc[2 * ntp + 1], pha, vf[2], vf[3]);
            }
        }
        __syncthreads();   // all warps done with kvb before next iter's load overwrites peer buf
    }

    // ---- write ctx fp16 ----
    const float inv0 = 1.f / l0, inv1 = 1.f / l1;
    const size_t cr0 = (size_t)((b << 10) + q0 + wr + qr);
    const size_t colb = (size_t)(h * 64 + qc);
#pragma unroll
    for (int nt = 0; nt < 8; nt++) {
        const __half2 h2a = __floats2half2_rn(oacc[nt][0] * inv0, oacc[nt][1] * inv0);
        const __half2 h2b = __floats2half2_rn(oacc[nt][2] * inv1, oacc[nt][3] * inv1);
        *(__half2*)(CTXF + cr0 * 1024 + colb + nt * 8)       = h2a;
        *(__half2*)(CTXF + (cr0 + 8) * 1024 + colb + nt * 8) = h2b;
    }
#undef LOAD_KV
}

// =================== weight transpose -> single fp16 (with row interleave) ===================
__global__ __launch_bounds__(256)
void transpose_conv(const float* __restrict__ W, __half* __restrict__ T,
                    int K, int N, int rs, int ro) {
    __shared__ float t[32][33];
    const int k0 = blockIdx.y * 32, n0 = blockIdx.x * 32;
    const int tx = threadIdx.x & 31, ty = threadIdx.x >> 5;
#pragma unroll
    for (int l = 0; l < 4; l++)
        t[ty + 8 * l][tx] = W[(size_t)(k0 + ty + 8 * l) * N + n0 + tx];
    __syncthreads();
#pragma unroll
    for (int l = 0; l < 4; l++) {
        const size_t o = ((size_t)(n0 + ty + 8 * l) * rs + ro) * K + k0 + tx;
        T[o] = __float2half(t[tx][ty + 8 * l]);
    }
}

__global__ __launch_bounds__(256)
void conv_half(const float* __restrict__ X, __half* __restrict__ Xf) {
    const size_t i = ((size_t)blockIdx.x * 256 + threadIdx.x) * 4;
    const float4 v = *(const float4*)(X + i);
    uint2 o;
    const __half2 a = __floats2half2_rn(v.x, v.y);
    const __half2 b = __floats2half2_rn(v.z, v.w);
    o.x = *(const uint32_t*)&a;
    o.y = *(const uint32_t*)&b;
    *(uint2*)(Xf + i) = o;
}

__global__ void pack_bias(const float* bq, const float* bk, const float* bv,
                          const float* bg, const float* bf1, const float* bfg,
                          float* outq, float* outf) {
    const int i = blockIdx.x * 256 + threadIdx.x;   // 0..12287
    if (i < 1024) outq[i] = bq[i];
    else if (i < 2048) outq[i] = bk[i - 1024];
    else if (i < 3072) outq[i] = bv[i - 2048];
    else if (i < 4096) outq[i] = bg[i - 3072];
    else if (i < 8192) outf[2 * (i - 4096)] = bf1[i - 4096];
    else outf[2 * (i - 8192) + 1] = bfg[i - 8192];
}

__global__ __launch_bounds__(256)
void posbias_kernel(const float* __restrict__ pe, float* __restrict__ pb) {
    const size_t i = (size_t)blockIdx.x * 256 + threadIdx.x;
    const float4 a = *(const float4*)&pe[i * 8];
    const float4 b = *(const float4*)&pe[i * 8 + 4];
    pb[i] = (a.x + a.y + a.z + a.w + b.x + b.y + b.z + b.w) * 0.125f;
}

// ---------------- LN1: x1 = LN(x + sigmoid(gate)*attn); emit fp32 + fp16 ----------------
__global__ __launch_bounds__(256)
void ln1_kernel(const float* __restrict__ x, const float* __restrict__ attn,
                const __half* __restrict__ qkvgf, const float* __restrict__ gw,
                const float* __restrict__ gb, float* __restrict__ x1,
                __half* __restrict__ x1f) {
    const size_t base = (size_t)blockIdx.x * E_DIM;
    const size_t gbase = (size_t)blockIdx.x * 4096 + 3072;
    const int t = threadIdx.x;
    float vals[4];
    float s = 0.f, s2 = 0.f;
#pragma unroll
    for (int i = 0; i < 4; i++) {
        const int c = t + i * 256;
        const float gp = __half2float(qkvgf[gbase + c]);
        const float sg = 1.f / (1.f + __expf(-gp));
        const float val = x[base + c] + attn[base + c] * sg;
        vals[i] = val; s += val; s2 += val * val;
    }
    __shared__ float rsm[8], rs2[8];
#pragma unroll
    for (int o = 16; o; o >>= 1) {
        s  += __shfl_xor_sync(0xffffffffu, s,  o);
        s2 += __shfl_xor_sync(0xffffffffu, s2, o);
    }
    if ((t & 31) == 0) { rsm[t >> 5] = s; rs2[t >> 5] = s2; }
    __syncthreads();
    float S = 0.f, S2 = 0.f;
#pragma unroll
    for (int i = 0; i < 8; i++) { S += rsm[i]; S2 += rs2[i]; }
    const float mean = S * (1.f / E_DIM);
    const float var = S2 * (1.f / E_DIM) - mean * mean;
    const float inv = rsqrtf(var + 1e-6f);
#pragma unroll
    for (int i = 0; i < 4; i++) {
        const int c = t + i * 256;
        const float v = (vals[i] - mean) * inv * gw[c] + gb[c];
        x1[base + c] = v;
        x1f[base + c] = __float2half(v);
    }
}

// ---------------- LN2 (input already contains x1+ff residual) ----------------
__global__ __launch_bounds__(256)
void ln2_kernel(const float* __restrict__ ff,
                const float* __restrict__ gw, const float* __restrict__ gb,
                float* __restrict__ out) {
    const size_t base = (size_t)blockIdx.x * E_DIM;
    const int t = threadIdx.x;
    float vals[4];
    float s = 0.f, s2 = 0.f;
#pragma unroll
    for (int i = 0; i < 4; i++) {
        const int c = t + i * 256;
        const float val = ff[base + c];
        vals[i] = val; s += val; s2 += val * val;
    }
    __shared__ float rsm[8], rs2[8];
#pragma unroll
    for (int o = 16; o; o >>= 1) {
        s  += __shfl_xor_sync(0xffffffffu, s,  o);
        s2 += __shfl_xor_sync(0xffffffffu, s2, o);
    }
    if ((t & 31) == 0) { rsm[t >> 5] = s; rs2[t >> 5] = s2; }
    __syncthreads();
    float S = 0.f, S2 = 0.f;
#pragma unroll
    for (int i = 0; i < 8; i++) { S += rsm[i]; S2 += rs2[i]; }
    const float mean = S * (1.f / E_DIM);
    const float var = S2 * (1.f / E_DIM) - mean * mean;
    const float inv = rsqrtf(var + 1e-6f);
#pragma unroll
    for (int i = 0; i < 4; i++) {
        const int c = t + i * 256;
        out[base + c] = (vals[i] - mean) * inv * gw[c] + gb[c];
    }
}

// =================== launch ===================
extern "C" void kernel_launch(void* const* d_in, const int* in_sizes, int n_in,
                              void* d_out, int out_size) {
    const float* x   = (const float*)d_in[0];
    const float* pe  = (const float*)d_in[1];
    const float* Wq  = (const float*)d_in[2];
    const float* bq  = (const float*)d_in[3];
    const float* Wk  = (const float*)d_in[4];
    const float* bk  = (const float*)d_in[5];
    const float* Wv  = (const float*)d_in[6];
    const float* bv  = (const float*)d_in[7];
    const float* Wo  = (const float*)d_in[8];
    const float* bo  = (const float*)d_in[9];
    const float* Wg  = (const float*)d_in[10];
    const float* bg  = (const float*)d_in[11];
    const float* Wf1 = (const float*)d_in[12];
    const float* bf1 = (const float*)d_in[13];
    const float* Wfg = (const float*)d_in[14];
    const float* bfg = (const float*)d_in[15];
    const float* Wf2 = (const float*)d_in[16];
    const float* bf2 = (const float*)d_in[17];
    const float* l1g = (const float*)d_in[18];
    const float* l1b = (const float*)d_in[19];
    const float* l2g = (const float*)d_in[20];
    const float* l2b = (const float*)d_in[21];
    float* out = (float*)d_out;

    float *tmp, *x1, *pb, *biasq, *biasf;
    __half *qkvgf, *xf, *ctxf, *x1f, *h1f;
    __half *wq, *wo, *wff, *w2;
    cudaGetSymbolAddress((void**)&tmp, g_tmp);
    cudaGetSymbolAddress((void**)&x1, g_x1);
    cudaGetSymbolAddress((void**)&pb, g_pb);
    cudaGetSymbolAddress((void**)&biasq, g_bias_qkvg);
    cudaGetSymbolAddress((void**)&biasf, g_bias_ff);
    cudaGetSymbolAddress((void**)&qkvgf, g_qkvgf);
    cudaGetSymbolAddress((void**)&xf, g_xf);
    cudaGetSymbolAddress((void**)&ctxf, g_ctxf);
    cudaGetSymbolAddress((void**)&x1f, g_x1f);
    cudaGetSymbolAddress((void**)&h1f, g_h1f);
    cudaGetSymbolAddress((void**)&wq, g_wqkvg);
    cudaGetSymbolAddress((void**)&wo, g_wo);
    cudaGetSymbolAddress((void**)&wff, g_wff);
    cudaGetSymbolAddress((void**)&w2, g_wf2);

    cudaFuncSetAttribute(attention_f16,
                         cudaFuncAttributeMaxDynamicSharedMemorySize, ATT_SMEM);
    cudaFuncSetAttribute(hmma_gemm<0>,
                         cudaFuncAttributeMaxDynamicSharedMemorySize, GEMM_SMEM);
    cudaFuncSetAttribute(hmma_gemm<1>,
                         cudaFuncAttributeMaxDynamicSharedMemorySize, GEMM_SMEM);
    cudaFuncSetAttribute(hmma_gemm<2>,
                         cudaFuncAttributeMaxDynamicSharedMemorySize, GEMM_SMEM);
    cudaFuncSetAttribute(hmma_gemm<3>,
                         cudaFuncAttributeMaxDynamicSharedMemorySize, GEMM_SMEM);

    // --- prep ---
    posbias_kernel<<<4096, 256>>>(pe, pb);
    conv_half<<<M_ROWS * E_DIM / 1024, 256>>>(x, xf);

    transpose_conv<<<dim3(32, 32), 256>>>(Wq,  wq,             1024, 1024, 1, 0);
    transpose_conv<<<dim3(32, 32), 256>>>(Wk,  wq + 1024*1024, 1024, 1024, 1, 0);
    transpose_conv<<<dim3(32, 32), 256>>>(Wv,  wq + 2048*1024, 1024, 1024, 1, 0);
    transpose_conv<<<dim3(32, 32), 256>>>(Wg,  wq + 3072*1024, 1024, 1024, 1, 0);
    transpose_conv<<<dim3(32, 32), 256>>>(Wo,  wo, 1024, 1024, 1, 0);
    transpose_conv<<<dim3(128, 32), 256>>>(Wf1, wff, 1024, 4096, 2, 0);
    transpose_conv<<<dim3(128, 32), 256>>>(Wfg, wff, 1024, 4096, 2, 1);
    transpose_conv<<<dim3(32, 128), 256>>>(Wf2, w2, 4096, 1024, 1, 0);
    pack_bias<<<48, 256>>>(bq, bk, bv, bg, bf1, bfg, biasq, biasf);

    // --- QKV + gate projection (fp16 output) ---
    hmma_gemm<3><<<dim3(32, 32), 256, GEMM_SMEM>>>(xf, wq, biasq, nullptr,
                                                   qkvgf, nullptr,
                                                   M_ROWS, 4096, 1024);
    // --- fp16 flash attention ---
    attention_f16<<<dim3(8, 64), 256, ATT_SMEM>>>(qkvgf, pb, ctxf);
    // --- output projection ---
    hmma_gemm<0><<<dim3(8, 32), 256, GEMM_SMEM>>>(ctxf, wo, bo, tmp,
                                                  nullptr, nullptr,
                                                  M_ROWS, 1024, 1024);
    // --- gate + residual + LN1 ---
    ln1_kernel<<<M_ROWS, 256>>>(x, tmp, qkvgf, l1g, l1b, x1, x1f);
    // --- FFN up with fused SwiGLU epilogue ---
    hmma_gemm<1><<<dim3(64, 32), 256, GEMM_SMEM>>>(x1f, wff, biasf, nullptr,
                                                   h1f, nullptr,
                                                   M_ROWS, 8192, 1024);
    // --- FFN down + fused residual add (tmp = x1 + ff) ---
    hmma_gemm<2><<<dim3(8, 32), 256, GEMM_SMEM>>>(h1f, w2, bf2, tmp,
                                                  nullptr, x1,
                                                  M_ROWS, 1024, 4096);
    // --- LN2 ---
    ln2_kernel<<<M_ROWS, 256>>>(tmp, l2g, l2b, out);
}